// round 1
// baseline (speedup 1.0000x reference)
#include <cuda_runtime.h>
#include <cuda_bf16.h>
#include <math.h>

#define Bdim 8
#define Nseq 1024
#define Ddim 512
#define Hn 8
#define DH 64
#define BN_ROWS (Bdim * Nseq)   // 8192

// ---------------- scratch (device globals; no allocation allowed) ------------
__device__ float g_h[BN_ROWS * Ddim];        // LN1 output
__device__ float g_q[BN_ROWS * Ddim];        // [B,H,N,DH]
__device__ float g_k[BN_ROWS * Ddim];        // [B,H,N,DH]
__device__ float g_v[BN_ROWS * Ddim];        // [B,H,N,DH]
__device__ float g_attnout[BN_ROWS * Ddim];  // [B,N,D]
__device__ float g_y[BN_ROWS * Ddim];        // proj + residual, pre-LN2

// ---------------- LayerNorm: one block per row, 128 threads ------------------
__global__ void ln_kernel(const float* __restrict__ in,
                          const float* __restrict__ gamma,
                          const float* __restrict__ beta,
                          float* __restrict__ out)
{
    int row = blockIdx.x;
    const float4* r = (const float4*)(in + (size_t)row * Ddim);
    float4 a = r[threadIdx.x];                       // 128 threads * 4 = 512
    float s  = a.x + a.y + a.z + a.w;
    float s2 = a.x*a.x + a.y*a.y + a.z*a.z + a.w*a.w;

    #pragma unroll
    for (int off = 16; off; off >>= 1) {
        s  += __shfl_xor_sync(0xffffffffu, s,  off);
        s2 += __shfl_xor_sync(0xffffffffu, s2, off);
    }
    __shared__ float sbA[4], sbB[4];
    int wid = threadIdx.x >> 5, lane = threadIdx.x & 31;
    if (lane == 0) { sbA[wid] = s; sbB[wid] = s2; }
    __syncthreads();
    s  = sbA[0] + sbA[1] + sbA[2] + sbA[3];
    s2 = sbB[0] + sbB[1] + sbB[2] + sbB[3];

    float mean = s * (1.0f / Ddim);
    float var  = s2 * (1.0f / Ddim) - mean * mean;
    float rstd = rsqrtf(var + 1e-5f);

    float4 g = ((const float4*)gamma)[threadIdx.x];
    float4 b = ((const float4*)beta)[threadIdx.x];
    float4 o;
    o.x = (a.x - mean) * rstd * g.x + b.x;
    o.y = (a.y - mean) * rstd * g.y + b.y;
    o.z = (a.z - mean) * rstd * g.z + b.z;
    o.w = (a.w - mean) * rstd * g.w + b.w;
    ((float4*)(out + (size_t)row * Ddim))[threadIdx.x] = o;
}

// ---------------- GEMM core: 64x64 tile, K-step 16, 256 thr, 4x4 microtile ---
#define BM 64
#define BNt 64
#define BKt 16

__device__ __forceinline__ void gemm_tile_body(const float* __restrict__ A,
                                               const float* __restrict__ W,
                                               float acc[4][4],
                                               float As[BKt][BM + 1],
                                               float Ws[BKt][BNt])
{
    int t  = threadIdx.x;
    int tx = t & 15, ty = t >> 4;
    int m0 = blockIdx.y * BM, n0 = blockIdx.x * BNt;

    #pragma unroll
    for (int i = 0; i < 4; i++)
        #pragma unroll
        for (int j = 0; j < 4; j++) acc[i][j] = 0.f;

    for (int k0 = 0; k0 < Ddim; k0 += BKt) {
        // A tile: 64 rows x 16 cols, transposed into As[k][m]
        int ar = t >> 2, ac = (t & 3) * 4;
        float4 av = *(const float4*)(A + (size_t)(m0 + ar) * Ddim + k0 + ac);
        As[ac + 0][ar] = av.x;
        As[ac + 1][ar] = av.y;
        As[ac + 2][ar] = av.z;
        As[ac + 3][ar] = av.w;
        // W tile: 16 rows x 64 cols
        int wr = t >> 4, wc = (t & 15) * 4;
        *(float4*)(&Ws[wr][wc]) = *(const float4*)(W + (size_t)(k0 + wr) * Ddim + n0 + wc);
        __syncthreads();

        #pragma unroll
        for (int kk = 0; kk < BKt; kk++) {
            float a0 = As[kk][ty * 4 + 0];
            float a1 = As[kk][ty * 4 + 1];
            float a2 = As[kk][ty * 4 + 2];
            float a3 = As[kk][ty * 4 + 3];
            float4 bw = *(const float4*)(&Ws[kk][tx * 4]);
            acc[0][0] = fmaf(a0, bw.x, acc[0][0]); acc[0][1] = fmaf(a0, bw.y, acc[0][1]);
            acc[0][2] = fmaf(a0, bw.z, acc[0][2]); acc[0][3] = fmaf(a0, bw.w, acc[0][3]);
            acc[1][0] = fmaf(a1, bw.x, acc[1][0]); acc[1][1] = fmaf(a1, bw.y, acc[1][1]);
            acc[1][2] = fmaf(a1, bw.z, acc[1][2]); acc[1][3] = fmaf(a1, bw.w, acc[1][3]);
            acc[2][0] = fmaf(a2, bw.x, acc[2][0]); acc[2][1] = fmaf(a2, bw.y, acc[2][1]);
            acc[2][2] = fmaf(a2, bw.z, acc[2][2]); acc[2][3] = fmaf(a2, bw.w, acc[2][3]);
            acc[3][0] = fmaf(a3, bw.x, acc[3][0]); acc[3][1] = fmaf(a3, bw.y, acc[3][1]);
            acc[3][2] = fmaf(a3, bw.z, acc[3][2]); acc[3][3] = fmaf(a3, bw.w, acc[3][3]);
        }
        __syncthreads();
    }
}

// QKV GEMM: z selects {q,k,v}; output written directly in [B,H,N,DH] layout.
__global__ void gemm_qkv_kernel(const float* __restrict__ Wq,
                                const float* __restrict__ Wk,
                                const float* __restrict__ Wv,
                                const float* __restrict__ bq,
                                const float* __restrict__ bk,
                                const float* __restrict__ bv)
{
    __shared__ float As[BKt][BM + 1];
    __shared__ float Ws[BKt][BNt];
    const float* W; const float* bias; float* O;
    if (blockIdx.z == 0)      { W = Wq; bias = bq; O = g_q; }
    else if (blockIdx.z == 1) { W = Wk; bias = bk; O = g_k; }
    else                      { W = Wv; bias = bv; O = g_v; }

    float acc[4][4];
    gemm_tile_body(g_h, W, acc, As, Ws);

    int tx = threadIdx.x & 15, ty = threadIdx.x >> 4;
    int m0 = blockIdx.y * BM, n0 = blockIdx.x * BNt;
    #pragma unroll
    for (int i = 0; i < 4; i++) {
        int m = m0 + ty * 4 + i;
        int b = m >> 10, ns = m & 1023;
        #pragma unroll
        for (int j = 0; j < 4; j++) {
            int n  = n0 + tx * 4 + j;
            int h  = n >> 6, dh = n & 63;
            O[(((size_t)(b * Hn + h)) * Nseq + ns) * DH + dh] = acc[i][j] + bias[n];
        }
    }
}

// Output projection + bias + residual: g_y = g_attnout @ Wo + bo + x
__global__ void gemm_proj_kernel(const float* __restrict__ Wo,
                                 const float* __restrict__ bo,
                                 const float* __restrict__ xres)
{
    __shared__ float As[BKt][BM + 1];
    __shared__ float Ws[BKt][BNt];
    float acc[4][4];
    gemm_tile_body(g_attnout, Wo, acc, As, Ws);

    int tx = threadIdx.x & 15, ty = threadIdx.x >> 4;
    int m0 = blockIdx.y * BM, n0 = blockIdx.x * BNt;
    #pragma unroll
    for (int i = 0; i < 4; i++) {
        int m = m0 + ty * 4 + i;
        #pragma unroll
        for (int j = 0; j < 4; j++) {
            int n = n0 + tx * 4 + j;
            size_t idx = (size_t)m * Ddim + n;
            g_y[idx] = acc[i][j] + bo[n] + xres[idx];
        }
    }
}

// ---------------- Attention: 1 thread per query, 16-key tiles, online softmax
#define TK 16

__global__ void attn_kernel()
{
    int bh = blockIdx.y;                       // b*H + h
    int qi = blockIdx.x * 128 + threadIdx.x;   // query index within sequence
    const float* Qb = g_q + (size_t)bh * Nseq * DH;
    const float* Kb = g_k + (size_t)bh * Nseq * DH;
    const float* Vb = g_v + (size_t)bh * Nseq * DH;

    float q[DH];
    #pragma unroll
    for (int i = 0; i < DH / 4; i++) {
        float4 t4 = ((const float4*)(Qb + (size_t)qi * DH))[i];
        q[i*4+0] = t4.x; q[i*4+1] = t4.y; q[i*4+2] = t4.z; q[i*4+3] = t4.w;
    }
    float o[DH];
    #pragma unroll
    for (int d = 0; d < DH; d++) o[d] = 0.f;
    float mmax = -1e30f, l = 0.f;

    __shared__ float ks[TK * DH];
    __shared__ float vs[TK * DH];

    for (int t0 = 0; t0 < Nseq; t0 += TK) {
        __syncthreads();
        const float4* ksrc = (const float4*)(Kb + (size_t)t0 * DH);
        const float4* vsrc = (const float4*)(Vb + (size_t)t0 * DH);
        ((float4*)ks)[threadIdx.x]       = ksrc[threadIdx.x];
        ((float4*)ks)[threadIdx.x + 128] = ksrc[threadIdx.x + 128];
        ((float4*)vs)[threadIdx.x]       = vsrc[threadIdx.x];
        ((float4*)vs)[threadIdx.x + 128] = vsrc[threadIdx.x + 128];
        __syncthreads();

        float s[TK];
        #pragma unroll
        for (int j = 0; j < TK; j++) {
            float d2 = 0.f;
            #pragma unroll
            for (int d = 0; d < DH; d++) {
                float df = q[d] - ks[j * DH + d];
                d2 = fmaf(df, df, d2);
            }
            s[j] = -sqrtf(d2 + 1e-8f);
        }
        float tmax = s[0];
        #pragma unroll
        for (int j = 1; j < TK; j++) tmax = fmaxf(tmax, s[j]);
        float newm  = fmaxf(mmax, tmax);
        float scale = __expf(mmax - newm);
        l *= scale;
        #pragma unroll
        for (int d = 0; d < DH; d++) o[d] *= scale;
        #pragma unroll
        for (int j = 0; j < TK; j++) {
            float p = __expf(s[j] - newm);
            l += p;
            #pragma unroll
            for (int d = 0; d < DH; d++)
                o[d] = fmaf(p, vs[j * DH + d], o[d]);
        }
        mmax = newm;
    }

    float inv = 1.f / l;
    int b = bh >> 3, h = bh & 7;
    float* orow = g_attnout + ((size_t)(b * Nseq + qi)) * Ddim + h * DH;
    #pragma unroll
    for (int i = 0; i < DH / 4; i++) {
        float4 t4;
        t4.x = o[i*4+0] * inv; t4.y = o[i*4+1] * inv;
        t4.z = o[i*4+2] * inv; t4.w = o[i*4+3] * inv;
        ((float4*)orow)[i] = t4;
    }
}

// ---------------- launch ------------------------------------------------------
extern "C" void kernel_launch(void* const* d_in, const int* in_sizes, int n_in,
                              void* d_out, int out_size)
{
    // Classify inputs by element count. Relative order of the 262144-sized
    // (Wq,Wk,Wv,Wo) and 512-sized (bq,bk,bv,bo,ln1_g,ln1_b,ln2_g,ln2_b)
    // entries is identical in both the dict and signature orderings.
    const float* x = nullptr;
    const float* Wm[4] = {nullptr, nullptr, nullptr, nullptr};
    const float* vec[8] = {nullptr};
    int nm = 0, nv = 0;
    for (int i = 0; i < n_in; i++) {
        if (in_sizes[i] == BN_ROWS * Ddim)      x = (const float*)d_in[i];
        else if (in_sizes[i] == Ddim * Ddim)    { if (nm < 4) Wm[nm++] = (const float*)d_in[i]; }
        else if (in_sizes[i] == Ddim)           { if (nv < 8) vec[nv++] = (const float*)d_in[i]; }
    }
    const float *Wq = Wm[0], *Wk = Wm[1], *Wv = Wm[2], *Wo = Wm[3];
    const float *bq = vec[0], *bk = vec[1], *bv = vec[2], *bo = vec[3];
    const float *ln1g = vec[4], *ln1b = vec[5], *ln2g = vec[6], *ln2b = vec[7];

    void *p_h = nullptr, *p_y = nullptr;
    cudaGetSymbolAddress(&p_h, g_h);
    cudaGetSymbolAddress(&p_y, g_y);

    // 1) LN1
    ln_kernel<<<BN_ROWS, 128>>>(x, ln1g, ln1b, (float*)p_h);
    // 2) QKV projections (z = 0,1,2)
    dim3 ggrid(Ddim / BNt, BN_ROWS / BM, 3);
    gemm_qkv_kernel<<<ggrid, 256>>>(Wq, Wk, Wv, bq, bk, bv);
    // 3) Geometric attention
    attn_kernel<<<dim3(Nseq / 128, Bdim * Hn), 128>>>();
    // 4) Output projection + bias + residual
    gemm_proj_kernel<<<dim3(Ddim / BNt, BN_ROWS / BM), 256>>>(Wo, bo, x);
    // 5) LN2 -> d_out
    ln_kernel<<<BN_ROWS, 128>>>((const float*)p_y, ln2g, ln2b, (float*)d_out);
}

// round 3
// speedup vs baseline: 3.6065x; 3.6065x over previous
#include <cuda_runtime.h>
#include <cuda_bf16.h>
#include <stdint.h>
#include <cstdint>
#include <math.h>

#define Bdim 8
#define Nseq 1024
#define Ddim 512
#define Hn 8
#define DH 64
#define BN_ROWS (Bdim * Nseq)   // 8192
#define NBH (Bdim * Hn)         // 64

typedef unsigned int u32;

// ---------------- scratch (device globals; no allocation allowed) ------------
__device__ float g_h[BN_ROWS * Ddim];        // LN1 output
__device__ float g_q[BN_ROWS * Ddim];        // [BH, N, DH]
__device__ float g_k[BN_ROWS * Ddim];        // [BH, N, DH]
__device__ float g_v[BN_ROWS * Ddim];        // [BH, N, DH]
__device__ float g_attnout[BN_ROWS * Ddim];  // [B, N, D]
__device__ float g_y[BN_ROWS * Ddim];        // proj + residual, pre-LN2
__device__ float g_l[NBH * Nseq];            // softmax row sums
__device__ float g_P[67108864];              // [BH, N, N] unnormalized probs (256MB)

// ---------------- tf32 mma helpers -------------------------------------------
__device__ __forceinline__ u32 f2tf(float f) {
    u32 u;
    asm("cvt.rna.tf32.f32 %0, %1;" : "=r"(u) : "f"(f));
    return u;
}
__device__ __forceinline__ float tfbits(float f) { return __uint_as_float(f2tf(f)); }

__device__ __forceinline__ void mma8(float* c, const u32* a, const u32* b) {
    asm volatile(
        "mma.sync.aligned.m16n8k8.row.col.f32.tf32.tf32.f32 "
        "{%0,%1,%2,%3},{%4,%5,%6,%7},{%8,%9},{%0,%1,%2,%3};\n"
        : "+f"(c[0]), "+f"(c[1]), "+f"(c[2]), "+f"(c[3])
        : "r"(a[0]), "r"(a[1]), "r"(a[2]), "r"(a[3]), "r"(b[0]), "r"(b[1]));
}

// A fragment from row-major [m][k] smem (stride in floats)
__device__ __forceinline__ void ldA(u32* a, const float* S, int stride,
                                    int m, int k, int gid, int tig) {
    a[0] = __float_as_uint(S[(m + gid) * stride + k + tig]);
    a[1] = __float_as_uint(S[(m + gid + 8) * stride + k + tig]);
    a[2] = __float_as_uint(S[(m + gid) * stride + k + tig + 4]);
    a[3] = __float_as_uint(S[(m + gid + 8) * stride + k + tig + 4]);
}
// B fragment from row-major [k][n] smem
__device__ __forceinline__ void ldBkn(u32* b, const float* S, int stride,
                                      int k, int n, int gid, int tig) {
    b[0] = __float_as_uint(S[(k + tig) * stride + n + gid]);
    b[1] = __float_as_uint(S[(k + tig + 4) * stride + n + gid]);
}
// B fragment from row-major [n][k] smem
__device__ __forceinline__ void ldBnk(u32* b, const float* S, int stride,
                                      int k, int n, int gid, int tig) {
    b[0] = __float_as_uint(S[(n + gid) * stride + k + tig]);
    b[1] = __float_as_uint(S[(n + gid) * stride + k + tig + 4]);
}

// ---------------- LayerNorm ---------------------------------------------------
__global__ void ln_kernel(const float* __restrict__ in,
                          const float* __restrict__ gamma,
                          const float* __restrict__ beta,
                          float* __restrict__ out)
{
    int row = blockIdx.x;
    const float4* r = (const float4*)(in + (size_t)row * Ddim);
    float4 a = r[threadIdx.x];
    float s  = a.x + a.y + a.z + a.w;
    float s2 = a.x*a.x + a.y*a.y + a.z*a.z + a.w*a.w;
    #pragma unroll
    for (int off = 16; off; off >>= 1) {
        s  += __shfl_xor_sync(0xffffffffu, s,  off);
        s2 += __shfl_xor_sync(0xffffffffu, s2, off);
    }
    __shared__ float sbA[4], sbB[4];
    int wid = threadIdx.x >> 5, lane = threadIdx.x & 31;
    if (lane == 0) { sbA[wid] = s; sbB[wid] = s2; }
    __syncthreads();
    s  = sbA[0] + sbA[1] + sbA[2] + sbA[3];
    s2 = sbB[0] + sbB[1] + sbB[2] + sbB[3];
    float mean = s * (1.0f / Ddim);
    float var  = s2 * (1.0f / Ddim) - mean * mean;
    float rstd = rsqrtf(var + 1e-5f);
    float4 g = ((const float4*)gamma)[threadIdx.x];
    float4 b = ((const float4*)beta)[threadIdx.x];
    float4 o;
    o.x = (a.x - mean) * rstd * g.x + b.x;
    o.y = (a.y - mean) * rstd * g.y + b.y;
    o.z = (a.z - mean) * rstd * g.z + b.z;
    o.w = (a.w - mean) * rstd * g.w + b.w;
    ((float4*)(out + (size_t)row * Ddim))[threadIdx.x] = o;
}

// ---------------- tf32 MMA projection GEMM core -------------------------------
// Block 128(M) x 128(N), K-chunk 32, 256 threads, warp grid 2(M) x 4(N),
// warp tile 64x32 -> 4 mtiles x 4 ntiles of m16n8k8.
__device__ __forceinline__ void gemm_mma_body(const float* __restrict__ A,
                                              const float* __restrict__ W,
                                              float acc[4][4][4],
                                              float* As, float* Ws)
{
    const int t = threadIdx.x, lane = t & 31, wid = t >> 5;
    const int gid = lane >> 2, tig = lane & 3;
    const int wm = (wid >> 2) * 64, wn = (wid & 3) * 32;
    const int m0 = blockIdx.y * 128, n0 = blockIdx.x * 128;

    #pragma unroll
    for (int i = 0; i < 4; i++)
        #pragma unroll
        for (int j = 0; j < 4; j++)
            #pragma unroll
            for (int c = 0; c < 4; c++) acc[i][j][c] = 0.f;

    for (int k0 = 0; k0 < Ddim; k0 += 32) {
        #pragma unroll
        for (int i = 0; i < 4; i++) {        // A: 128x32 = 1024 float4
            int f = t + 256 * i;
            int r = f >> 3, c = (f & 7) * 4;
            float4 v = *(const float4*)(A + (size_t)(m0 + r) * Ddim + k0 + c);
            float4 w4 = { tfbits(v.x), tfbits(v.y), tfbits(v.z), tfbits(v.w) };
            *(float4*)(As + r * 36 + c) = w4;
        }
        #pragma unroll
        for (int i = 0; i < 4; i++) {        // W: 32x128 = 1024 float4
            int f = t + 256 * i;
            int r = f >> 5, c = (f & 31) * 4;
            float4 v = *(const float4*)(W + (size_t)(k0 + r) * Ddim + n0 + c);
            float4 w4 = { tfbits(v.x), tfbits(v.y), tfbits(v.z), tfbits(v.w) };
            *(float4*)(Ws + r * 136 + c) = w4;
        }
        __syncthreads();
        #pragma unroll
        for (int ks = 0; ks < 4; ks++) {
            int kk = ks * 8;
            u32 a[4][4], b[4][2];
            #pragma unroll
            for (int mt = 0; mt < 4; mt++) ldA(a[mt], As, 36, wm + mt * 16, kk, gid, tig);
            #pragma unroll
            for (int nt = 0; nt < 4; nt++) ldBkn(b[nt], Ws, 136, kk, wn + nt * 8, gid, tig);
            #pragma unroll
            for (int mt = 0; mt < 4; mt++)
                #pragma unroll
                for (int nt = 0; nt < 4; nt++) mma8(acc[mt][nt], a[mt], b[nt]);
        }
        __syncthreads();
    }
}

// QKV: z picks {q,k,v}; output in [BH, N, DH] layout, bias fused.
__global__ void __launch_bounds__(256) qkv_mma_kernel(
    const float* __restrict__ Wq, const float* __restrict__ Wk,
    const float* __restrict__ Wv, const float* __restrict__ bq,
    const float* __restrict__ bk, const float* __restrict__ bv)
{
    __shared__ float As[128 * 36];
    __shared__ float Ws[32 * 136];
    __shared__ float bs[128];
    const float* W; const float* bias; float* O;
    if (blockIdx.z == 0)      { W = Wq; bias = bq; O = g_q; }
    else if (blockIdx.z == 1) { W = Wk; bias = bk; O = g_k; }
    else                      { W = Wv; bias = bv; O = g_v; }

    const int t = threadIdx.x, lane = t & 31, wid = t >> 5;
    const int gid = lane >> 2, tig = lane & 3;
    const int wm = (wid >> 2) * 64, wn = (wid & 3) * 32;
    const int m0 = blockIdx.y * 128, n0 = blockIdx.x * 128;
    if (t < 128) bs[t] = bias[n0 + t];

    float acc[4][4][4];
    gemm_mma_body(g_h, W, acc, As, Ws);

    #pragma unroll
    for (int mt = 0; mt < 4; mt++)
        #pragma unroll
        for (int nt = 0; nt < 4; nt++) {
            int cl = wn + nt * 8 + 2 * tig;
            int n  = n0 + cl;
            int h  = n >> 6, dh = n & 63;
            int mr = m0 + wm + mt * 16 + gid;
            {
                int b0i = mr >> 10, ns = mr & 1023;
                float2 p = { acc[mt][nt][0] + bs[cl], acc[mt][nt][1] + bs[cl + 1] };
                *(float2*)(O + (((size_t)(b0i * Hn + h) * Nseq + ns) * DH + dh)) = p;
            }
            {
                int mr2 = mr + 8;
                int b0i = mr2 >> 10, ns = mr2 & 1023;
                float2 p = { acc[mt][nt][2] + bs[cl], acc[mt][nt][3] + bs[cl + 1] };
                *(float2*)(O + (((size_t)(b0i * Hn + h) * Nseq + ns) * DH + dh)) = p;
            }
        }
}

// Output projection: g_y = attnout @ Wo + bo + x
__global__ void __launch_bounds__(256) proj_mma_kernel(
    const float* __restrict__ Wo, const float* __restrict__ bo,
    const float* __restrict__ xres)
{
    __shared__ float As[128 * 36];
    __shared__ float Ws[32 * 136];
    __shared__ float bs[128];
    const int t = threadIdx.x, lane = t & 31, wid = t >> 5;
    const int gid = lane >> 2, tig = lane & 3;
    const int wm = (wid >> 2) * 64, wn = (wid & 3) * 32;
    const int m0 = blockIdx.y * 128, n0 = blockIdx.x * 128;
    if (t < 128) bs[t] = bo[n0 + t];

    float acc[4][4][4];
    gemm_mma_body(g_attnout, Wo, acc, As, Ws);

    #pragma unroll
    for (int mt = 0; mt < 4; mt++)
        #pragma unroll
        for (int nt = 0; nt < 4; nt++) {
            int cl = wn + nt * 8 + 2 * tig;
            int n  = n0 + cl;
            int mr = m0 + wm + mt * 16 + gid;
            {
                size_t idx = (size_t)mr * Ddim + n;
                float2 xr = *(const float2*)(xres + idx);
                float2 p = { acc[mt][nt][0] + bs[cl] + xr.x,
                             acc[mt][nt][1] + bs[cl + 1] + xr.y };
                *(float2*)(g_y + idx) = p;
            }
            {
                size_t idx = (size_t)(mr + 8) * Ddim + n;
                float2 xr = *(const float2*)(xres + idx);
                float2 p = { acc[mt][nt][2] + bs[cl] + xr.x,
                             acc[mt][nt][3] + bs[cl + 1] + xr.y };
                *(float2*)(g_y + idx) = p;
            }
        }
}

// ---------------- Scores pass: P = exp(-dist(Q,K)), row sums l ----------------
// grid (Nseq/128, NBH). Block covers 128 query rows x all 1024 keys (8 chunks).
// Scores <= 0 so exp() never overflows: no max-subtraction needed.
#define SQ_STRIDE 68
__global__ void __launch_bounds__(256) attn_scores_kernel()
{
    extern __shared__ float smem_dyn[];
    float* Qs  = smem_dyn;
    float* Ks  = smem_dyn + 128 * SQ_STRIDE;
    float* q2s = smem_dyn + 2 * 128 * SQ_STRIDE;
    float* k2s = q2s + 128;
    float* ls  = k2s + 128;

    const int t = threadIdx.x, lane = t & 31, wid = t >> 5;
    const int gid = lane >> 2, tig = lane & 3;
    const int wm = (wid >> 2) * 64, wn = (wid & 3) * 32;
    const int i0 = blockIdx.x * 128;
    const int bh = blockIdx.y;
    const float* Qg = g_q + (size_t)bh * Nseq * DH;
    const float* Kg = g_k + (size_t)bh * Nseq * DH;
    float* Pg = g_P + (size_t)bh * Nseq * Nseq;

    #pragma unroll
    for (int i = 0; i < 8; i++) {
        int f = t + 256 * i;                  // 2048 float4 = 128x64
        int r = f >> 4, c = (f & 15) * 4;
        float4 v = *(const float4*)(Qg + (size_t)(i0 + r) * DH + c);
        float4 w4 = { tfbits(v.x), tfbits(v.y), tfbits(v.z), tfbits(v.w) };
        *(float4*)(Qs + r * SQ_STRIDE + c) = w4;
    }
    if (t < 128) ls[t] = 0.f;
    __syncthreads();
    if (t < 128) {
        float s = 0.f;
        #pragma unroll
        for (int c = 0; c < DH; c += 4) {
            float4 v = *(const float4*)(Qs + t * SQ_STRIDE + c);
            s += v.x*v.x + v.y*v.y + v.z*v.z + v.w*v.w;
        }
        q2s[t] = s;
    }
    __syncthreads();

    float rs[4][2];
    #pragma unroll
    for (int mt = 0; mt < 4; mt++) { rs[mt][0] = 0.f; rs[mt][1] = 0.f; }

    for (int jc = 0; jc < 8; jc++) {
        int j0 = jc * 128;
        #pragma unroll
        for (int i = 0; i < 8; i++) {
            int f = t + 256 * i;
            int r = f >> 4, c = (f & 15) * 4;
            float4 v = *(const float4*)(Kg + (size_t)(j0 + r) * DH + c);
            float4 w4 = { tfbits(v.x), tfbits(v.y), tfbits(v.z), tfbits(v.w) };
            *(float4*)(Ks + r * SQ_STRIDE + c) = w4;
        }
        __syncthreads();
        if (t < 128) {
            float s = 0.f;
            #pragma unroll
            for (int c = 0; c < DH; c += 4) {
                float4 v = *(const float4*)(Ks + t * SQ_STRIDE + c);
                s += v.x*v.x + v.y*v.y + v.z*v.z + v.w*v.w;
            }
            k2s[t] = s;
        }
        __syncthreads();

        float acc[4][4][4];
        #pragma unroll
        for (int mt = 0; mt < 4; mt++)
            #pragma unroll
            for (int nt = 0; nt < 4; nt++)
                #pragma unroll
                for (int c = 0; c < 4; c++) acc[mt][nt][c] = 0.f;

        #pragma unroll
        for (int ks = 0; ks < 8; ks++) {
            int kk = ks * 8;
            u32 a[4][4], b[4][2];
            #pragma unroll
            for (int mt = 0; mt < 4; mt++) ldA(a[mt], Qs, SQ_STRIDE, wm + mt * 16, kk, gid, tig);
            #pragma unroll
            for (int nt = 0; nt < 4; nt++) ldBnk(b[nt], Ks, SQ_STRIDE, kk, wn + nt * 8, gid, tig);
            #pragma unroll
            for (int mt = 0; mt < 4; mt++)
                #pragma unroll
                for (int nt = 0; nt < 4; nt++) mma8(acc[mt][nt], a[mt], b[nt]);
        }

        #pragma unroll
        for (int mt = 0; mt < 4; mt++) {
            int rl = wm + mt * 16 + gid;
            float q2a = q2s[rl], q2b = q2s[rl + 8];
            #pragma unroll
            for (int nt = 0; nt < 4; nt++) {
                int cl = wn + nt * 8 + 2 * tig;
                float k2a = k2s[cl], k2b = k2s[cl + 1];
                float d0 = fmaxf(fmaf(-2.f, acc[mt][nt][0], q2a + k2a), 0.f) + 1e-8f;
                float d1 = fmaxf(fmaf(-2.f, acc[mt][nt][1], q2a + k2b), 0.f) + 1e-8f;
                float d2 = fmaxf(fmaf(-2.f, acc[mt][nt][2], q2b + k2a), 0.f) + 1e-8f;
                float d3 = fmaxf(fmaf(-2.f, acc[mt][nt][3], q2b + k2b), 0.f) + 1e-8f;
                float p0 = __expf(-sqrtf(d0));
                float p1 = __expf(-sqrtf(d1));
                float p2 = __expf(-sqrtf(d2));
                float p3 = __expf(-sqrtf(d3));
                rs[mt][0] += p0 + p1;
                rs[mt][1] += p2 + p3;
                int jg = j0 + cl;
                float2 w0 = { p0, p1 };
                float2 w1 = { p2, p3 };
                *(float2*)(Pg + (size_t)(i0 + rl) * Nseq + jg) = w0;
                *(float2*)(Pg + (size_t)(i0 + rl + 8) * Nseq + jg) = w1;
            }
        }
        __syncthreads();
    }

    // reduce row sums: quad shuffle then shared atomics across the 4 n-warps
    #pragma unroll
    for (int mt = 0; mt < 4; mt++) {
        float v0 = rs[mt][0], v1 = rs[mt][1];
        v0 += __shfl_xor_sync(0xffffffffu, v0, 1);
        v0 += __shfl_xor_sync(0xffffffffu, v0, 2);
        v1 += __shfl_xor_sync(0xffffffffu, v1, 1);
        v1 += __shfl_xor_sync(0xffffffffu, v1, 2);
        if (tig == 0) {
            atomicAdd(&ls[wm + mt * 16 + gid], v0);
            atomicAdd(&ls[wm + mt * 16 + gid + 8], v1);
        }
    }
    __syncthreads();
    if (t < 128) g_l[(size_t)bh * Nseq + i0 + t] = ls[t];
}

// ---------------- PV pass: attnout = (P @ V) / l ------------------------------
// Block 128(M) x 64(N), K-chunk 32, warp grid 4(M) x 2(N), warp tile 32x32.
__global__ void __launch_bounds__(256) attn_pv_kernel()
{
    __shared__ float Ps[128 * 36];
    __shared__ float Vs[32 * 72];
    const int t = threadIdx.x, lane = t & 31, wid = t >> 5;
    const int gid = lane >> 2, tig = lane & 3;
    const int wm = (wid >> 1) * 32, wn = (wid & 1) * 32;
    const int i0 = blockIdx.x * 128;
    const int bh = blockIdx.y;
    const float* Pg = g_P + (size_t)bh * Nseq * Nseq;
    const float* Vg = g_v + (size_t)bh * Nseq * DH;

    float acc[2][4][4];
    #pragma unroll
    for (int mt = 0; mt < 2; mt++)
        #pragma unroll
        for (int nt = 0; nt < 4; nt++)
            #pragma unroll
            for (int c = 0; c < 4; c++) acc[mt][nt][c] = 0.f;

    for (int k0 = 0; k0 < Nseq; k0 += 32) {
        #pragma unroll
        for (int i = 0; i < 4; i++) {        // P chunk 128x32
            int f = t + 256 * i;
            int r = f >> 3, c = (f & 7) * 4;
            float4 v = *(const float4*)(Pg + (size_t)(i0 + r) * Nseq + k0 + c);
            float4 w4 = { tfbits(v.x), tfbits(v.y), tfbits(v.z), tfbits(v.w) };
            *(float4*)(Ps + r * 36 + c) = w4;
        }
        #pragma unroll
        for (int i = 0; i < 2; i++) {        // V chunk 32x64
            int f = t + 256 * i;
            int r = f >> 4, c = (f & 15) * 4;
            float4 v = *(const float4*)(Vg + (size_t)(k0 + r) * DH + c);
            float4 w4 = { tfbits(v.x), tfbits(v.y), tfbits(v.z), tfbits(v.w) };
            *(float4*)(Vs + r * 72 + c) = w4;
        }
        __syncthreads();
        #pragma unroll
        for (int ks = 0; ks < 4; ks++) {
            int kk = ks * 8;
            u32 a[2][4], b[4][2];
            #pragma unroll
            for (int mt = 0; mt < 2; mt++) ldA(a[mt], Ps, 36, wm + mt * 16, kk, gid, tig);
            #pragma unroll
            for (int nt = 0; nt < 4; nt++) ldBkn(b[nt], Vs, 72, kk, wn + nt * 8, gid, tig);
            #pragma unroll
            for (int mt = 0; mt < 2; mt++)
                #pragma unroll
                for (int nt = 0; nt < 4; nt++) mma8(acc[mt][nt], a[mt], b[nt]);
        }
        __syncthreads();
    }

    const int b = bh >> 3, h = bh & 7;
    #pragma unroll
    for (int mt = 0; mt < 2; mt++) {
        int i  = i0 + wm + mt * 16 + gid;
        float li0 = 1.0f / g_l[(size_t)bh * Nseq + i];
        float li1 = 1.0f / g_l[(size_t)bh * Nseq + i + 8];
        #pragma unroll
        for (int nt = 0; nt < 4; nt++) {
            int dh = wn + nt * 8 + 2 * tig;
            float2 w0 = { acc[mt][nt][0] * li0, acc[mt][nt][1] * li0 };
            float2 w1 = { acc[mt][nt][2] * li1, acc[mt][nt][3] * li1 };
            *(float2*)(g_attnout + ((size_t)(b * Nseq + i) * Ddim + h * DH + dh)) = w0;
            *(float2*)(g_attnout + ((size_t)(b * Nseq + i + 8) * Ddim + h * DH + dh)) = w1;
        }
    }
}

// ---------------- launch ------------------------------------------------------
extern "C" void kernel_launch(void* const* d_in, const int* in_sizes, int n_in,
                              void* d_out, int out_size)
{
    const float* x = nullptr;
    const float* Wm[4] = {nullptr, nullptr, nullptr, nullptr};
    const float* vec[8] = {nullptr};
    int nm = 0, nv = 0;
    for (int i = 0; i < n_in; i++) {
        if (in_sizes[i] == BN_ROWS * Ddim)      x = (const float*)d_in[i];
        else if (in_sizes[i] == Ddim * Ddim)    { if (nm < 4) Wm[nm++] = (const float*)d_in[i]; }
        else if (in_sizes[i] == Ddim)           { if (nv < 8) vec[nv++] = (const float*)d_in[i]; }
    }
    const float *Wq = Wm[0], *Wk = Wm[1], *Wv = Wm[2], *Wo = Wm[3];
    const float *bq = vec[0], *bk = vec[1], *bv = vec[2], *bo = vec[3];
    const float *ln1g = vec[4], *ln1b = vec[5], *ln2g = vec[6], *ln2b = vec[7];

    void *p_h = nullptr, *p_y = nullptr;
    cudaGetSymbolAddress(&p_h, g_h);
    cudaGetSymbolAddress(&p_y, g_y);

    const int scores_smem = (2 * 128 * SQ_STRIDE + 3 * 128) * sizeof(float); // 71168
    cudaFuncSetAttribute(attn_scores_kernel,
                         cudaFuncAttributeMaxDynamicSharedMemorySize, scores_smem);

    ln_kernel<<<BN_ROWS, 128>>>(x, ln1g, ln1b, (float*)p_h);
    qkv_mma_kernel<<<dim3(Ddim / 128, BN_ROWS / 128, 3), 256>>>(Wq, Wk, Wv, bq, bk, bv);
    attn_scores_kernel<<<dim3(Nseq / 128, NBH), 256, scores_smem>>>();
    attn_pv_kernel<<<dim3(Nseq / 128, NBH), 256>>>();
    proj_mma_kernel<<<dim3(Ddim / 128, BN_ROWS / 128), 256>>>(Wo, bo, x);
    ln_kernel<<<BN_ROWS, 128>>>((const float*)p_y, ln2g, ln2b, (float*)d_out);
}

// round 4
// speedup vs baseline: 4.3660x; 1.2106x over previous
#include <cuda_runtime.h>
#include <cuda_bf16.h>
#include <stdint.h>
#include <cstdint>
#include <math.h>

#define Bdim 8
#define Nseq 1024
#define Ddim 512
#define Hn 8
#define DH 64
#define BN_ROWS (Bdim * Nseq)   // 8192
#define NBH (Bdim * Hn)         // 64

typedef unsigned int u32;

// ---------------- scratch (device globals; no allocation allowed) ------------
__device__ float g_h[BN_ROWS * Ddim];        // LN1 output
__device__ float g_q[BN_ROWS * Ddim];        // [BH, N, DH]
__device__ float g_k[BN_ROWS * Ddim];        // [BH, N, DH]
__device__ float g_v[BN_ROWS * Ddim];        // [BH, N, DH]
__device__ float g_attnout[BN_ROWS * Ddim];  // [B, N, D]
__device__ float g_y[BN_ROWS * Ddim];        // proj + residual, pre-LN2

// ---------------- tf32 mma helpers -------------------------------------------
__device__ __forceinline__ u32 f2tf(float f) {
    u32 u;
    asm("cvt.rna.tf32.f32 %0, %1;" : "=r"(u) : "f"(f));
    return u;
}
__device__ __forceinline__ float tfbits(float f) { return __uint_as_float(f2tf(f)); }

__device__ __forceinline__ void mma8(float* c, const u32* a, const u32* b) {
    asm volatile(
        "mma.sync.aligned.m16n8k8.row.col.f32.tf32.tf32.f32 "
        "{%0,%1,%2,%3},{%4,%5,%6,%7},{%8,%9},{%0,%1,%2,%3};\n"
        : "+f"(c[0]), "+f"(c[1]), "+f"(c[2]), "+f"(c[3])
        : "r"(a[0]), "r"(a[1]), "r"(a[2]), "r"(a[3]), "r"(b[0]), "r"(b[1]));
}

// A fragment from row-major [m][k] smem (stride in floats)
__device__ __forceinline__ void ldA(u32* a, const float* S, int stride,
                                    int m, int k, int gid, int tig) {
    a[0] = __float_as_uint(S[(m + gid) * stride + k + tig]);
    a[1] = __float_as_uint(S[(m + gid + 8) * stride + k + tig]);
    a[2] = __float_as_uint(S[(m + gid) * stride + k + tig + 4]);
    a[3] = __float_as_uint(S[(m + gid + 8) * stride + k + tig + 4]);
}
// B fragment from row-major [k][n] smem
__device__ __forceinline__ void ldBkn(u32* b, const float* S, int stride,
                                      int k, int n, int gid, int tig) {
    b[0] = __float_as_uint(S[(k + tig) * stride + n + gid]);
    b[1] = __float_as_uint(S[(k + tig + 4) * stride + n + gid]);
}
// B fragment from row-major [n][k] smem
__device__ __forceinline__ void ldBnk(u32* b, const float* S, int stride,
                                      int k, int n, int gid, int tig) {
    b[0] = __float_as_uint(S[(n + gid) * stride + k + tig]);
    b[1] = __float_as_uint(S[(n + gid) * stride + k + tig + 4]);
}

// ---------------- LayerNorm ---------------------------------------------------
__global__ void ln_kernel(const float* __restrict__ in,
                          const float* __restrict__ gamma,
                          const float* __restrict__ beta,
                          float* __restrict__ out)
{
    int row = blockIdx.x;
    const float4* r = (const float4*)(in + (size_t)row * Ddim);
    float4 a = r[threadIdx.x];
    float s  = a.x + a.y + a.z + a.w;
    float s2 = a.x*a.x + a.y*a.y + a.z*a.z + a.w*a.w;
    #pragma unroll
    for (int off = 16; off; off >>= 1) {
        s  += __shfl_xor_sync(0xffffffffu, s,  off);
        s2 += __shfl_xor_sync(0xffffffffu, s2, off);
    }
    __shared__ float sbA[4], sbB[4];
    int wid = threadIdx.x >> 5, lane = threadIdx.x & 31;
    if (lane == 0) { sbA[wid] = s; sbB[wid] = s2; }
    __syncthreads();
    s  = sbA[0] + sbA[1] + sbA[2] + sbA[3];
    s2 = sbB[0] + sbB[1] + sbB[2] + sbB[3];
    float mean = s * (1.0f / Ddim);
    float var  = s2 * (1.0f / Ddim) - mean * mean;
    float rstd = rsqrtf(var + 1e-5f);
    float4 g = ((const float4*)gamma)[threadIdx.x];
    float4 b = ((const float4*)beta)[threadIdx.x];
    float4 o;
    o.x = (a.x - mean) * rstd * g.x + b.x;
    o.y = (a.y - mean) * rstd * g.y + b.y;
    o.z = (a.z - mean) * rstd * g.z + b.z;
    o.w = (a.w - mean) * rstd * g.w + b.w;
    ((float4*)(out + (size_t)row * Ddim))[threadIdx.x] = o;
}

// ---------------- tf32 MMA projection GEMM core -------------------------------
__device__ __forceinline__ void gemm_mma_body(const float* __restrict__ A,
                                              const float* __restrict__ W,
                                              float acc[4][4][4],
                                              float* As, float* Ws)
{
    const int t = threadIdx.x, lane = t & 31, wid = t >> 5;
    const int gid = lane >> 2, tig = lane & 3;
    const int wm = (wid >> 2) * 64, wn = (wid & 3) * 32;
    const int m0 = blockIdx.y * 128, n0 = blockIdx.x * 128;

    #pragma unroll
    for (int i = 0; i < 4; i++)
        #pragma unroll
        for (int j = 0; j < 4; j++)
            #pragma unroll
            for (int c = 0; c < 4; c++) acc[i][j][c] = 0.f;

    for (int k0 = 0; k0 < Ddim; k0 += 32) {
        #pragma unroll
        for (int i = 0; i < 4; i++) {
            int f = t + 256 * i;
            int r = f >> 3, c = (f & 7) * 4;
            float4 v = *(const float4*)(A + (size_t)(m0 + r) * Ddim + k0 + c);
            float4 w4 = { tfbits(v.x), tfbits(v.y), tfbits(v.z), tfbits(v.w) };
            *(float4*)(As + r * 36 + c) = w4;
        }
        #pragma unroll
        for (int i = 0; i < 4; i++) {
            int f = t + 256 * i;
            int r = f >> 5, c = (f & 31) * 4;
            float4 v = *(const float4*)(W + (size_t)(k0 + r) * Ddim + n0 + c);
            float4 w4 = { tfbits(v.x), tfbits(v.y), tfbits(v.z), tfbits(v.w) };
            *(float4*)(Ws + r * 136 + c) = w4;
        }
        __syncthreads();
        #pragma unroll
        for (int ks = 0; ks < 4; ks++) {
            int kk = ks * 8;
            u32 a[4][4], b[4][2];
            #pragma unroll
            for (int mt = 0; mt < 4; mt++) ldA(a[mt], As, 36, wm + mt * 16, kk, gid, tig);
            #pragma unroll
            for (int nt = 0; nt < 4; nt++) ldBkn(b[nt], Ws, 136, kk, wn + nt * 8, gid, tig);
            #pragma unroll
            for (int mt = 0; mt < 4; mt++)
                #pragma unroll
                for (int nt = 0; nt < 4; nt++) mma8(acc[mt][nt], a[mt], b[nt]);
        }
        __syncthreads();
    }
}

// QKV: z picks {q,k,v}; output in [BH, N, DH] layout, bias fused.
__global__ void __launch_bounds__(256) qkv_mma_kernel(
    const float* __restrict__ Wq, const float* __restrict__ Wk,
    const float* __restrict__ Wv, const float* __restrict__ bq,
    const float* __restrict__ bk, const float* __restrict__ bv)
{
    __shared__ float As[128 * 36];
    __shared__ float Ws[32 * 136];
    __shared__ float bs[128];
    const float* W; const float* bias; float* O;
    if (blockIdx.z == 0)      { W = Wq; bias = bq; O = g_q; }
    else if (blockIdx.z == 1) { W = Wk; bias = bk; O = g_k; }
    else                      { W = Wv; bias = bv; O = g_v; }

    const int t = threadIdx.x, lane = t & 31, wid = t >> 5;
    const int gid = lane >> 2, tig = lane & 3;
    const int wm = (wid >> 2) * 64, wn = (wid & 3) * 32;
    const int m0 = blockIdx.y * 128, n0 = blockIdx.x * 128;
    if (t < 128) bs[t] = bias[n0 + t];

    float acc[4][4][4];
    gemm_mma_body(g_h, W, acc, As, Ws);

    #pragma unroll
    for (int mt = 0; mt < 4; mt++)
        #pragma unroll
        for (int nt = 0; nt < 4; nt++) {
            int cl = wn + nt * 8 + 2 * tig;
            int n  = n0 + cl;
            int h  = n >> 6, dh = n & 63;
            int mr = m0 + wm + mt * 16 + gid;
            {
                int b0i = mr >> 10, ns = mr & 1023;
                float2 p = { acc[mt][nt][0] + bs[cl], acc[mt][nt][1] + bs[cl + 1] };
                *(float2*)(O + (((size_t)(b0i * Hn + h) * Nseq + ns) * DH + dh)) = p;
            }
            {
                int mr2 = mr + 8;
                int b0i = mr2 >> 10, ns = mr2 & 1023;
                float2 p = { acc[mt][nt][2] + bs[cl], acc[mt][nt][3] + bs[cl + 1] };
                *(float2*)(O + (((size_t)(b0i * Hn + h) * Nseq + ns) * DH + dh)) = p;
            }
        }
}

// Output projection: g_y = attnout @ Wo + bo + x
__global__ void __launch_bounds__(256) proj_mma_kernel(
    const float* __restrict__ Wo, const float* __restrict__ bo,
    const float* __restrict__ xres)
{
    __shared__ float As[128 * 36];
    __shared__ float Ws[32 * 136];
    __shared__ float bs[128];
    const int t = threadIdx.x, lane = t & 31, wid = t >> 5;
    const int gid = lane >> 2, tig = lane & 3;
    const int wm = (wid >> 2) * 64, wn = (wid & 3) * 32;
    const int m0 = blockIdx.y * 128, n0 = blockIdx.x * 128;
    if (t < 128) bs[t] = bo[n0 + t];

    float acc[4][4][4];
    gemm_mma_body(g_attnout, Wo, acc, As, Ws);

    #pragma unroll
    for (int mt = 0; mt < 4; mt++)
        #pragma unroll
        for (int nt = 0; nt < 4; nt++) {
            int cl = wn + nt * 8 + 2 * tig;
            int n  = n0 + cl;
            int mr = m0 + wm + mt * 16 + gid;
            {
                size_t idx = (size_t)mr * Ddim + n;
                float2 xr = *(const float2*)(xres + idx);
                float2 p = { acc[mt][nt][0] + bs[cl] + xr.x,
                             acc[mt][nt][1] + bs[cl + 1] + xr.y };
                *(float2*)(g_y + idx) = p;
            }
            {
                size_t idx = (size_t)(mr + 8) * Ddim + n;
                float2 xr = *(const float2*)(xres + idx);
                float2 p = { acc[mt][nt][2] + bs[cl] + xr.x,
                             acc[mt][nt][3] + bs[cl + 1] + xr.y };
                *(float2*)(g_y + idx) = p;
            }
        }
}

// ---------------- Fused attention --------------------------------------------
// One block = 128 queries of one (b,h). Loops over 16 chunks of 64 keys:
// S = Q@K^T (tf32 mma), P = exp(-sqrt(max(q2+k2-2S,0)+eps)) (no max-sub: S<=0),
// P round-trips through smem to become the A operand of O += P@V.
// l accumulates in registers; single divide at the end. No HBM P traffic.
// Warp grid 4(M) x 2(N); warp tile 32x32 for both mmas.
#define QS_OFF 0            // 128 x 68
#define KS_OFF 8704         // 64 x 68
#define VS_OFF 13056        // 64 x 72
#define PS_OFF 17664        // 128 x 68
#define Q2_OFF 26368        // 128
#define K2_OFF 26496        // 64
#define LS_OFF 26560        // 128
#define FA_SMEM_FLOATS 26688

__global__ void __launch_bounds__(256, 2) fused_attn_kernel()
{
    extern __shared__ float sm[];
    float* Qs  = sm + QS_OFF;
    float* Ks  = sm + KS_OFF;
    float* Vs  = sm + VS_OFF;
    float* Ps  = sm + PS_OFF;
    float* q2s = sm + Q2_OFF;
    float* k2s = sm + K2_OFF;
    float* ls  = sm + LS_OFF;

    const int t = threadIdx.x, lane = t & 31, wid = t >> 5;
    const int gid = lane >> 2, tig = lane & 3;
    const int wm = (wid >> 1) * 32, wn = (wid & 1) * 32;
    const int i0 = blockIdx.x * 128;
    const int bh = blockIdx.y;
    const float* Qg = g_q + (size_t)bh * Nseq * DH;
    const float* Kg = g_k + (size_t)bh * Nseq * DH;
    const float* Vg = g_v + (size_t)bh * Nseq * DH;

    // load Q tile (tf32-rounded): 128x64 = 2048 float4
    #pragma unroll
    for (int i = 0; i < 8; i++) {
        int f = t + 256 * i;
        int r = f >> 4, c = (f & 15) * 4;
        float4 v = *(const float4*)(Qg + (size_t)(i0 + r) * DH + c);
        float4 w4 = { tfbits(v.x), tfbits(v.y), tfbits(v.z), tfbits(v.w) };
        *(float4*)(Qs + r * 68 + c) = w4;
    }
    if (t < 128) ls[t] = 0.f;
    __syncthreads();
    if (t < 128) {
        float s = 0.f;
        #pragma unroll
        for (int c = 0; c < DH; c += 4) {
            float4 v = *(const float4*)(Qs + t * 68 + c);
            s += v.x*v.x + v.y*v.y + v.z*v.z + v.w*v.w;
        }
        q2s[t] = s;
    }

    float oacc[2][4][4];
    #pragma unroll
    for (int mt = 0; mt < 2; mt++)
        #pragma unroll
        for (int nt = 0; nt < 4; nt++)
            #pragma unroll
            for (int c = 0; c < 4; c++) oacc[mt][nt][c] = 0.f;
    float rs[2][2];
    rs[0][0] = rs[0][1] = rs[1][0] = rs[1][1] = 0.f;

    for (int jc = 0; jc < 16; jc++) {
        int j0 = jc * 64;
        __syncthreads();   // prev iter done reading Ks/Vs/Ps, k2s
        // load K and V chunks (64x64 each = 1024 float4 each -> 4 per thread)
        #pragma unroll
        for (int i = 0; i < 4; i++) {
            int f = t + 256 * i;
            int r = f >> 4, c = (f & 15) * 4;
            float4 kv = *(const float4*)(Kg + (size_t)(j0 + r) * DH + c);
            float4 kw = { tfbits(kv.x), tfbits(kv.y), tfbits(kv.z), tfbits(kv.w) };
            *(float4*)(Ks + r * 68 + c) = kw;
            float4 vv = *(const float4*)(Vg + (size_t)(j0 + r) * DH + c);
            float4 vw = { tfbits(vv.x), tfbits(vv.y), tfbits(vv.z), tfbits(vv.w) };
            *(float4*)(Vs + r * 72 + c) = vw;
        }
        __syncthreads();
        if (t < 64) {
            float s = 0.f;
            #pragma unroll
            for (int c = 0; c < DH; c += 4) {
                float4 v = *(const float4*)(Ks + t * 68 + c);
                s += v.x*v.x + v.y*v.y + v.z*v.z + v.w*v.w;
            }
            k2s[t] = s;
        }

        // S = Q @ K^T over this chunk: M=128, N=64, K=64
        float sacc[2][4][4];
        #pragma unroll
        for (int mt = 0; mt < 2; mt++)
            #pragma unroll
            for (int nt = 0; nt < 4; nt++)
                #pragma unroll
                for (int c = 0; c < 4; c++) sacc[mt][nt][c] = 0.f;
        #pragma unroll
        for (int ks = 0; ks < 8; ks++) {
            int kk = ks * 8;
            u32 a[2][4], b[4][2];
            #pragma unroll
            for (int mt = 0; mt < 2; mt++) ldA(a[mt], Qs, 68, wm + mt * 16, kk, gid, tig);
            #pragma unroll
            for (int nt = 0; nt < 4; nt++) ldBnk(b[nt], Ks, 68, kk, wn + nt * 8, gid, tig);
            #pragma unroll
            for (int mt = 0; mt < 2; mt++)
                #pragma unroll
                for (int nt = 0; nt < 4; nt++) mma8(sacc[mt][nt], a[mt], b[nt]);
        }
        __syncthreads();   // k2s visible to all (also S reads of Ks done)

        // epilogue: P = exp(-dist); accumulate row sums; stash tf32 P in smem
        #pragma unroll
        for (int mt = 0; mt < 2; mt++) {
            int rl = wm + mt * 16 + gid;
            float q2a = q2s[rl], q2b = q2s[rl + 8];
            #pragma unroll
            for (int nt = 0; nt < 4; nt++) {
                int cl = wn + nt * 8 + 2 * tig;
                float k2a = k2s[cl], k2b = k2s[cl + 1];
                float d0 = fmaxf(fmaf(-2.f, sacc[mt][nt][0], q2a + k2a), 0.f) + 1e-8f;
                float d1 = fmaxf(fmaf(-2.f, sacc[mt][nt][1], q2a + k2b), 0.f) + 1e-8f;
                float d2 = fmaxf(fmaf(-2.f, sacc[mt][nt][2], q2b + k2a), 0.f) + 1e-8f;
                float d3 = fmaxf(fmaf(-2.f, sacc[mt][nt][3], q2b + k2b), 0.f) + 1e-8f;
                float p0 = __expf(-sqrtf(d0));
                float p1 = __expf(-sqrtf(d1));
                float p2 = __expf(-sqrtf(d2));
                float p3 = __expf(-sqrtf(d3));
                rs[mt][0] += p0 + p1;
                rs[mt][1] += p2 + p3;
                float2 w0 = { tfbits(p0), tfbits(p1) };
                float2 w1 = { tfbits(p2), tfbits(p3) };
                *(float2*)(Ps + rl * 68 + cl) = w0;
                *(float2*)(Ps + (rl + 8) * 68 + cl) = w1;
            }
        }
        __syncthreads();   // Ps visible

        // O += P @ V : M=128, N=64(dh), K=64(keys)
        #pragma unroll
        for (int ks = 0; ks < 8; ks++) {
            int kk = ks * 8;
            u32 a[2][4], b[4][2];
            #pragma unroll
            for (int mt = 0; mt < 2; mt++) ldA(a[mt], Ps, 68, wm + mt * 16, kk, gid, tig);
            #pragma unroll
            for (int nt = 0; nt < 4; nt++) ldBkn(b[nt], Vs, 72, kk, wn + nt * 8, gid, tig);
            #pragma unroll
            for (int mt = 0; mt < 2; mt++)
                #pragma unroll
                for (int nt = 0; nt < 4; nt++) mma8(oacc[mt][nt], a[mt], b[nt]);
        }
    }

    // reduce row sums: quad shuffle, then across the 2 n-warps via shared atomics
    #pragma unroll
    for (int mt = 0; mt < 2; mt++) {
        float v0 = rs[mt][0], v1 = rs[mt][1];
        v0 += __shfl_xor_sync(0xffffffffu, v0, 1);
        v0 += __shfl_xor_sync(0xffffffffu, v0, 2);
        v1 += __shfl_xor_sync(0xffffffffu, v1, 1);
        v1 += __shfl_xor_sync(0xffffffffu, v1, 2);
        if (tig == 0) {
            atomicAdd(&ls[wm + mt * 16 + gid], v0);
            atomicAdd(&ls[wm + mt * 16 + gid + 8], v1);
        }
    }
    __syncthreads();

    const int b = bh >> 3, h = bh & 7;
    #pragma unroll
    for (int mt = 0; mt < 2; mt++) {
        int rl = wm + mt * 16 + gid;
        int i  = i0 + rl;
        float li0 = 1.0f / ls[rl];
        float li1 = 1.0f / ls[rl + 8];
        #pragma unroll
        for (int nt = 0; nt < 4; nt++) {
            int dh = wn + nt * 8 + 2 * tig;
            float2 w0 = { oacc[mt][nt][0] * li0, oacc[mt][nt][1] * li0 };
            float2 w1 = { oacc[mt][nt][2] * li1, oacc[mt][nt][3] * li1 };
            *(float2*)(g_attnout + ((size_t)(b * Nseq + i) * Ddim + h * DH + dh)) = w0;
            *(float2*)(g_attnout + ((size_t)(b * Nseq + i + 8) * Ddim + h * DH + dh)) = w1;
        }
    }
}

// ---------------- launch ------------------------------------------------------
extern "C" void kernel_launch(void* const* d_in, const int* in_sizes, int n_in,
                              void* d_out, int out_size)
{
    const float* x = nullptr;
    const float* Wm[4] = {nullptr, nullptr, nullptr, nullptr};
    const float* vec[8] = {nullptr};
    int nm = 0, nv = 0;
    for (int i = 0; i < n_in; i++) {
        if (in_sizes[i] == BN_ROWS * Ddim)      x = (const float*)d_in[i];
        else if (in_sizes[i] == Ddim * Ddim)    { if (nm < 4) Wm[nm++] = (const float*)d_in[i]; }
        else if (in_sizes[i] == Ddim)           { if (nv < 8) vec[nv++] = (const float*)d_in[i]; }
    }
    const float *Wq = Wm[0], *Wk = Wm[1], *Wv = Wm[2], *Wo = Wm[3];
    const float *bq = vec[0], *bk = vec[1], *bv = vec[2], *bo = vec[3];
    const float *ln1g = vec[4], *ln1b = vec[5], *ln2g = vec[6], *ln2b = vec[7];

    void *p_h = nullptr, *p_y = nullptr;
    cudaGetSymbolAddress(&p_h, g_h);
    cudaGetSymbolAddress(&p_y, g_y);

    const int fa_smem = FA_SMEM_FLOATS * sizeof(float);   // 106752 B
    cudaFuncSetAttribute(fused_attn_kernel,
                         cudaFuncAttributeMaxDynamicSharedMemorySize, fa_smem);

    ln_kernel<<<BN_ROWS, 128>>>(x, ln1g, ln1b, (float*)p_h);
    qkv_mma_kernel<<<dim3(Ddim / 128, BN_ROWS / 128, 3), 256>>>(Wq, Wk, Wv, bq, bk, bv);
    fused_attn_kernel<<<dim3(Nseq / 128, NBH), 256, fa_smem>>>();
    proj_mma_kernel<<<dim3(Ddim / 128, BN_ROWS / 128), 256>>>(Wo, bo, x);
    ln_kernel<<<BN_ROWS, 128>>>((const float*)p_y, ln2g, ln2b, (float*)d_out);
}

// round 6
// speedup vs baseline: 5.0842x; 1.1645x over previous
#include <cuda_runtime.h>
#include <cuda_bf16.h>
#include <stdint.h>
#include <cstdint>
#include <math.h>

#define Bdim 8
#define Nseq 1024
#define Ddim 512
#define Hn 8
#define DH 64
#define BN_ROWS (Bdim * Nseq)   // 8192
#define NBH (Bdim * Hn)         // 64

typedef unsigned int u32;
typedef __nv_bfloat16 bf16;
typedef __nv_bfloat162 bf162;

// ---------------- scratch (device globals; no allocation allowed) ------------
__device__ bf16  g_h[BN_ROWS * Ddim];        // LN1 output (bf16)
__device__ float g_q[BN_ROWS * Ddim];        // [BH, N, DH] f32
__device__ float g_k[BN_ROWS * Ddim];
__device__ float g_v[BN_ROWS * Ddim];
__device__ float g_attnout[BN_ROWS * Ddim];  // [B, N, D] f32
__device__ float g_y[BN_ROWS * Ddim];        // proj + residual, pre-LN2 (f32)

// ---------------- bf16 mma helpers --------------------------------------------
__device__ __forceinline__ u32 s2u(const void* p) {
    u32 a;
    asm("{ .reg .u64 t; cvta.to.shared.u64 t, %1; cvt.u32.u64 %0, t; }" : "=r"(a) : "l"(p));
    return a;
}
__device__ __forceinline__ void ldsm4(u32* r, u32 addr) {
    asm volatile("ldmatrix.sync.aligned.m8n8.x4.shared.b16 {%0,%1,%2,%3},[%4];"
                 : "=r"(r[0]), "=r"(r[1]), "=r"(r[2]), "=r"(r[3]) : "r"(addr));
}
__device__ __forceinline__ void ldsm4t(u32* r, u32 addr) {
    asm volatile("ldmatrix.sync.aligned.m8n8.x4.trans.shared.b16 {%0,%1,%2,%3},[%4];"
                 : "=r"(r[0]), "=r"(r[1]), "=r"(r[2]), "=r"(r[3]) : "r"(addr));
}
__device__ __forceinline__ void mma16(float* c, const u32* a, const u32* b) {
    asm volatile(
        "mma.sync.aligned.m16n8k16.row.col.f32.bf16.bf16.f32 "
        "{%0,%1,%2,%3},{%4,%5,%6,%7},{%8,%9},{%0,%1,%2,%3};\n"
        : "+f"(c[0]), "+f"(c[1]), "+f"(c[2]), "+f"(c[3])
        : "r"(a[0]), "r"(a[1]), "r"(a[2]), "r"(a[3]), "r"(b[0]), "r"(b[1]));
}
// A-operand 16x16 tile at (mm, k) in row-major [m][k] smem
__device__ __forceinline__ u32 aaddr(const bf16* base, int stride, int mm, int k, int lane) {
    int row = mm + (lane & 7) + (((lane >> 3) & 1) << 3);
    int col = k + ((lane >> 4) << 3);
    return s2u(base + row * stride + col);
}
// B-operand (trans), memory rows = k, cols = n, covers k..k+15, n..n+15
__device__ __forceinline__ u32 baddr_t(const bf16* base, int stride, int k, int n, int lane) {
    int m = lane >> 3;
    int row = k + ((m & 1) << 3) + (lane & 7);
    int col = n + ((m >> 1) << 3);
    return s2u(base + row * stride + col);
}

// ---------------- tf32 mma helpers (attention, known-good R4 path) ------------
__device__ __forceinline__ u32 f2tf(float f) {
    u32 u;
    asm("cvt.rna.tf32.f32 %0, %1;" : "=r"(u) : "f"(f));
    return u;
}
__device__ __forceinline__ float tfbits(float f) { return __uint_as_float(f2tf(f)); }

__device__ __forceinline__ void mma8(float* c, const u32* a, const u32* b) {
    asm volatile(
        "mma.sync.aligned.m16n8k8.row.col.f32.tf32.tf32.f32 "
        "{%0,%1,%2,%3},{%4,%5,%6,%7},{%8,%9},{%0,%1,%2,%3};\n"
        : "+f"(c[0]), "+f"(c[1]), "+f"(c[2]), "+f"(c[3])
        : "r"(a[0]), "r"(a[1]), "r"(a[2]), "r"(a[3]), "r"(b[0]), "r"(b[1]));
}
__device__ __forceinline__ void ldAf(u32* a, const float* S, int stride,
                                     int m, int k, int gid, int tig) {
    a[0] = __float_as_uint(S[(m + gid) * stride + k + tig]);
    a[1] = __float_as_uint(S[(m + gid + 8) * stride + k + tig]);
    a[2] = __float_as_uint(S[(m + gid) * stride + k + tig + 4]);
    a[3] = __float_as_uint(S[(m + gid + 8) * stride + k + tig + 4]);
}
__device__ __forceinline__ void ldBknf(u32* b, const float* S, int stride,
                                       int k, int n, int gid, int tig) {
    b[0] = __float_as_uint(S[(k + tig) * stride + n + gid]);
    b[1] = __float_as_uint(S[(k + tig + 4) * stride + n + gid]);
}
__device__ __forceinline__ void ldBnkf(u32* b, const float* S, int stride,
                                       int k, int n, int gid, int tig) {
    b[0] = __float_as_uint(S[(n + gid) * stride + k + tig]);
    b[1] = __float_as_uint(S[(n + gid) * stride + k + tig + 4]);
}

// ---------------- LayerNorm ---------------------------------------------------
__device__ __forceinline__ float4 ln_row_body(const float* __restrict__ in,
                                              const float* __restrict__ gamma,
                                              const float* __restrict__ beta,
                                              int row)
{
    const float4* r = (const float4*)(in + (size_t)row * Ddim);
    float4 a = r[threadIdx.x];
    float s  = a.x + a.y + a.z + a.w;
    float s2 = a.x*a.x + a.y*a.y + a.z*a.z + a.w*a.w;
    #pragma unroll
    for (int off = 16; off; off >>= 1) {
        s  += __shfl_xor_sync(0xffffffffu, s,  off);
        s2 += __shfl_xor_sync(0xffffffffu, s2, off);
    }
    __shared__ float sbA[4], sbB[4];
    int wid = threadIdx.x >> 5, lane = threadIdx.x & 31;
    if (lane == 0) { sbA[wid] = s; sbB[wid] = s2; }
    __syncthreads();
    s  = sbA[0] + sbA[1] + sbA[2] + sbA[3];
    s2 = sbB[0] + sbB[1] + sbB[2] + sbB[3];
    float mean = s * (1.0f / Ddim);
    float var  = s2 * (1.0f / Ddim) - mean * mean;
    float rstd = rsqrtf(var + 1e-5f);
    float4 g = ((const float4*)gamma)[threadIdx.x];
    float4 b = ((const float4*)beta)[threadIdx.x];
    float4 o;
    o.x = (a.x - mean) * rstd * g.x + b.x;
    o.y = (a.y - mean) * rstd * g.y + b.y;
    o.z = (a.z - mean) * rstd * g.z + b.z;
    o.w = (a.w - mean) * rstd * g.w + b.w;
    return o;
}

__global__ void ln_bf16_kernel(const float* __restrict__ in,
                               const float* __restrict__ gamma,
                               const float* __restrict__ beta,
                               bf16* __restrict__ out)
{
    int row = blockIdx.x;
    float4 o = ln_row_body(in, gamma, beta, row);
    bf162 lo = __floats2bfloat162_rn(o.x, o.y);
    bf162 hi = __floats2bfloat162_rn(o.z, o.w);
    uint2 pk = { *(u32*)&lo, *(u32*)&hi };
    *(uint2*)(out + (size_t)row * Ddim + 4 * threadIdx.x) = pk;
}

__global__ void ln_f32_kernel(const float* __restrict__ in,
                              const float* __restrict__ gamma,
                              const float* __restrict__ beta,
                              float* __restrict__ out)
{
    int row = blockIdx.x;
    float4 o = ln_row_body(in, gamma, beta, row);
    ((float4*)(out + (size_t)row * Ddim))[threadIdx.x] = o;
}

// ---------------- bf16 MMA GEMM core ------------------------------------------
// Block 128(M) x 128(N), K-chunk 64, 256 threads, warp grid 2(M) x 4(N),
// warp tile 64x32 -> 4 mt x 4 nt of m16n8k16, ldmatrix fragment loads.
#define AST 72
#define WST 136
template <bool A_IS_BF16>
__device__ __forceinline__ void gemm_bf16_body(const void* __restrict__ Aptr,
                                               const float* __restrict__ W,
                                               float acc[4][4][4],
                                               bf16* As, bf16* Ws)
{
    const int t = threadIdx.x, lane = t & 31, wid = t >> 5;
    const int wm = (wid >> 2) * 64, wn = (wid & 3) * 32;
    const int m0 = blockIdx.y * 128, n0 = blockIdx.x * 128;

    #pragma unroll
    for (int i = 0; i < 4; i++)
        #pragma unroll
        for (int j = 0; j < 4; j++)
            #pragma unroll
            for (int c = 0; c < 4; c++) acc[i][j][c] = 0.f;

    for (int k0 = 0; k0 < Ddim; k0 += 64) {
        if (A_IS_BF16) {
            const bf16* A = (const bf16*)Aptr;
            #pragma unroll
            for (int i = 0; i < 4; i++) {       // 128x64 bf16 = 1024 uint4
                int f = t + 256 * i;
                int r = f >> 3, c = (f & 7) * 8;
                *(uint4*)(As + r * AST + c) =
                    *(const uint4*)(A + (size_t)(m0 + r) * Ddim + k0 + c);
            }
        } else {
            const float* A = (const float*)Aptr;
            #pragma unroll
            for (int i = 0; i < 8; i++) {       // 128x64 f32 = 2048 float4
                int f = t + 256 * i;
                int r = f >> 4, c = (f & 15) * 4;
                float4 v = *(const float4*)(A + (size_t)(m0 + r) * Ddim + k0 + c);
                bf162 lo = __floats2bfloat162_rn(v.x, v.y);
                bf162 hi = __floats2bfloat162_rn(v.z, v.w);
                uint2 pk = { *(u32*)&lo, *(u32*)&hi };
                *(uint2*)(As + r * AST + c) = pk;
            }
        }
        // W chunk 64x128 f32 -> bf16: 2048 float4
        #pragma unroll
        for (int i = 0; i < 8; i++) {
            int f = t + 256 * i;
            int r = f >> 5, c = (f & 31) * 4;
            float4 v = *(const float4*)(W + (size_t)(k0 + r) * Ddim + n0 + c);
            bf162 lo = __floats2bfloat162_rn(v.x, v.y);
            bf162 hi = __floats2bfloat162_rn(v.z, v.w);
            uint2 pk = { *(u32*)&lo, *(u32*)&hi };
            *(uint2*)(Ws + r * WST + c) = pk;
        }
        __syncthreads();
        #pragma unroll
        for (int ks = 0; ks < 4; ks++) {
            int kk = ks * 16;
            u32 a[4][4], b[4][2];
            #pragma unroll
            for (int mt = 0; mt < 4; mt++)
                ldsm4(a[mt], aaddr(As, AST, wm + mt * 16, kk, lane));
            #pragma unroll
            for (int p = 0; p < 2; p++) {
                u32 bb[4];
                ldsm4t(bb, baddr_t(Ws, WST, kk, wn + 16 * p, lane));
                b[2*p][0] = bb[0]; b[2*p][1] = bb[1];
                b[2*p+1][0] = bb[2]; b[2*p+1][1] = bb[3];
            }
            #pragma unroll
            for (int mt = 0; mt < 4; mt++)
                #pragma unroll
                for (int nt = 0; nt < 4; nt++) mma16(acc[mt][nt], a[mt], b[nt]);
        }
        __syncthreads();
    }
}

// QKV: z picks {q,k,v}; f32 output in [BH, N, DH] layout, bias fused.
__global__ void __launch_bounds__(256) qkv_mma_kernel(
    const float* __restrict__ Wq, const float* __restrict__ Wk,
    const float* __restrict__ Wv, const float* __restrict__ bq,
    const float* __restrict__ bk, const float* __restrict__ bv)
{
    __shared__ bf16 As[128 * AST];
    __shared__ bf16 Ws[64 * WST];
    __shared__ float bs[128];
    const float* W; const float* bias; float* O;
    if (blockIdx.z == 0)      { W = Wq; bias = bq; O = g_q; }
    else if (blockIdx.z == 1) { W = Wk; bias = bk; O = g_k; }
    else                      { W = Wv; bias = bv; O = g_v; }

    const int t = threadIdx.x, lane = t & 31, wid = t >> 5;
    const int gid = lane >> 2, tig = lane & 3;
    const int wm = (wid >> 2) * 64, wn = (wid & 3) * 32;
    const int m0 = blockIdx.y * 128, n0 = blockIdx.x * 128;
    if (t < 128) bs[t] = bias[n0 + t];

    float acc[4][4][4];
    gemm_bf16_body<true>(g_h, W, acc, As, Ws);

    #pragma unroll
    for (int mt = 0; mt < 4; mt++)
        #pragma unroll
        for (int nt = 0; nt < 4; nt++) {
            int cl = wn + nt * 8 + 2 * tig;
            int n  = n0 + cl;
            int h  = n >> 6, dh = n & 63;
            int mr = m0 + wm + mt * 16 + gid;
            {
                int b0i = mr >> 10, ns = mr & 1023;
                float2 p = { acc[mt][nt][0] + bs[cl], acc[mt][nt][1] + bs[cl + 1] };
                *(float2*)(O + (((size_t)(b0i * Hn + h) * Nseq + ns) * DH + dh)) = p;
            }
            {
                int mr2 = mr + 8;
                int b0i = mr2 >> 10, ns = mr2 & 1023;
                float2 p = { acc[mt][nt][2] + bs[cl], acc[mt][nt][3] + bs[cl + 1] };
                *(float2*)(O + (((size_t)(b0i * Hn + h) * Nseq + ns) * DH + dh)) = p;
            }
        }
}

// Output projection: g_y = attnout @ Wo + bo + x   (f32 in/out, bf16 compute)
__global__ void __launch_bounds__(256) proj_mma_kernel(
    const float* __restrict__ Wo, const float* __restrict__ bo,
    const float* __restrict__ xres)
{
    __shared__ bf16 As[128 * AST];
    __shared__ bf16 Ws[64 * WST];
    __shared__ float bs[128];
    const int t = threadIdx.x, lane = t & 31, wid = t >> 5;
    const int gid = lane >> 2, tig = lane & 3;
    const int wm = (wid >> 2) * 64, wn = (wid & 3) * 32;
    const int m0 = blockIdx.y * 128, n0 = blockIdx.x * 128;
    if (t < 128) bs[t] = bo[n0 + t];

    float acc[4][4][4];
    gemm_bf16_body<false>(g_attnout, Wo, acc, As, Ws);

    #pragma unroll
    for (int mt = 0; mt < 4; mt++)
        #pragma unroll
        for (int nt = 0; nt < 4; nt++) {
            int cl = wn + nt * 8 + 2 * tig;
            int n  = n0 + cl;
            int mr = m0 + wm + mt * 16 + gid;
            {
                size_t idx = (size_t)mr * Ddim + n;
                float2 xr = *(const float2*)(xres + idx);
                float2 p = { acc[mt][nt][0] + bs[cl] + xr.x,
                             acc[mt][nt][1] + bs[cl + 1] + xr.y };
                *(float2*)(g_y + idx) = p;
            }
            {
                size_t idx = (size_t)(mr + 8) * Ddim + n;
                float2 xr = *(const float2*)(xres + idx);
                float2 p = { acc[mt][nt][2] + bs[cl] + xr.x,
                             acc[mt][nt][3] + bs[cl + 1] + xr.y };
                *(float2*)(g_y + idx) = p;
            }
        }
}

// ---------------- Fused attention (R4 tf32 path, known good) ------------------
#define QS_OFF 0            // 128 x 68
#define KS_OFF 8704         // 64 x 68
#define VS_OFF 13056        // 64 x 72
#define PS_OFF 17664        // 128 x 68
#define Q2_OFF 26368        // 128
#define K2_OFF 26496        // 64
#define LS_OFF 26560        // 128
#define FA_SMEM_FLOATS 26688

__global__ void __launch_bounds__(256, 2) fused_attn_kernel()
{
    extern __shared__ float sm[];
    float* Qs  = sm + QS_OFF;
    float* Ks  = sm + KS_OFF;
    float* Vs  = sm + VS_OFF;
    float* Ps  = sm + PS_OFF;
    float* q2s = sm + Q2_OFF;
    float* k2s = sm + K2_OFF;
    float* ls  = sm + LS_OFF;

    const int t = threadIdx.x, lane = t & 31, wid = t >> 5;
    const int gid = lane >> 2, tig = lane & 3;
    const int wm = (wid >> 1) * 32, wn = (wid & 1) * 32;
    const int i0 = blockIdx.x * 128;
    const int bh = blockIdx.y;
    const float* Qg = g_q + (size_t)bh * Nseq * DH;
    const float* Kg = g_k + (size_t)bh * Nseq * DH;
    const float* Vg = g_v + (size_t)bh * Nseq * DH;

    #pragma unroll
    for (int i = 0; i < 8; i++) {
        int f = t + 256 * i;
        int r = f >> 4, c = (f & 15) * 4;
        float4 v = *(const float4*)(Qg + (size_t)(i0 + r) * DH + c);
        float4 w4 = { tfbits(v.x), tfbits(v.y), tfbits(v.z), tfbits(v.w) };
        *(float4*)(Qs + r * 68 + c) = w4;
    }
    if (t < 128) ls[t] = 0.f;
    __syncthreads();
    if (t < 128) {
        float s = 0.f;
        #pragma unroll
        for (int c = 0; c < DH; c += 4) {
            float4 v = *(const float4*)(Qs + t * 68 + c);
            s += v.x*v.x + v.y*v.y + v.z*v.z + v.w*v.w;
        }
        q2s[t] = s;
    }

    float oacc[2][4][4];
    #pragma unroll
    for (int mt = 0; mt < 2; mt++)
        #pragma unroll
        for (int nt = 0; nt < 4; nt++)
            #pragma unroll
            for (int c = 0; c < 4; c++) oacc[mt][nt][c] = 0.f;
    float rs[2][2];
    rs[0][0] = rs[0][1] = rs[1][0] = rs[1][1] = 0.f;

    for (int jc = 0; jc < 16; jc++) {
        int j0 = jc * 64;
        __syncthreads();
        #pragma unroll
        for (int i = 0; i < 4; i++) {
            int f = t + 256 * i;
            int r = f >> 4, c = (f & 15) * 4;
            float4 kv = *(const float4*)(Kg + (size_t)(j0 + r) * DH + c);
            float4 kw = { tfbits(kv.x), tfbits(kv.y), tfbits(kv.z), tfbits(kv.w) };
            *(float4*)(Ks + r * 68 + c) = kw;
            float4 vv = *(const float4*)(Vg + (size_t)(j0 + r) * DH + c);
            float4 vw = { tfbits(vv.x), tfbits(vv.y), tfbits(vv.z), tfbits(vv.w) };
            *(float4*)(Vs + r * 72 + c) = vw;
        }
        __syncthreads();
        if (t < 64) {
            float s = 0.f;
            #pragma unroll
            for (int c = 0; c < DH; c += 4) {
                float4 v = *(const float4*)(Ks + t * 68 + c);
                s += v.x*v.x + v.y*v.y + v.z*v.z + v.w*v.w;
            }
            k2s[t] = s;
        }

        float sacc[2][4][4];
        #pragma unroll
        for (int mt = 0; mt < 2; mt++)
            #pragma unroll
            for (int nt = 0; nt < 4; nt++)
                #pragma unroll
                for (int c = 0; c < 4; c++) sacc[mt][nt][c] = 0.f;
        #pragma unroll
        for (int ks = 0; ks < 8; ks++) {
            int kk = ks * 8;
            u32 a[2][4], b[4][2];
            #pragma unroll
            for (int mt = 0; mt < 2; mt++) ldAf(a[mt], Qs, 68, wm + mt * 16, kk, gid, tig);
            #pragma unroll
            for (int nt = 0; nt < 4; nt++) ldBnkf(b[nt], Ks, 68, kk, wn + nt * 8, gid, tig);
            #pragma unroll
            for (int mt = 0; mt < 2; mt++)
                #pragma unroll
                for (int nt = 0; nt < 4; nt++) mma8(sacc[mt][nt], a[mt], b[nt]);
        }
        __syncthreads();

        #pragma unroll
        for (int mt = 0; mt < 2; mt++) {
            int rl = wm + mt * 16 + gid;
            float q2a = q2s[rl], q2b = q2s[rl + 8];
            #pragma unroll
            for (int nt = 0; nt < 4; nt++) {
                int cl = wn + nt * 8 + 2 * tig;
                float k2a = k2s[cl], k2b = k2s[cl + 1];
                float d0 = fmaxf(fmaf(-2.f, sacc[mt][nt][0], q2a + k2a), 0.f) + 1e-8f;
                float d1 = fmaxf(fmaf(-2.f, sacc[mt][nt][1], q2a + k2b), 0.f) + 1e-8f;
                float d2 = fmaxf(fmaf(-2.f, sacc[mt][nt][2], q2b + k2a), 0.f) + 1e-8f;
                float d3 = fmaxf(fmaf(-2.f, sacc[mt][nt][3], q2b + k2b), 0.f) + 1e-8f;
                float p0 = __expf(-sqrtf(d0));
                float p1 = __expf(-sqrtf(d1));
                float p2 = __expf(-sqrtf(d2));
                float p3 = __expf(-sqrtf(d3));
                rs[mt][0] += p0 + p1;
                rs[mt][1] += p2 + p3;
                float2 w0 = { tfbits(p0), tfbits(p1) };
                float2 w1 = { tfbits(p2), tfbits(p3) };
                *(float2*)(Ps + rl * 68 + cl) = w0;
                *(float2*)(Ps + (rl + 8) * 68 + cl) = w1;
            }
        }
        __syncthreads();

        #pragma unroll
        for (int ks = 0; ks < 8; ks++) {
            int kk = ks * 8;
            u32 a[2][4], b[4][2];
            #pragma unroll
            for (int mt = 0; mt < 2; mt++) ldAf(a[mt], Ps, 68, wm + mt * 16, kk, gid, tig);
            #pragma unroll
            for (int nt = 0; nt < 4; nt++) ldBknf(b[nt], Vs, 72, kk, wn + nt * 8, gid, tig);
            #pragma unroll
            for (int mt = 0; mt < 2; mt++)
                #pragma unroll
                for (int nt = 0; nt < 4; nt++) mma8(oacc[mt][nt], a[mt], b[nt]);
        }
    }

    #pragma unroll
    for (int mt = 0; mt < 2; mt++) {
        float v0 = rs[mt][0], v1 = rs[mt][1];
        v0 += __shfl_xor_sync(0xffffffffu, v0, 1);
        v0 += __shfl_xor_sync(0xffffffffu, v0, 2);
        v1 += __shfl_xor_sync(0xffffffffu, v1, 1);
        v1 += __shfl_xor_sync(0xffffffffu, v1, 2);
        if (tig == 0) {
            atomicAdd(&ls[wm + mt * 16 + gid], v0);
            atomicAdd(&ls[wm + mt * 16 + gid + 8], v1);
        }
    }
    __syncthreads();

    const int b = bh >> 3, h = bh & 7;
    #pragma unroll
    for (int mt = 0; mt < 2; mt++) {
        int rl = wm + mt * 16 + gid;
        int i  = i0 + rl;
        float li0 = 1.0f / ls[rl];
        float li1 = 1.0f / ls[rl + 8];
        #pragma unroll
        for (int nt = 0; nt < 4; nt++) {
            int dh = wn + nt * 8 + 2 * tig;
            float2 w0 = { oacc[mt][nt][0] * li0, oacc[mt][nt][1] * li0 };
            float2 w1 = { oacc[mt][nt][2] * li1, oacc[mt][nt][3] * li1 };
            *(float2*)(g_attnout + ((size_t)(b * Nseq + i) * Ddim + h * DH + dh)) = w0;
            *(float2*)(g_attnout + ((size_t)(b * Nseq + i + 8) * Ddim + h * DH + dh)) = w1;
        }
    }
}

// ---------------- launch ------------------------------------------------------
extern "C" void kernel_launch(void* const* d_in, const int* in_sizes, int n_in,
                              void* d_out, int out_size)
{
    const float* x = nullptr;
    const float* Wm[4] = {nullptr, nullptr, nullptr, nullptr};
    const float* vec[8] = {nullptr};
    int nm = 0, nv = 0;
    for (int i = 0; i < n_in; i++) {
        if (in_sizes[i] == BN_ROWS * Ddim)      x = (const float*)d_in[i];
        else if (in_sizes[i] == Ddim * Ddim)    { if (nm < 4) Wm[nm++] = (const float*)d_in[i]; }
        else if (in_sizes[i] == Ddim)           { if (nv < 8) vec[nv++] = (const float*)d_in[i]; }
    }
    const float *Wq = Wm[0], *Wk = Wm[1], *Wv = Wm[2], *Wo = Wm[3];
    const float *bq = vec[0], *bk = vec[1], *bv = vec[2], *bo = vec[3];
    const float *ln1g = vec[4], *ln1b = vec[5], *ln2g = vec[6], *ln2b = vec[7];

    void *p_h = nullptr, *p_y = nullptr;
    cudaGetSymbolAddress(&p_h, g_h);
    cudaGetSymbolAddress(&p_y, g_y);

    const int fa_smem = FA_SMEM_FLOATS * sizeof(float);   // 106752 B
    cudaFuncSetAttribute(fused_attn_kernel,
                         cudaFuncAttributeMaxDynamicSharedMemorySize, fa_smem);

    ln_bf16_kernel<<<BN_ROWS, 128>>>(x, ln1g, ln1b, (bf16*)p_h);
    qkv_mma_kernel<<<dim3(Ddim / 128, BN_ROWS / 128, 3), 256>>>(Wq, Wk, Wv, bq, bk, bv);
    fused_attn_kernel<<<dim3(Nseq / 128, NBH), 256, fa_smem>>>();
    proj_mma_kernel<<<dim3(Ddim / 128, BN_ROWS / 128), 256>>>(Wo, bo, x);
    ln_f32_kernel<<<BN_ROWS, 128>>>((const float*)p_y, ln2g, ln2b, (float*)d_out);
}

// round 7
// speedup vs baseline: 5.8010x; 1.1410x over previous
#include <cuda_runtime.h>
#include <cuda_bf16.h>
#include <stdint.h>
#include <cstdint>
#include <math.h>

#define Bdim 8
#define Nseq 1024
#define Ddim 512
#define Hn 8
#define DH 64
#define BN_ROWS (Bdim * Nseq)   // 8192
#define NBH (Bdim * Hn)         // 64

typedef unsigned int u32;
typedef __nv_bfloat16 bf16;
typedef __nv_bfloat162 bf162;

// ---------------- scratch (device globals; no allocation allowed) ------------
__device__ bf16  g_h[BN_ROWS * Ddim];        // LN1 output (bf16)
__device__ bf16  g_q[BN_ROWS * Ddim];        // [BH, N, DH] bf16
__device__ bf16  g_k[BN_ROWS * Ddim];
__device__ bf16  g_v[BN_ROWS * Ddim];
__device__ bf16  g_attnout[BN_ROWS * Ddim];  // [B, N, D] bf16
__device__ float g_y[BN_ROWS * Ddim];        // proj + residual, pre-LN2 (f32)

// ---------------- bf16 mma helpers --------------------------------------------
__device__ __forceinline__ u32 s2u(const void* p) {
    u32 a;
    asm("{ .reg .u64 t; cvta.to.shared.u64 t, %1; cvt.u32.u64 %0, t; }" : "=r"(a) : "l"(p));
    return a;
}
__device__ __forceinline__ void ldsm4(u32* r, u32 addr) {
    asm volatile("ldmatrix.sync.aligned.m8n8.x4.shared.b16 {%0,%1,%2,%3},[%4];"
                 : "=r"(r[0]), "=r"(r[1]), "=r"(r[2]), "=r"(r[3]) : "r"(addr));
}
__device__ __forceinline__ void ldsm4t(u32* r, u32 addr) {
    asm volatile("ldmatrix.sync.aligned.m8n8.x4.trans.shared.b16 {%0,%1,%2,%3},[%4];"
                 : "=r"(r[0]), "=r"(r[1]), "=r"(r[2]), "=r"(r[3]) : "r"(addr));
}
__device__ __forceinline__ void mma16(float* c, const u32* a, const u32* b) {
    asm volatile(
        "mma.sync.aligned.m16n8k16.row.col.f32.bf16.bf16.f32 "
        "{%0,%1,%2,%3},{%4,%5,%6,%7},{%8,%9},{%0,%1,%2,%3};\n"
        : "+f"(c[0]), "+f"(c[1]), "+f"(c[2]), "+f"(c[3])
        : "r"(a[0]), "r"(a[1]), "r"(a[2]), "r"(a[3]), "r"(b[0]), "r"(b[1]));
}
// A-operand 16x16 tile at (mm, k) in row-major [m][k] smem
__device__ __forceinline__ u32 aaddr(const bf16* base, int stride, int mm, int k, int lane) {
    int row = mm + (lane & 7) + (((lane >> 3) & 1) << 3);
    int col = k + ((lane >> 4) << 3);
    return s2u(base + row * stride + col);
}
// B-operand, memory rows = n, cols = k (k-contiguous), covers n..n+15, k..k+15
__device__ __forceinline__ u32 baddr_k(const bf16* base, int stride, int n, int k, int lane) {
    int m = lane >> 3;
    int row = n + ((m >> 1) << 3) + (lane & 7);
    int col = k + ((m & 1) << 3);
    return s2u(base + row * stride + col);
}
// B-operand (trans), memory rows = k, cols = n, covers k..k+15, n..n+15
__device__ __forceinline__ u32 baddr_t(const bf16* base, int stride, int k, int n, int lane) {
    int m = lane >> 3;
    int row = k + ((m & 1) << 3) + (lane & 7);
    int col = n + ((m >> 1) << 3);
    return s2u(base + row * stride + col);
}
__device__ __forceinline__ float2 b2f(u32 u) {
    bf162 h = *(bf162*)&u;
    return __bfloat1622float2(h);
}

// ---------------- LayerNorm ---------------------------------------------------
__device__ __forceinline__ float4 ln_row_body(const float* __restrict__ in,
                                              const float* __restrict__ gamma,
                                              const float* __restrict__ beta,
                                              int row)
{
    const float4* r = (const float4*)(in + (size_t)row * Ddim);
    float4 a = r[threadIdx.x];
    float s  = a.x + a.y + a.z + a.w;
    float s2 = a.x*a.x + a.y*a.y + a.z*a.z + a.w*a.w;
    #pragma unroll
    for (int off = 16; off; off >>= 1) {
        s  += __shfl_xor_sync(0xffffffffu, s,  off);
        s2 += __shfl_xor_sync(0xffffffffu, s2, off);
    }
    __shared__ float sbA[4], sbB[4];
    int wid = threadIdx.x >> 5, lane = threadIdx.x & 31;
    if (lane == 0) { sbA[wid] = s; sbB[wid] = s2; }
    __syncthreads();
    s  = sbA[0] + sbA[1] + sbA[2] + sbA[3];
    s2 = sbB[0] + sbB[1] + sbB[2] + sbB[3];
    float mean = s * (1.0f / Ddim);
    float var  = s2 * (1.0f / Ddim) - mean * mean;
    float rstd = rsqrtf(var + 1e-5f);
    float4 g = ((const float4*)gamma)[threadIdx.x];
    float4 b = ((const float4*)beta)[threadIdx.x];
    float4 o;
    o.x = (a.x - mean) * rstd * g.x + b.x;
    o.y = (a.y - mean) * rstd * g.y + b.y;
    o.z = (a.z - mean) * rstd * g.z + b.z;
    o.w = (a.w - mean) * rstd * g.w + b.w;
    return o;
}

__global__ void ln_bf16_kernel(const float* __restrict__ in,
                               const float* __restrict__ gamma,
                               const float* __restrict__ beta,
                               bf16* __restrict__ out)
{
    int row = blockIdx.x;
    float4 o = ln_row_body(in, gamma, beta, row);
    bf162 lo = __floats2bfloat162_rn(o.x, o.y);
    bf162 hi = __floats2bfloat162_rn(o.z, o.w);
    uint2 pk = { *(u32*)&lo, *(u32*)&hi };
    *(uint2*)(out + (size_t)row * Ddim + 4 * threadIdx.x) = pk;
}

__global__ void ln_f32_kernel(const float* __restrict__ in,
                              const float* __restrict__ gamma,
                              const float* __restrict__ beta,
                              float* __restrict__ out)
{
    int row = blockIdx.x;
    float4 o = ln_row_body(in, gamma, beta, row);
    ((float4*)(out + (size_t)row * Ddim))[threadIdx.x] = o;
}

// ---------------- bf16 MMA GEMM core (validated in R6) ------------------------
#define AST 72
#define WST 136
__device__ __forceinline__ void gemm_bf16_body(const bf16* __restrict__ A,
                                               const float* __restrict__ W,
                                               float acc[4][4][4],
                                               bf16* As, bf16* Ws)
{
    const int t = threadIdx.x, lane = t & 31, wid = t >> 5;
    const int wm = (wid >> 2) * 64, wn = (wid & 3) * 32;
    const int m0 = blockIdx.y * 128, n0 = blockIdx.x * 128;

    #pragma unroll
    for (int i = 0; i < 4; i++)
        #pragma unroll
        for (int j = 0; j < 4; j++)
            #pragma unroll
            for (int c = 0; c < 4; c++) acc[i][j][c] = 0.f;

    for (int k0 = 0; k0 < Ddim; k0 += 64) {
        #pragma unroll
        for (int i = 0; i < 4; i++) {       // A: 128x64 bf16 = 1024 uint4
            int f = t + 256 * i;
            int r = f >> 3, c = (f & 7) * 8;
            *(uint4*)(As + r * AST + c) =
                *(const uint4*)(A + (size_t)(m0 + r) * Ddim + k0 + c);
        }
        #pragma unroll
        for (int i = 0; i < 8; i++) {       // W: 64x128 f32 -> bf16
            int f = t + 256 * i;
            int r = f >> 5, c = (f & 31) * 4;
            float4 v = *(const float4*)(W + (size_t)(k0 + r) * Ddim + n0 + c);
            bf162 lo = __floats2bfloat162_rn(v.x, v.y);
            bf162 hi = __floats2bfloat162_rn(v.z, v.w);
            uint2 pk = { *(u32*)&lo, *(u32*)&hi };
            *(uint2*)(Ws + r * WST + c) = pk;
        }
        __syncthreads();
        #pragma unroll
        for (int ks = 0; ks < 4; ks++) {
            int kk = ks * 16;
            u32 a[4][4], b[4][2];
            #pragma unroll
            for (int mt = 0; mt < 4; mt++)
                ldsm4(a[mt], aaddr(As, AST, wm + mt * 16, kk, lane));
            #pragma unroll
            for (int p = 0; p < 2; p++) {
                u32 bb[4];
                ldsm4t(bb, baddr_t(Ws, WST, kk, wn + 16 * p, lane));
                b[2*p][0] = bb[0]; b[2*p][1] = bb[1];
                b[2*p+1][0] = bb[2]; b[2*p+1][1] = bb[3];
            }
            #pragma unroll
            for (int mt = 0; mt < 4; mt++)
                #pragma unroll
                for (int nt = 0; nt < 4; nt++) mma16(acc[mt][nt], a[mt], b[nt]);
        }
        __syncthreads();
    }
}

// QKV: z picks {q,k,v}; bf16 output in [BH, N, DH] layout, bias fused.
__global__ void __launch_bounds__(256) qkv_mma_kernel(
    const float* __restrict__ Wq, const float* __restrict__ Wk,
    const float* __restrict__ Wv, const float* __restrict__ bq,
    const float* __restrict__ bk, const float* __restrict__ bv)
{
    __shared__ bf16 As[128 * AST];
    __shared__ bf16 Ws[64 * WST];
    __shared__ float bs[128];
    const float* W; const float* bias; bf16* O;
    if (blockIdx.z == 0)      { W = Wq; bias = bq; O = g_q; }
    else if (blockIdx.z == 1) { W = Wk; bias = bk; O = g_k; }
    else                      { W = Wv; bias = bv; O = g_v; }

    const int t = threadIdx.x, lane = t & 31, wid = t >> 5;
    const int gid = lane >> 2, tig = lane & 3;
    const int wm = (wid >> 2) * 64, wn = (wid & 3) * 32;
    const int m0 = blockIdx.y * 128, n0 = blockIdx.x * 128;
    if (t < 128) bs[t] = bias[n0 + t];

    float acc[4][4][4];
    gemm_bf16_body(g_h, W, acc, As, Ws);

    #pragma unroll
    for (int mt = 0; mt < 4; mt++)
        #pragma unroll
        for (int nt = 0; nt < 4; nt++) {
            int cl = wn + nt * 8 + 2 * tig;
            int n  = n0 + cl;
            int h  = n >> 6, dh = n & 63;
            int mr = m0 + wm + mt * 16 + gid;
            {
                int b0i = mr >> 10, ns = mr & 1023;
                bf162 v = __floats2bfloat162_rn(acc[mt][nt][0] + bs[cl],
                                                acc[mt][nt][1] + bs[cl + 1]);
                *(u32*)(O + (((size_t)(b0i * Hn + h) * Nseq + ns) * DH + dh)) = *(u32*)&v;
            }
            {
                int mr2 = mr + 8;
                int b0i = mr2 >> 10, ns = mr2 & 1023;
                bf162 v = __floats2bfloat162_rn(acc[mt][nt][2] + bs[cl],
                                                acc[mt][nt][3] + bs[cl + 1]);
                *(u32*)(O + (((size_t)(b0i * Hn + h) * Nseq + ns) * DH + dh)) = *(u32*)&v;
            }
        }
}

// Output projection: g_y = attnout @ Wo + bo + x   (bf16 A, f32 out)
__global__ void __launch_bounds__(256) proj_mma_kernel(
    const float* __restrict__ Wo, const float* __restrict__ bo,
    const float* __restrict__ xres)
{
    __shared__ bf16 As[128 * AST];
    __shared__ bf16 Ws[64 * WST];
    __shared__ float bs[128];
    const int t = threadIdx.x, lane = t & 31, wid = t >> 5;
    const int gid = lane >> 2, tig = lane & 3;
    const int wm = (wid >> 2) * 64, wn = (wid & 3) * 32;
    const int m0 = blockIdx.y * 128, n0 = blockIdx.x * 128;
    if (t < 128) bs[t] = bo[n0 + t];

    float acc[4][4][4];
    gemm_bf16_body(g_attnout, Wo, acc, As, Ws);

    #pragma unroll
    for (int mt = 0; mt < 4; mt++)
        #pragma unroll
        for (int nt = 0; nt < 4; nt++) {
            int cl = wn + nt * 8 + 2 * tig;
            int n  = n0 + cl;
            int mr = m0 + wm + mt * 16 + gid;
            {
                size_t idx = (size_t)mr * Ddim + n;
                float2 xr = *(const float2*)(xres + idx);
                float2 p = { acc[mt][nt][0] + bs[cl] + xr.x,
                             acc[mt][nt][1] + bs[cl + 1] + xr.y };
                *(float2*)(g_y + idx) = p;
            }
            {
                size_t idx = (size_t)(mr + 8) * Ddim + n;
                float2 xr = *(const float2*)(xres + idx);
                float2 p = { acc[mt][nt][2] + bs[cl] + xr.x,
                             acc[mt][nt][3] + bs[cl + 1] + xr.y };
                *(float2*)(g_y + idx) = p;
            }
        }
}

// ---------------- Fused attention (bf16 mma + ldmatrix, q2/k2 FIXED) ----------
#define FAST 72
#define QS_B 0
#define KS_B 18432
#define VS_B 27648
#define PS_B 36864
#define Q2_B 55296
#define K2_B 55808
#define LS_B 56064
#define FA_SMEM 56576

__global__ void __launch_bounds__(256, 2) fused_attn_kernel()
{
    extern __shared__ char smraw[];
    bf16*  Qs  = (bf16*)(smraw + QS_B);
    bf16*  Ks  = (bf16*)(smraw + KS_B);
    bf16*  Vs  = (bf16*)(smraw + VS_B);
    bf16*  Ps  = (bf16*)(smraw + PS_B);
    float* q2s = (float*)(smraw + Q2_B);
    float* k2s = (float*)(smraw + K2_B);
    float* ls  = (float*)(smraw + LS_B);

    const int t = threadIdx.x, lane = t & 31, wid = t >> 5;
    const int gid = lane >> 2, tig = lane & 3;
    const int wm = (wid >> 1) * 32, wn = (wid & 1) * 32;
    const int i0 = blockIdx.x * 128;
    const int bh = blockIdx.y;
    const bf16* Qg = g_q + (size_t)bh * Nseq * DH;
    const bf16* Kg = g_k + (size_t)bh * Nseq * DH;
    const bf16* Vg = g_v + (size_t)bh * Nseq * DH;

    // load Q tile: 128x64 bf16 = 1024 uint4
    #pragma unroll
    for (int i = 0; i < 4; i++) {
        int f = t + 256 * i;
        int r = f >> 3, c = (f & 7) * 8;
        *(uint4*)(Qs + r * FAST + c) = *(const uint4*)(Qg + (size_t)(i0 + r) * DH + c);
    }
    if (t < 128) ls[t] = 0.f;
    __syncthreads();
    if (t < 128) {
        float s = 0.f;
        #pragma unroll
        for (int i = 0; i < 8; i++) {               // FIXED: uint4 = 8 bf16, covers all 64
            uint4 u = *(uint4*)(Qs + t * FAST + i * 8);
            float2 f0 = b2f(u.x), f1 = b2f(u.y), f2 = b2f(u.z), f3 = b2f(u.w);
            s += f0.x*f0.x + f0.y*f0.y + f1.x*f1.x + f1.y*f1.y
               + f2.x*f2.x + f2.y*f2.y + f3.x*f3.x + f3.y*f3.y;
        }
        q2s[t] = s;
    }

    float oacc[2][4][4];
    #pragma unroll
    for (int mt = 0; mt < 2; mt++)
        #pragma unroll
        for (int nt = 0; nt < 4; nt++)
            #pragma unroll
            for (int c = 0; c < 4; c++) oacc[mt][nt][c] = 0.f;
    float rs[2][2];
    rs[0][0] = rs[0][1] = rs[1][0] = rs[1][1] = 0.f;

    for (int jc = 0; jc < 16; jc++) {
        int j0 = jc * 64;
        __syncthreads();   // prev iter done reading Ks/Vs/Ps
        #pragma unroll
        for (int i = 0; i < 2; i++) {               // K,V: 64x64 bf16 = 512 uint4 each
            int f = t + 256 * i;
            int r = f >> 3, c = (f & 7) * 8;
            *(uint4*)(Ks + r * FAST + c) = *(const uint4*)(Kg + (size_t)(j0 + r) * DH + c);
            *(uint4*)(Vs + r * FAST + c) = *(const uint4*)(Vg + (size_t)(j0 + r) * DH + c);
        }
        __syncthreads();
        if (t < 64) {
            float s = 0.f;
            #pragma unroll
            for (int i = 0; i < 8; i++) {           // FIXED: uint4, all 64 elements
                uint4 u = *(uint4*)(Ks + t * FAST + i * 8);
                float2 f0 = b2f(u.x), f1 = b2f(u.y), f2 = b2f(u.z), f3 = b2f(u.w);
                s += f0.x*f0.x + f0.y*f0.y + f1.x*f1.x + f1.y*f1.y
                   + f2.x*f2.x + f2.y*f2.y + f3.x*f3.x + f3.y*f3.y;
            }
            k2s[t] = s;
        }

        // S = Q @ K^T : M=128, N=64(keys), K=64(dh)
        float sacc[2][4][4];
        #pragma unroll
        for (int mt = 0; mt < 2; mt++)
            #pragma unroll
            for (int nt = 0; nt < 4; nt++)
                #pragma unroll
                for (int c = 0; c < 4; c++) sacc[mt][nt][c] = 0.f;
        #pragma unroll
        for (int ks = 0; ks < 4; ks++) {
            int kk = ks * 16;
            u32 a[2][4], b[4][2];
            #pragma unroll
            for (int mt = 0; mt < 2; mt++)
                ldsm4(a[mt], aaddr(Qs, FAST, wm + mt * 16, kk, lane));
            #pragma unroll
            for (int p = 0; p < 2; p++) {
                u32 bb[4];
                ldsm4(bb, baddr_k(Ks, FAST, wn + 16 * p, kk, lane));
                b[2*p][0] = bb[0]; b[2*p][1] = bb[1];
                b[2*p+1][0] = bb[2]; b[2*p+1][1] = bb[3];
            }
            #pragma unroll
            for (int mt = 0; mt < 2; mt++)
                #pragma unroll
                for (int nt = 0; nt < 4; nt++) mma16(sacc[mt][nt], a[mt], b[nt]);
        }
        __syncthreads();   // k2s visible; S reads of Ks done

        // epilogue: P = exp(-dist); row sums; stash bf16 P in smem
        #pragma unroll
        for (int mt = 0; mt < 2; mt++) {
            int rl = wm + mt * 16 + gid;
            float q2a = q2s[rl], q2b = q2s[rl + 8];
            #pragma unroll
            for (int nt = 0; nt < 4; nt++) {
                int cl = wn + nt * 8 + 2 * tig;
                float k2a = k2s[cl], k2b = k2s[cl + 1];
                float d0 = fmaxf(fmaf(-2.f, sacc[mt][nt][0], q2a + k2a), 0.f) + 1e-8f;
                float d1 = fmaxf(fmaf(-2.f, sacc[mt][nt][1], q2a + k2b), 0.f) + 1e-8f;
                float d2 = fmaxf(fmaf(-2.f, sacc[mt][nt][2], q2b + k2a), 0.f) + 1e-8f;
                float d3 = fmaxf(fmaf(-2.f, sacc[mt][nt][3], q2b + k2b), 0.f) + 1e-8f;
                float p0 = __expf(-sqrtf(d0));
                float p1 = __expf(-sqrtf(d1));
                float p2 = __expf(-sqrtf(d2));
                float p3 = __expf(-sqrtf(d3));
                rs[mt][0] += p0 + p1;
                rs[mt][1] += p2 + p3;
                bf162 w0 = __floats2bfloat162_rn(p0, p1);
                bf162 w1 = __floats2bfloat162_rn(p2, p3);
                *(u32*)(Ps + rl * FAST + cl) = *(u32*)&w0;
                *(u32*)(Ps + (rl + 8) * FAST + cl) = *(u32*)&w1;
            }
        }
        __syncthreads();   // Ps visible

        // O += P @ V : M=128, N=64(dh), K=64(keys)
        #pragma unroll
        for (int ks = 0; ks < 4; ks++) {
            int kk = ks * 16;
            u32 a[2][4], b[4][2];
            #pragma unroll
            for (int mt = 0; mt < 2; mt++)
                ldsm4(a[mt], aaddr(Ps, FAST, wm + mt * 16, kk, lane));
            #pragma unroll
            for (int p = 0; p < 2; p++) {
                u32 bb[4];
                ldsm4t(bb, baddr_t(Vs, FAST, kk, wn + 16 * p, lane));
                b[2*p][0] = bb[0]; b[2*p][1] = bb[1];
                b[2*p+1][0] = bb[2]; b[2*p+1][1] = bb[3];
            }
            #pragma unroll
            for (int mt = 0; mt < 2; mt++)
                #pragma unroll
                for (int nt = 0; nt < 4; nt++) mma16(oacc[mt][nt], a[mt], b[nt]);
        }
    }

    // reduce row sums: quad shuffle, then across the 2 n-warps via shared atomics
    #pragma unroll
    for (int mt = 0; mt < 2; mt++) {
        float v0 = rs[mt][0], v1 = rs[mt][1];
        v0 += __shfl_xor_sync(0xffffffffu, v0, 1);
        v0 += __shfl_xor_sync(0xffffffffu, v0, 2);
        v1 += __shfl_xor_sync(0xffffffffu, v1, 1);
        v1 += __shfl_xor_sync(0xffffffffu, v1, 2);
        if (tig == 0) {
            atomicAdd(&ls[wm + mt * 16 + gid], v0);
            atomicAdd(&ls[wm + mt * 16 + gid + 8], v1);
        }
    }
    __syncthreads();

    const int b = bh >> 3, h = bh & 7;
    #pragma unroll
    for (int mt = 0; mt < 2; mt++) {
        int rl = wm + mt * 16 + gid;
        int i  = i0 + rl;
        float li0 = 1.0f / ls[rl];
        float li1 = 1.0f / ls[rl + 8];
        #pragma unroll
        for (int nt = 0; nt < 4; nt++) {
            int dh = wn + nt * 8 + 2 * tig;
            bf162 w0 = __floats2bfloat162_rn(oacc[mt][nt][0] * li0, oacc[mt][nt][1] * li0);
            bf162 w1 = __floats2bfloat162_rn(oacc[mt][nt][2] * li1, oacc[mt][nt][3] * li1);
            *(u32*)(g_attnout + ((size_t)(b * Nseq + i) * Ddim + h * DH + dh)) = *(u32*)&w0;
            *(u32*)(g_attnout + ((size_t)(b * Nseq + i + 8) * Ddim + h * DH + dh)) = *(u32*)&w1;
        }
    }
}

// ---------------- launch ------------------------------------------------------
extern "C" void kernel_launch(void* const* d_in, const int* in_sizes, int n_in,
                              void* d_out, int out_size)
{
    const float* x = nullptr;
    const float* Wm[4] = {nullptr, nullptr, nullptr, nullptr};
    const float* vec[8] = {nullptr};
    int nm = 0, nv = 0;
    for (int i = 0; i < n_in; i++) {
        if (in_sizes[i] == BN_ROWS * Ddim)      x = (const float*)d_in[i];
        else if (in_sizes[i] == Ddim * Ddim)    { if (nm < 4) Wm[nm++] = (const float*)d_in[i]; }
        else if (in_sizes[i] == Ddim)           { if (nv < 8) vec[nv++] = (const float*)d_in[i]; }
    }
    const float *Wq = Wm[0], *Wk = Wm[1], *Wv = Wm[2], *Wo = Wm[3];
    const float *bq = vec[0], *bk = vec[1], *bv = vec[2], *bo = vec[3];
    const float *ln1g = vec[4], *ln1b = vec[5], *ln2g = vec[6], *ln2b = vec[7];

    void *p_h = nullptr, *p_y = nullptr;
    cudaGetSymbolAddress(&p_h, g_h);
    cudaGetSymbolAddress(&p_y, g_y);

    cudaFuncSetAttribute(fused_attn_kernel,
                         cudaFuncAttributeMaxDynamicSharedMemorySize, FA_SMEM);

    ln_bf16_kernel<<<BN_ROWS, 128>>>(x, ln1g, ln1b, (bf16*)p_h);
    qkv_mma_kernel<<<dim3(Ddim / 128, BN_ROWS / 128, 3), 256>>>(Wq, Wk, Wv, bq, bk, bv);
    fused_attn_kernel<<<dim3(Nseq / 128, NBH), 256, FA_SMEM>>>();
    proj_mma_kernel<<<dim3(Ddim / 128, BN_ROWS / 128), 256>>>(Wo, bo, x);
    ln_f32_kernel<<<BN_ROWS, 128>>>((const float*)p_y, ln2g, ln2b, (float*)d_out);
}

// round 8
// speedup vs baseline: 6.8057x; 1.1732x over previous
#include <cuda_runtime.h>
#include <cuda_bf16.h>
#include <stdint.h>
#include <cstdint>
#include <math.h>

#define Bdim 8
#define Nseq 1024
#define Ddim 512
#define Hn 8
#define DH 64
#define BN_ROWS (Bdim * Nseq)   // 8192
#define NBH (Bdim * Hn)         // 64

typedef unsigned int u32;
typedef __nv_bfloat16 bf16;
typedef __nv_bfloat162 bf162;

// ---------------- scratch (device globals; no allocation allowed) ------------
__device__ bf16  g_h[BN_ROWS * Ddim];        // LN1 output (bf16)
__device__ bf16  g_q[BN_ROWS * Ddim];        // [BH, N, DH] bf16
__device__ bf16  g_k[BN_ROWS * Ddim];
__device__ bf16  g_v[BN_ROWS * Ddim];
__device__ bf16  g_attnout[BN_ROWS * Ddim];  // [B, N, D] bf16
__device__ float g_y[BN_ROWS * Ddim];        // proj + residual, pre-LN2 (f32)
__device__ bf16  g_wb[4][Ddim * Ddim];       // bf16 copies of Wq,Wk,Wv,Wo

// ---------------- helpers -----------------------------------------------------
__device__ __forceinline__ u32 s2u(const void* p) {
    u32 a;
    asm("{ .reg .u64 t; cvta.to.shared.u64 t, %1; cvt.u32.u64 %0, t; }" : "=r"(a) : "l"(p));
    return a;
}
__device__ __forceinline__ void cpa16(u32 smem, const void* g) {
    asm volatile("cp.async.cg.shared.global [%0],[%1],16;" :: "r"(smem), "l"(g));
}
#define CP_COMMIT() asm volatile("cp.async.commit_group;")
#define CP_WAIT0()  asm volatile("cp.async.wait_group 0;")

__device__ __forceinline__ void ldsm4(u32* r, u32 addr) {
    asm volatile("ldmatrix.sync.aligned.m8n8.x4.shared.b16 {%0,%1,%2,%3},[%4];"
                 : "=r"(r[0]), "=r"(r[1]), "=r"(r[2]), "=r"(r[3]) : "r"(addr));
}
__device__ __forceinline__ void ldsm4t(u32* r, u32 addr) {
    asm volatile("ldmatrix.sync.aligned.m8n8.x4.trans.shared.b16 {%0,%1,%2,%3},[%4];"
                 : "=r"(r[0]), "=r"(r[1]), "=r"(r[2]), "=r"(r[3]) : "r"(addr));
}
__device__ __forceinline__ void mma16(float* c, const u32* a, const u32* b) {
    asm volatile(
        "mma.sync.aligned.m16n8k16.row.col.f32.bf16.bf16.f32 "
        "{%0,%1,%2,%3},{%4,%5,%6,%7},{%8,%9},{%0,%1,%2,%3};\n"
        : "+f"(c[0]), "+f"(c[1]), "+f"(c[2]), "+f"(c[3])
        : "r"(a[0]), "r"(a[1]), "r"(a[2]), "r"(a[3]), "r"(b[0]), "r"(b[1]));
}
__device__ __forceinline__ u32 aaddr(const bf16* base, int stride, int mm, int k, int lane) {
    int row = mm + (lane & 7) + (((lane >> 3) & 1) << 3);
    int col = k + ((lane >> 4) << 3);
    return s2u(base + row * stride + col);
}
__device__ __forceinline__ u32 baddr_k(const bf16* base, int stride, int n, int k, int lane) {
    int m = lane >> 3;
    int row = n + ((m >> 1) << 3) + (lane & 7);
    int col = k + ((m & 1) << 3);
    return s2u(base + row * stride + col);
}
__device__ __forceinline__ u32 baddr_t(const bf16* base, int stride, int k, int n, int lane) {
    int m = lane >> 3;
    int row = k + ((m & 1) << 3) + (lane & 7);
    int col = n + ((m >> 1) << 3);
    return s2u(base + row * stride + col);
}
__device__ __forceinline__ float2 b2f(u32 u) {
    bf162 h = *(bf162*)&u;
    return __bfloat1622float2(h);
}

// ---------------- weight f32->bf16 conversion ---------------------------------
__global__ void wconv_kernel(const float* __restrict__ w0, const float* __restrict__ w1,
                             const float* __restrict__ w2, const float* __restrict__ w3)
{
    const float* src = (blockIdx.y == 0) ? w0 : (blockIdx.y == 1) ? w1
                      : (blockIdx.y == 2) ? w2 : w3;
    bf16* dst = g_wb[blockIdx.y];
    int i = blockIdx.x * 256 + threadIdx.x;          // 256 blocks x 256 thr x 4 elems
    float4 v = ((const float4*)src)[i];
    bf162 lo = __floats2bfloat162_rn(v.x, v.y);
    bf162 hi = __floats2bfloat162_rn(v.z, v.w);
    uint2 pk = { *(u32*)&lo, *(u32*)&hi };
    ((uint2*)dst)[i] = pk;
}

// ---------------- LayerNorm ---------------------------------------------------
__device__ __forceinline__ float4 ln_row_body(const float* __restrict__ in,
                                              const float* __restrict__ gamma,
                                              const float* __restrict__ beta,
                                              int row)
{
    const float4* r = (const float4*)(in + (size_t)row * Ddim);
    float4 a = r[threadIdx.x];
    float s  = a.x + a.y + a.z + a.w;
    float s2 = a.x*a.x + a.y*a.y + a.z*a.z + a.w*a.w;
    #pragma unroll
    for (int off = 16; off; off >>= 1) {
        s  += __shfl_xor_sync(0xffffffffu, s,  off);
        s2 += __shfl_xor_sync(0xffffffffu, s2, off);
    }
    __shared__ float sbA[4], sbB[4];
    int wid = threadIdx.x >> 5, lane = threadIdx.x & 31;
    if (lane == 0) { sbA[wid] = s; sbB[wid] = s2; }
    __syncthreads();
    s  = sbA[0] + sbA[1] + sbA[2] + sbA[3];
    s2 = sbB[0] + sbB[1] + sbB[2] + sbB[3];
    float mean = s * (1.0f / Ddim);
    float var  = s2 * (1.0f / Ddim) - mean * mean;
    float rstd = rsqrtf(var + 1e-5f);
    float4 g = ((const float4*)gamma)[threadIdx.x];
    float4 b = ((const float4*)beta)[threadIdx.x];
    float4 o;
    o.x = (a.x - mean) * rstd * g.x + b.x;
    o.y = (a.y - mean) * rstd * g.y + b.y;
    o.z = (a.z - mean) * rstd * g.z + b.z;
    o.w = (a.w - mean) * rstd * g.w + b.w;
    return o;
}

__global__ void ln_bf16_kernel(const float* __restrict__ in,
                               const float* __restrict__ gamma,
                               const float* __restrict__ beta,
                               bf16* __restrict__ out)
{
    int row = blockIdx.x;
    float4 o = ln_row_body(in, gamma, beta, row);
    bf162 lo = __floats2bfloat162_rn(o.x, o.y);
    bf162 hi = __floats2bfloat162_rn(o.z, o.w);
    uint2 pk = { *(u32*)&lo, *(u32*)&hi };
    *(uint2*)(out + (size_t)row * Ddim + 4 * threadIdx.x) = pk;
}

__global__ void ln_f32_kernel(const float* __restrict__ in,
                              const float* __restrict__ gamma,
                              const float* __restrict__ beta,
                              float* __restrict__ out)
{
    int row = blockIdx.x;
    float4 o = ln_row_body(in, gamma, beta, row);
    ((float4*)(out + (size_t)row * Ddim))[threadIdx.x] = o;
}

// ---------------- bf16 MMA GEMM core, cp.async double-buffered ----------------
// Block 128x128, K-chunk 64, 256 thr, warp grid 2x4, warp tile 64x32.
#define AST 72
#define WST 136
// dynamic smem layout (bytes)
#define GAS0 0
#define GAS1 18432
#define GWS0 36864
#define GWS1 54272
#define GBS  71680
#define GEMM_SMEM 72192

__device__ __forceinline__ void gemm_load_stage(const bf16* __restrict__ A,
                                                const bf16* __restrict__ W,
                                                bf16* As, bf16* Ws,
                                                int m0, int n0, int k0, int t)
{
    #pragma unroll
    for (int i = 0; i < 4; i++) {           // A tile 128x64: 1024 x 16B
        int f = t + 256 * i;
        int r = f >> 3, c = (f & 7) * 8;
        cpa16(s2u(As + r * AST + c), A + (size_t)(m0 + r) * Ddim + k0 + c);
    }
    #pragma unroll
    for (int i = 0; i < 4; i++) {           // W tile 64x128: 1024 x 16B
        int f = t + 256 * i;
        int r = f >> 4, c = (f & 15) * 8;
        cpa16(s2u(Ws + r * WST + c), W + (size_t)(k0 + r) * Ddim + n0 + c);
    }
    CP_COMMIT();
}

__device__ __forceinline__ void gemm_pipe_body(const bf16* __restrict__ A,
                                               const bf16* __restrict__ W,
                                               float acc[4][4][4],
                                               char* smraw)
{
    bf16* Asb[2] = { (bf16*)(smraw + GAS0), (bf16*)(smraw + GAS1) };
    bf16* Wsb[2] = { (bf16*)(smraw + GWS0), (bf16*)(smraw + GWS1) };
    const int t = threadIdx.x, lane = t & 31, wid = t >> 5;
    const int wm = (wid >> 2) * 64, wn = (wid & 3) * 32;
    const int m0 = blockIdx.y * 128, n0 = blockIdx.x * 128;

    #pragma unroll
    for (int i = 0; i < 4; i++)
        #pragma unroll
        for (int j = 0; j < 4; j++)
            #pragma unroll
            for (int c = 0; c < 4; c++) acc[i][j][c] = 0.f;

    gemm_load_stage(A, W, Asb[0], Wsb[0], m0, n0, 0, t);

    for (int kc = 0; kc < 8; kc++) {
        bf16* As = Asb[kc & 1];
        bf16* Ws = Wsb[kc & 1];
        CP_WAIT0();
        __syncthreads();   // stage data visible; all reads of other buffer done
        if (kc < 7)
            gemm_load_stage(A, W, Asb[(kc + 1) & 1], Wsb[(kc + 1) & 1],
                            m0, n0, (kc + 1) * 64, t);
        #pragma unroll
        for (int ks = 0; ks < 4; ks++) {
            int kk = ks * 16;
            u32 a[4][4], b[4][2];
            #pragma unroll
            for (int mt = 0; mt < 4; mt++)
                ldsm4(a[mt], aaddr(As, AST, wm + mt * 16, kk, lane));
            #pragma unroll
            for (int p = 0; p < 2; p++) {
                u32 bb[4];
                ldsm4t(bb, baddr_t(Ws, WST, kk, wn + 16 * p, lane));
                b[2*p][0] = bb[0]; b[2*p][1] = bb[1];
                b[2*p+1][0] = bb[2]; b[2*p+1][1] = bb[3];
            }
            #pragma unroll
            for (int mt = 0; mt < 4; mt++)
                #pragma unroll
                for (int nt = 0; nt < 4; nt++) mma16(acc[mt][nt], a[mt], b[nt]);
        }
    }
}

// QKV: z picks {q,k,v}; bf16 output in [BH, N, DH] layout, bias fused.
__global__ void __launch_bounds__(256) qkv_mma_kernel(
    const float* __restrict__ bq, const float* __restrict__ bk,
    const float* __restrict__ bv)
{
    extern __shared__ char smraw[];
    float* bs = (float*)(smraw + GBS);
    const bf16* W = g_wb[blockIdx.z];
    const float* bias = (blockIdx.z == 0) ? bq : (blockIdx.z == 1) ? bk : bv;
    bf16* O = (blockIdx.z == 0) ? g_q : (blockIdx.z == 1) ? g_k : g_v;

    const int t = threadIdx.x, lane = t & 31, wid = t >> 5;
    const int gid = lane >> 2, tig = lane & 3;
    const int wm = (wid >> 2) * 64, wn = (wid & 3) * 32;
    const int m0 = blockIdx.y * 128, n0 = blockIdx.x * 128;
    if (t < 128) bs[t] = bias[n0 + t];

    float acc[4][4][4];
    gemm_pipe_body(g_h, W, acc, smraw);

    #pragma unroll
    for (int mt = 0; mt < 4; mt++)
        #pragma unroll
        for (int nt = 0; nt < 4; nt++) {
            int cl = wn + nt * 8 + 2 * tig;
            int n  = n0 + cl;
            int h  = n >> 6, dh = n & 63;
            int mr = m0 + wm + mt * 16 + gid;
            {
                int b0i = mr >> 10, ns = mr & 1023;
                bf162 v = __floats2bfloat162_rn(acc[mt][nt][0] + bs[cl],
                                                acc[mt][nt][1] + bs[cl + 1]);
                *(u32*)(O + (((size_t)(b0i * Hn + h) * Nseq + ns) * DH + dh)) = *(u32*)&v;
            }
            {
                int mr2 = mr + 8;
                int b0i = mr2 >> 10, ns = mr2 & 1023;
                bf162 v = __floats2bfloat162_rn(acc[mt][nt][2] + bs[cl],
                                                acc[mt][nt][3] + bs[cl + 1]);
                *(u32*)(O + (((size_t)(b0i * Hn + h) * Nseq + ns) * DH + dh)) = *(u32*)&v;
            }
        }
}

// Output projection: g_y = attnout @ Wo + bo + x   (bf16 A, f32 out)
__global__ void __launch_bounds__(256) proj_mma_kernel(
    const float* __restrict__ bo, const float* __restrict__ xres)
{
    extern __shared__ char smraw[];
    float* bs = (float*)(smraw + GBS);
    const int t = threadIdx.x, lane = t & 31, wid = t >> 5;
    const int gid = lane >> 2, tig = lane & 3;
    const int wm = (wid >> 2) * 64, wn = (wid & 3) * 32;
    const int m0 = blockIdx.y * 128, n0 = blockIdx.x * 128;
    if (t < 128) bs[t] = bo[n0 + t];

    float acc[4][4][4];
    gemm_pipe_body(g_attnout, g_wb[3], acc, smraw);

    #pragma unroll
    for (int mt = 0; mt < 4; mt++)
        #pragma unroll
        for (int nt = 0; nt < 4; nt++) {
            int cl = wn + nt * 8 + 2 * tig;
            int n  = n0 + cl;
            int mr = m0 + wm + mt * 16 + gid;
            {
                size_t idx = (size_t)mr * Ddim + n;
                float2 xr = *(const float2*)(xres + idx);
                float2 p = { acc[mt][nt][0] + bs[cl] + xr.x,
                             acc[mt][nt][1] + bs[cl + 1] + xr.y };
                *(float2*)(g_y + idx) = p;
            }
            {
                size_t idx = (size_t)(mr + 8) * Ddim + n;
                float2 xr = *(const float2*)(xres + idx);
                float2 p = { acc[mt][nt][2] + bs[cl] + xr.x,
                             acc[mt][nt][3] + bs[cl + 1] + xr.y };
                *(float2*)(g_y + idx) = p;
            }
        }
}

// ---------------- Fused attention (bf16 mma, cp.async K/V double-buffer) ------
#define FAST 72
#define QS_B  0
#define KS0_B 18432
#define KS1_B 27648
#define VS0_B 36864
#define VS1_B 46080
#define PS_B  55296
#define Q2_B  73728
#define K2_B  74240
#define LS_B  74496
#define FA_SMEM 75008

__global__ void __launch_bounds__(256, 2) fused_attn_kernel()
{
    extern __shared__ char smraw[];
    bf16*  Qs  = (bf16*)(smraw + QS_B);
    bf16*  Ksb[2] = { (bf16*)(smraw + KS0_B), (bf16*)(smraw + KS1_B) };
    bf16*  Vsb[2] = { (bf16*)(smraw + VS0_B), (bf16*)(smraw + VS1_B) };
    bf16*  Ps  = (bf16*)(smraw + PS_B);
    float* q2s = (float*)(smraw + Q2_B);
    float* k2s = (float*)(smraw + K2_B);
    float* ls  = (float*)(smraw + LS_B);

    const int t = threadIdx.x, lane = t & 31, wid = t >> 5;
    const int gid = lane >> 2, tig = lane & 3;
    const int wm = (wid >> 1) * 32, wn = (wid & 1) * 32;
    const int i0 = blockIdx.x * 128;
    const int bh = blockIdx.y;
    const bf16* Qg = g_q + (size_t)bh * Nseq * DH;
    const bf16* Kg = g_k + (size_t)bh * Nseq * DH;
    const bf16* Vg = g_v + (size_t)bh * Nseq * DH;

    // prefetch K/V chunk 0
    #pragma unroll
    for (int i = 0; i < 2; i++) {
        int f = t + 256 * i;
        int r = f >> 3, c = (f & 7) * 8;
        cpa16(s2u(Ksb[0] + r * FAST + c), Kg + (size_t)r * DH + c);
        cpa16(s2u(Vsb[0] + r * FAST + c), Vg + (size_t)r * DH + c);
    }
    CP_COMMIT();

    // load Q tile: 128x64 bf16 = 1024 uint4
    #pragma unroll
    for (int i = 0; i < 4; i++) {
        int f = t + 256 * i;
        int r = f >> 3, c = (f & 7) * 8;
        *(uint4*)(Qs + r * FAST + c) = *(const uint4*)(Qg + (size_t)(i0 + r) * DH + c);
    }
    if (t < 128) ls[t] = 0.f;
    __syncthreads();
    if (t < 128) {
        float s = 0.f;
        #pragma unroll
        for (int i = 0; i < 8; i++) {
            uint4 u = *(uint4*)(Qs + t * FAST + i * 8);
            float2 f0 = b2f(u.x), f1 = b2f(u.y), f2 = b2f(u.z), f3 = b2f(u.w);
            s += f0.x*f0.x + f0.y*f0.y + f1.x*f1.x + f1.y*f1.y
               + f2.x*f2.x + f2.y*f2.y + f3.x*f3.x + f3.y*f3.y;
        }
        q2s[t] = s;
    }

    float oacc[2][4][4];
    #pragma unroll
    for (int mt = 0; mt < 2; mt++)
        #pragma unroll
        for (int nt = 0; nt < 4; nt++)
            #pragma unroll
            for (int c = 0; c < 4; c++) oacc[mt][nt][c] = 0.f;
    float rs[2][2];
    rs[0][0] = rs[0][1] = rs[1][0] = rs[1][1] = 0.f;

    for (int jc = 0; jc < 16; jc++) {
        bf16* Ks = Ksb[jc & 1];
        bf16* Vs = Vsb[jc & 1];
        CP_WAIT0();
        __syncthreads();   // chunk data visible; all reads of other buffer done
        if (jc < 15) {
            int j1 = (jc + 1) * 64;
            bf16* Kn = Ksb[(jc + 1) & 1];
            bf16* Vn = Vsb[(jc + 1) & 1];
            #pragma unroll
            for (int i = 0; i < 2; i++) {
                int f = t + 256 * i;
                int r = f >> 3, c = (f & 7) * 8;
                cpa16(s2u(Kn + r * FAST + c), Kg + (size_t)(j1 + r) * DH + c);
                cpa16(s2u(Vn + r * FAST + c), Vg + (size_t)(j1 + r) * DH + c);
            }
            CP_COMMIT();
        }
        if (t < 64) {
            float s = 0.f;
            #pragma unroll
            for (int i = 0; i < 8; i++) {
                uint4 u = *(uint4*)(Ks + t * FAST + i * 8);
                float2 f0 = b2f(u.x), f1 = b2f(u.y), f2 = b2f(u.z), f3 = b2f(u.w);
                s += f0.x*f0.x + f0.y*f0.y + f1.x*f1.x + f1.y*f1.y
                   + f2.x*f2.x + f2.y*f2.y + f3.x*f3.x + f3.y*f3.y;
            }
            k2s[t] = s;
        }

        // S = Q @ K^T : M=128, N=64(keys), K=64(dh)
        float sacc[2][4][4];
        #pragma unroll
        for (int mt = 0; mt < 2; mt++)
            #pragma unroll
            for (int nt = 0; nt < 4; nt++)
                #pragma unroll
                for (int c = 0; c < 4; c++) sacc[mt][nt][c] = 0.f;
        #pragma unroll
        for (int ks = 0; ks < 4; ks++) {
            int kk = ks * 16;
            u32 a[2][4], b[4][2];
            #pragma unroll
            for (int mt = 0; mt < 2; mt++)
                ldsm4(a[mt], aaddr(Qs, FAST, wm + mt * 16, kk, lane));
            #pragma unroll
            for (int p = 0; p < 2; p++) {
                u32 bb[4];
                ldsm4(bb, baddr_k(Ks, FAST, wn + 16 * p, kk, lane));
                b[2*p][0] = bb[0]; b[2*p][1] = bb[1];
                b[2*p+1][0] = bb[2]; b[2*p+1][1] = bb[3];
            }
            #pragma unroll
            for (int mt = 0; mt < 2; mt++)
                #pragma unroll
                for (int nt = 0; nt < 4; nt++) mma16(sacc[mt][nt], a[mt], b[nt]);
        }
        __syncthreads();   // k2s visible

        // epilogue: P = exp(-dist); row sums; stash bf16 P in smem
        #pragma unroll
        for (int mt = 0; mt < 2; mt++) {
            int rl = wm + mt * 16 + gid;
            float q2a = q2s[rl], q2b = q2s[rl + 8];
            #pragma unroll
            for (int nt = 0; nt < 4; nt++) {
                int cl = wn + nt * 8 + 2 * tig;
                float k2a = k2s[cl], k2b = k2s[cl + 1];
                float d0 = fmaxf(fmaf(-2.f, sacc[mt][nt][0], q2a + k2a), 0.f) + 1e-8f;
                float d1 = fmaxf(fmaf(-2.f, sacc[mt][nt][1], q2a + k2b), 0.f) + 1e-8f;
                float d2 = fmaxf(fmaf(-2.f, sacc[mt][nt][2], q2b + k2a), 0.f) + 1e-8f;
                float d3 = fmaxf(fmaf(-2.f, sacc[mt][nt][3], q2b + k2b), 0.f) + 1e-8f;
                float p0 = __expf(-sqrtf(d0));
                float p1 = __expf(-sqrtf(d1));
                float p2 = __expf(-sqrtf(d2));
                float p3 = __expf(-sqrtf(d3));
                rs[mt][0] += p0 + p1;
                rs[mt][1] += p2 + p3;
                bf162 w0 = __floats2bfloat162_rn(p0, p1);
                bf162 w1 = __floats2bfloat162_rn(p2, p3);
                *(u32*)(Ps + rl * FAST + cl) = *(u32*)&w0;
                *(u32*)(Ps + (rl + 8) * FAST + cl) = *(u32*)&w1;
            }
        }
        __syncthreads();   // Ps visible

        // O += P @ V : M=128, N=64(dh), K=64(keys)
        #pragma unroll
        for (int ks = 0; ks < 4; ks++) {
            int kk = ks * 16;
            u32 a[2][4], b[4][2];
            #pragma unroll
            for (int mt = 0; mt < 2; mt++)
                ldsm4(a[mt], aaddr(Ps, FAST, wm + mt * 16, kk, lane));
            #pragma unroll
            for (int p = 0; p < 2; p++) {
                u32 bb[4];
                ldsm4t(bb, baddr_t(Vs, FAST, kk, wn + 16 * p, lane));
                b[2*p][0] = bb[0]; b[2*p][1] = bb[1];
                b[2*p+1][0] = bb[2]; b[2*p+1][1] = bb[3];
            }
            #pragma unroll
            for (int mt = 0; mt < 2; mt++)
                #pragma unroll
                for (int nt = 0; nt < 4; nt++) mma16(oacc[mt][nt], a[mt], b[nt]);
        }
    }

    // reduce row sums: quad shuffle, then across the 2 n-warps via shared atomics
    #pragma unroll
    for (int mt = 0; mt < 2; mt++) {
        float v0 = rs[mt][0], v1 = rs[mt][1];
        v0 += __shfl_xor_sync(0xffffffffu, v0, 1);
        v0 += __shfl_xor_sync(0xffffffffu, v0, 2);
        v1 += __shfl_xor_sync(0xffffffffu, v1, 1);
        v1 += __shfl_xor_sync(0xffffffffu, v1, 2);
        if (tig == 0) {
            atomicAdd(&ls[wm + mt * 16 + gid], v0);
            atomicAdd(&ls[wm + mt * 16 + gid + 8], v1);
        }
    }
    __syncthreads();

    const int b = bh >> 3, h = bh & 7;
    #pragma unroll
    for (int mt = 0; mt < 2; mt++) {
        int rl = wm + mt * 16 + gid;
        int i  = i0 + rl;
        float li0 = 1.0f / ls[rl];
        float li1 = 1.0f / ls[rl + 8];
        #pragma unroll
        for (int nt = 0; nt < 4; nt++) {
            int dh = wn + nt * 8 + 2 * tig;
            bf162 w0 = __floats2bfloat162_rn(oacc[mt][nt][0] * li0, oacc[mt][nt][1] * li0);
            bf162 w1 = __floats2bfloat162_rn(oacc[mt][nt][2] * li1, oacc[mt][nt][3] * li1);
            *(u32*)(g_attnout + ((size_t)(b * Nseq + i) * Ddim + h * DH + dh)) = *(u32*)&w0;
            *(u32*)(g_attnout + ((size_t)(b * Nseq + i + 8) * Ddim + h * DH + dh)) = *(u32*)&w1;
        }
    }
}

// ---------------- launch ------------------------------------------------------
extern "C" void kernel_launch(void* const* d_in, const int* in_sizes, int n_in,
                              void* d_out, int out_size)
{
    const float* x = nullptr;
    const float* Wm[4] = {nullptr, nullptr, nullptr, nullptr};
    const float* vec[8] = {nullptr};
    int nm = 0, nv = 0;
    for (int i = 0; i < n_in; i++) {
        if (in_sizes[i] == BN_ROWS * Ddim)      x = (const float*)d_in[i];
        else if (in_sizes[i] == Ddim * Ddim)    { if (nm < 4) Wm[nm++] = (const float*)d_in[i]; }
        else if (in_sizes[i] == Ddim)           { if (nv < 8) vec[nv++] = (const float*)d_in[i]; }
    }
    const float *bq = vec[0], *bk = vec[1], *bv = vec[2], *bo = vec[3];
    const float *ln1g = vec[4], *ln1b = vec[5], *ln2g = vec[6], *ln2b = vec[7];

    void *p_h = nullptr, *p_y = nullptr;
    cudaGetSymbolAddress(&p_h, g_h);
    cudaGetSymbolAddress(&p_y, g_y);

    cudaFuncSetAttribute(fused_attn_kernel,
                         cudaFuncAttributeMaxDynamicSharedMemorySize, FA_SMEM);
    cudaFuncSetAttribute(qkv_mma_kernel,
                         cudaFuncAttributeMaxDynamicSharedMemorySize, GEMM_SMEM);
    cudaFuncSetAttribute(proj_mma_kernel,
                         cudaFuncAttributeMaxDynamicSharedMemorySize, GEMM_SMEM);

    wconv_kernel<<<dim3(256, 4), 256>>>(Wm[0], Wm[1], Wm[2], Wm[3]);
    ln_bf16_kernel<<<BN_ROWS, 128>>>(x, ln1g, ln1b, (bf16*)p_h);
    qkv_mma_kernel<<<dim3(Ddim / 128, BN_ROWS / 128, 3), 256, GEMM_SMEM>>>(bq, bk, bv);
    fused_attn_kernel<<<dim3(Nseq / 128, NBH), 256, FA_SMEM>>>();
    proj_mma_kernel<<<dim3(Ddim / 128, BN_ROWS / 128), 256, GEMM_SMEM>>>(bo, x);
    ln_f32_kernel<<<BN_ROWS, 128>>>((const float*)p_y, ln2g, ln2b, (float*)d_out);
}

// round 11
// speedup vs baseline: 7.0008x; 1.0287x over previous
#include <cuda_runtime.h>
#include <cuda_bf16.h>
#include <stdint.h>
#include <cstdint>
#include <math.h>

#define Bdim 8
#define Nseq 1024
#define Ddim 512
#define Hn 8
#define DH 64
#define BN_ROWS (Bdim * Nseq)   // 8192
#define NBH (Bdim * Hn)         // 64
#define HROWS (NBH * Nseq)      // 65536 head-rows of DH

typedef unsigned int u32;
typedef __nv_bfloat16 bf16;
typedef __nv_bfloat162 bf162;

// ---------------- scratch (device globals; no allocation allowed) ------------
__device__ bf16  g_h[BN_ROWS * Ddim];        // LN1 output (bf16)
__device__ bf16  g_q[BN_ROWS * Ddim];        // [BH, N, DH] bf16
__device__ bf16  g_k[BN_ROWS * Ddim];
__device__ bf16  g_v[BN_ROWS * Ddim];
__device__ bf16  g_attnout[BN_ROWS * Ddim];  // [B, N, D] bf16
__device__ float g_y[BN_ROWS * Ddim];        // proj + residual, pre-LN2 (f32)
__device__ bf16  g_wb[4][Ddim * Ddim];       // bf16 copies of Wq,Wk,Wv,Wo
__device__ float g_q2[HROWS];                // ||q||^2 per head-row (FIXED size)
__device__ float g_k2[HROWS];                // ||k||^2 per head-row (FIXED size)

// ---------------- helpers -----------------------------------------------------
__device__ __forceinline__ u32 s2u(const void* p) {
    u32 a;
    asm("{ .reg .u64 t; cvta.to.shared.u64 t, %1; cvt.u32.u64 %0, t; }" : "=r"(a) : "l"(p));
    return a;
}
__device__ __forceinline__ void cpa16(u32 smem, const void* g) {
    asm volatile("cp.async.cg.shared.global [%0],[%1],16;" :: "r"(smem), "l"(g));
}
#define CP_COMMIT() asm volatile("cp.async.commit_group;")
#define CP_WAIT0()  asm volatile("cp.async.wait_group 0;")

__device__ __forceinline__ void ldsm4(u32* r, u32 addr) {
    asm volatile("ldmatrix.sync.aligned.m8n8.x4.shared.b16 {%0,%1,%2,%3},[%4];"
                 : "=r"(r[0]), "=r"(r[1]), "=r"(r[2]), "=r"(r[3]) : "r"(addr));
}
__device__ __forceinline__ void ldsm4t(u32* r, u32 addr) {
    asm volatile("ldmatrix.sync.aligned.m8n8.x4.trans.shared.b16 {%0,%1,%2,%3},[%4];"
                 : "=r"(r[0]), "=r"(r[1]), "=r"(r[2]), "=r"(r[3]) : "r"(addr));
}
__device__ __forceinline__ void mma16(float* c, const u32* a, const u32* b) {
    asm volatile(
        "mma.sync.aligned.m16n8k16.row.col.f32.bf16.bf16.f32 "
        "{%0,%1,%2,%3},{%4,%5,%6,%7},{%8,%9},{%0,%1,%2,%3};\n"
        : "+f"(c[0]), "+f"(c[1]), "+f"(c[2]), "+f"(c[3])
        : "r"(a[0]), "r"(a[1]), "r"(a[2]), "r"(a[3]), "r"(b[0]), "r"(b[1]));
}
__device__ __forceinline__ u32 aaddr(const bf16* base, int stride, int mm, int k, int lane) {
    int row = mm + (lane & 7) + (((lane >> 3) & 1) << 3);
    int col = k + ((lane >> 4) << 3);
    return s2u(base + row * stride + col);
}
__device__ __forceinline__ u32 baddr_k(const bf16* base, int stride, int n, int k, int lane) {
    int m = lane >> 3;
    int row = n + ((m >> 1) << 3) + (lane & 7);
    int col = k + ((m & 1) << 3);
    return s2u(base + row * stride + col);
}
__device__ __forceinline__ u32 baddr_t(const bf16* base, int stride, int k, int n, int lane) {
    int m = lane >> 3;
    int row = k + ((m & 1) << 3) + (lane & 7);
    int col = n + ((m >> 1) << 3);
    return s2u(base + row * stride + col);
}
__device__ __forceinline__ float2 b2f(u32 u) {
    bf162 h = *(bf162*)&u;
    return __bfloat1622float2(h);
}

// ---------------- weight f32->bf16 conversion ---------------------------------
__global__ void wconv_kernel(const float* __restrict__ w0, const float* __restrict__ w1,
                             const float* __restrict__ w2, const float* __restrict__ w3)
{
    const float* src = (blockIdx.y == 0) ? w0 : (blockIdx.y == 1) ? w1
                      : (blockIdx.y == 2) ? w2 : w3;
    bf16* dst = g_wb[blockIdx.y];
    int i = blockIdx.x * 256 + threadIdx.x;
    float4 v = ((const float4*)src)[i];
    bf162 lo = __floats2bfloat162_rn(v.x, v.y);
    bf162 hi = __floats2bfloat162_rn(v.z, v.w);
    uint2 pk = { *(u32*)&lo, *(u32*)&hi };
    ((uint2*)dst)[i] = pk;
}

// ---------------- q2/k2 precompute (ALL 65536 head-rows) -----------------------
__global__ void sq_kernel()
{
    int row = blockIdx.x * 256 + threadIdx.x;    // 0..HROWS-1
    {
        const uint4* p = (const uint4*)(g_q + (size_t)row * DH);
        float s = 0.f;
        #pragma unroll
        for (int i = 0; i < 8; i++) {
            uint4 u = p[i];
            float2 f0 = b2f(u.x), f1 = b2f(u.y), f2 = b2f(u.z), f3 = b2f(u.w);
            s += f0.x*f0.x + f0.y*f0.y + f1.x*f1.x + f1.y*f1.y
               + f2.x*f2.x + f2.y*f2.y + f3.x*f3.x + f3.y*f3.y;
        }
        g_q2[row] = s;
    }
    {
        const uint4* p = (const uint4*)(g_k + (size_t)row * DH);
        float s = 0.f;
        #pragma unroll
        for (int i = 0; i < 8; i++) {
            uint4 u = p[i];
            float2 f0 = b2f(u.x), f1 = b2f(u.y), f2 = b2f(u.z), f3 = b2f(u.w);
            s += f0.x*f0.x + f0.y*f0.y + f1.x*f1.x + f1.y*f1.y
               + f2.x*f2.x + f2.y*f2.y + f3.x*f3.x + f3.y*f3.y;
        }
        g_k2[row] = s;
    }
}

// ---------------- LayerNorm ---------------------------------------------------
__device__ __forceinline__ float4 ln_row_body(const float* __restrict__ in,
                                              const float* __restrict__ gamma,
                                              const float* __restrict__ beta,
                                              int row)
{
    const float4* r = (const float4*)(in + (size_t)row * Ddim);
    float4 a = r[threadIdx.x];
    float s  = a.x + a.y + a.z + a.w;
    float s2 = a.x*a.x + a.y*a.y + a.z*a.z + a.w*a.w;
    #pragma unroll
    for (int off = 16; off; off >>= 1) {
        s  += __shfl_xor_sync(0xffffffffu, s,  off);
        s2 += __shfl_xor_sync(0xffffffffu, s2, off);
    }
    __shared__ float sbA[4], sbB[4];
    int wid = threadIdx.x >> 5, lane = threadIdx.x & 31;
    if (lane == 0) { sbA[wid] = s; sbB[wid] = s2; }
    __syncthreads();
    s  = sbA[0] + sbA[1] + sbA[2] + sbA[3];
    s2 = sbB[0] + sbB[1] + sbB[2] + sbB[3];
    float mean = s * (1.0f / Ddim);
    float var  = s2 * (1.0f / Ddim) - mean * mean;
    float rstd = rsqrtf(var + 1e-5f);
    float4 g = ((const float4*)gamma)[threadIdx.x];
    float4 b = ((const float4*)beta)[threadIdx.x];
    float4 o;
    o.x = (a.x - mean) * rstd * g.x + b.x;
    o.y = (a.y - mean) * rstd * g.y + b.y;
    o.z = (a.z - mean) * rstd * g.z + b.z;
    o.w = (a.w - mean) * rstd * g.w + b.w;
    return o;
}

__global__ void ln_bf16_kernel(const float* __restrict__ in,
                               const float* __restrict__ gamma,
                               const float* __restrict__ beta,
                               bf16* __restrict__ out)
{
    int row = blockIdx.x;
    float4 o = ln_row_body(in, gamma, beta, row);
    bf162 lo = __floats2bfloat162_rn(o.x, o.y);
    bf162 hi = __floats2bfloat162_rn(o.z, o.w);
    uint2 pk = { *(u32*)&lo, *(u32*)&hi };
    *(uint2*)(out + (size_t)row * Ddim + 4 * threadIdx.x) = pk;
}

__global__ void ln_f32_kernel(const float* __restrict__ in,
                              const float* __restrict__ gamma,
                              const float* __restrict__ beta,
                              float* __restrict__ out)
{
    int row = blockIdx.x;
    float4 o = ln_row_body(in, gamma, beta, row);
    ((float4*)(out + (size_t)row * Ddim))[threadIdx.x] = o;
}

// ---------------- bf16 MMA GEMM core, cp.async double-buffered (R8) -----------
#define AST 72
#define WST 136
#define GAS0 0
#define GAS1 18432
#define GWS0 36864
#define GWS1 54272
#define GBS  71680
#define GEMM_SMEM 72192

__device__ __forceinline__ void gemm_load_stage(const bf16* __restrict__ A,
                                                const bf16* __restrict__ W,
                                                bf16* As, bf16* Ws,
                                                int m0, int n0, int k0, int t)
{
    #pragma unroll
    for (int i = 0; i < 4; i++) {
        int f = t + 256 * i;
        int r = f >> 3, c = (f & 7) * 8;
        cpa16(s2u(As + r * AST + c), A + (size_t)(m0 + r) * Ddim + k0 + c);
    }
    #pragma unroll
    for (int i = 0; i < 4; i++) {
        int f = t + 256 * i;
        int r = f >> 4, c = (f & 15) * 8;
        cpa16(s2u(Ws + r * WST + c), W + (size_t)(k0 + r) * Ddim + n0 + c);
    }
    CP_COMMIT();
}

__device__ __forceinline__ void gemm_pipe_body(const bf16* __restrict__ A,
                                               const bf16* __restrict__ W,
                                               float acc[4][4][4],
                                               char* smraw)
{
    bf16* Asb[2] = { (bf16*)(smraw + GAS0), (bf16*)(smraw + GAS1) };
    bf16* Wsb[2] = { (bf16*)(smraw + GWS0), (bf16*)(smraw + GWS1) };
    const int t = threadIdx.x, lane = t & 31, wid = t >> 5;
    const int wm = (wid >> 2) * 64, wn = (wid & 3) * 32;
    const int m0 = blockIdx.y * 128, n0 = blockIdx.x * 128;

    #pragma unroll
    for (int i = 0; i < 4; i++)
        #pragma unroll
        for (int j = 0; j < 4; j++)
            #pragma unroll
            for (int c = 0; c < 4; c++) acc[i][j][c] = 0.f;

    gemm_load_stage(A, W, Asb[0], Wsb[0], m0, n0, 0, t);

    for (int kc = 0; kc < 8; kc++) {
        bf16* As = Asb[kc & 1];
        bf16* Ws = Wsb[kc & 1];
        CP_WAIT0();
        __syncthreads();
        if (kc < 7)
            gemm_load_stage(A, W, Asb[(kc + 1) & 1], Wsb[(kc + 1) & 1],
                            m0, n0, (kc + 1) * 64, t);
        #pragma unroll
        for (int ks = 0; ks < 4; ks++) {
            int kk = ks * 16;
            u32 a[4][4], b[4][2];
            #pragma unroll
            for (int mt = 0; mt < 4; mt++)
                ldsm4(a[mt], aaddr(As, AST, wm + mt * 16, kk, lane));
            #pragma unroll
            for (int p = 0; p < 2; p++) {
                u32 bb[4];
                ldsm4t(bb, baddr_t(Ws, WST, kk, wn + 16 * p, lane));
                b[2*p][0] = bb[0]; b[2*p][1] = bb[1];
                b[2*p+1][0] = bb[2]; b[2*p+1][1] = bb[3];
            }
            #pragma unroll
            for (int mt = 0; mt < 4; mt++)
                #pragma unroll
                for (int nt = 0; nt < 4; nt++) mma16(acc[mt][nt], a[mt], b[nt]);
        }
    }
}

// QKV: z picks {q,k,v}; bf16 output in [BH, N, DH] layout, bias fused.
__global__ void __launch_bounds__(256) qkv_mma_kernel(
    const float* __restrict__ bq, const float* __restrict__ bk,
    const float* __restrict__ bv)
{
    extern __shared__ char smraw[];
    float* bs = (float*)(smraw + GBS);
    const bf16* W = g_wb[blockIdx.z];
    const float* bias = (blockIdx.z == 0) ? bq : (blockIdx.z == 1) ? bk : bv;
    bf16* O = (blockIdx.z == 0) ? g_q : (blockIdx.z == 1) ? g_k : g_v;

    const int t = threadIdx.x, lane = t & 31, wid = t >> 5;
    const int gid = lane >> 2, tig = lane & 3;
    const int wm = (wid >> 2) * 64, wn = (wid & 3) * 32;
    const int m0 = blockIdx.y * 128, n0 = blockIdx.x * 128;
    if (t < 128) bs[t] = bias[n0 + t];

    float acc[4][4][4];
    gemm_pipe_body(g_h, W, acc, smraw);

    #pragma unroll
    for (int mt = 0; mt < 4; mt++)
        #pragma unroll
        for (int nt = 0; nt < 4; nt++) {
            int cl = wn + nt * 8 + 2 * tig;
            int n  = n0 + cl;
            int h  = n >> 6, dh = n & 63;
            int mr = m0 + wm + mt * 16 + gid;
            {
                int b0i = mr >> 10, ns = mr & 1023;
                bf162 v = __floats2bfloat162_rn(acc[mt][nt][0] + bs[cl],
                                                acc[mt][nt][1] + bs[cl + 1]);
                *(u32*)(O + (((size_t)(b0i * Hn + h) * Nseq + ns) * DH + dh)) = *(u32*)&v;
            }
            {
                int mr2 = mr + 8;
                int b0i = mr2 >> 10, ns = mr2 & 1023;
                bf162 v = __floats2bfloat162_rn(acc[mt][nt][2] + bs[cl],
                                                acc[mt][nt][3] + bs[cl + 1]);
                *(u32*)(O + (((size_t)(b0i * Hn + h) * Nseq + ns) * DH + dh)) = *(u32*)&v;
            }
        }
}

// Output projection: g_y = attnout @ Wo + bo + x   (bf16 A, f32 out)
__global__ void __launch_bounds__(256) proj_mma_kernel(
    const float* __restrict__ bo, const float* __restrict__ xres)
{
    extern __shared__ char smraw[];
    float* bs = (float*)(smraw + GBS);
    const int t = threadIdx.x, lane = t & 31, wid = t >> 5;
    const int gid = lane >> 2, tig = lane & 3;
    const int wm = (wid >> 2) * 64, wn = (wid & 3) * 32;
    const int m0 = blockIdx.y * 128, n0 = blockIdx.x * 128;
    if (t < 128) bs[t] = bo[n0 + t];

    float acc[4][4][4];
    gemm_pipe_body(g_attnout, g_wb[3], acc, smraw);

    #pragma unroll
    for (int mt = 0; mt < 4; mt++)
        #pragma unroll
        for (int nt = 0; nt < 4; nt++) {
            int cl = wn + nt * 8 + 2 * tig;
            int n  = n0 + cl;
            int mr = m0 + wm + mt * 16 + gid;
            {
                size_t idx = (size_t)mr * Ddim + n;
                float2 xr = *(const float2*)(xres + idx);
                float2 p = { acc[mt][nt][0] + bs[cl] + xr.x,
                             acc[mt][nt][1] + bs[cl + 1] + xr.y };
                *(float2*)(g_y + idx) = p;
            }
            {
                size_t idx = (size_t)(mr + 8) * Ddim + n;
                float2 xr = *(const float2*)(xres + idx);
                float2 p = { acc[mt][nt][2] + bs[cl] + xr.x,
                             acc[mt][nt][3] + bs[cl + 1] + xr.y };
                *(float2*)(g_y + idx) = p;
            }
        }
}

// ---------------- Fused attention: register-resident P (R9, now with fixed q2/k2)
#define FAST 72
#define QS_B   0
#define KS0_B  18432
#define KS1_B  27648
#define VS0_B  36864
#define VS1_B  46080
#define K20_B  55296
#define K21_B  55552
#define FA_SMEM 55808

__global__ void __launch_bounds__(256, 2) fused_attn_kernel()
{
    extern __shared__ char smraw[];
    bf16*  Qs     = (bf16*)(smraw + QS_B);
    bf16*  Ksb[2] = { (bf16*)(smraw + KS0_B), (bf16*)(smraw + KS1_B) };
    bf16*  Vsb[2] = { (bf16*)(smraw + VS0_B), (bf16*)(smraw + VS1_B) };
    float* k2b[2] = { (float*)(smraw + K20_B), (float*)(smraw + K21_B) };

    const int t = threadIdx.x, lane = t & 31, wid = t >> 5;
    const int gid = lane >> 2, tig = lane & 3;
    const int wm = wid * 16;
    const int i0 = blockIdx.x * 128;
    const int bh = blockIdx.y;
    const bf16* Qg = g_q + (size_t)bh * Nseq * DH;
    const bf16* Kg = g_k + (size_t)bh * Nseq * DH;
    const bf16* Vg = g_v + (size_t)bh * Nseq * DH;
    const float* k2g = g_k2 + (size_t)bh * Nseq;

    // prefetch chunk 0 (K, V, k2)
    #pragma unroll
    for (int i = 0; i < 2; i++) {
        int f = t + 256 * i;
        int r = f >> 3, c = (f & 7) * 8;
        cpa16(s2u(Ksb[0] + r * FAST + c), Kg + (size_t)r * DH + c);
        cpa16(s2u(Vsb[0] + r * FAST + c), Vg + (size_t)r * DH + c);
    }
    if (t < 16) cpa16(s2u(k2b[0] + t * 4), k2g + t * 4);
    CP_COMMIT();

    // load Q tile (plain stores; first chunk's sync orders them)
    #pragma unroll
    for (int i = 0; i < 4; i++) {
        int f = t + 256 * i;
        int r = f >> 3, c = (f & 7) * 8;
        *(uint4*)(Qs + r * FAST + c) = *(const uint4*)(Qg + (size_t)(i0 + r) * DH + c);
    }
    const float q2a = g_q2[(size_t)bh * Nseq + i0 + wm + gid];
    const float q2b = g_q2[(size_t)bh * Nseq + i0 + wm + gid + 8];

    float oacc[8][4];
    #pragma unroll
    for (int nt = 0; nt < 8; nt++)
        #pragma unroll
        for (int c = 0; c < 4; c++) oacc[nt][c] = 0.f;
    float rs0 = 0.f, rs1 = 0.f;

    for (int jc = 0; jc < 16; jc++) {
        bf16*  Ks  = Ksb[jc & 1];
        bf16*  Vs  = Vsb[jc & 1];
        float* k2c = k2b[jc & 1];
        CP_WAIT0();
        __syncthreads();   // chunk data visible; all warps done with other buffer
        if (jc < 15) {
            int j1 = (jc + 1) * 64;
            bf16*  Kn  = Ksb[(jc + 1) & 1];
            bf16*  Vn  = Vsb[(jc + 1) & 1];
            float* k2n = k2b[(jc + 1) & 1];
            #pragma unroll
            for (int i = 0; i < 2; i++) {
                int f = t + 256 * i;
                int r = f >> 3, c = (f & 7) * 8;
                cpa16(s2u(Kn + r * FAST + c), Kg + (size_t)(j1 + r) * DH + c);
                cpa16(s2u(Vn + r * FAST + c), Vg + (size_t)(j1 + r) * DH + c);
            }
            if (t < 16) cpa16(s2u(k2n + t * 4), k2g + j1 + t * 4);
            CP_COMMIT();
        }

        // S = Q @ K^T : warp tile 16 rows x 64 keys
        float sacc[8][4];
        #pragma unroll
        for (int nt = 0; nt < 8; nt++)
            #pragma unroll
            for (int c = 0; c < 4; c++) sacc[nt][c] = 0.f;
        #pragma unroll
        for (int ks = 0; ks < 4; ks++) {
            int kk = ks * 16;
            u32 a[4];
            ldsm4(a, aaddr(Qs, FAST, wm, kk, lane));
            #pragma unroll
            for (int p = 0; p < 4; p++) {
                u32 bb[4];
                ldsm4(bb, baddr_k(Ks, FAST, 16 * p, kk, lane));
                mma16(sacc[2*p],     a, &bb[0]);
                mma16(sacc[2*p + 1], a, &bb[2]);
            }
        }

        // epilogue: P = exp(-dist) directly into PV A-fragments (registers)
        u32 pa[4][4];
        #pragma unroll
        for (int nt = 0; nt < 8; nt++) {
            int cl = nt * 8 + 2 * tig;
            float k2a = k2c[cl], k2b2 = k2c[cl + 1];
            float d0 = fmaxf(fmaf(-2.f, sacc[nt][0], q2a + k2a),  0.f) + 1e-8f;
            float d1 = fmaxf(fmaf(-2.f, sacc[nt][1], q2a + k2b2), 0.f) + 1e-8f;
            float d2 = fmaxf(fmaf(-2.f, sacc[nt][2], q2b + k2a),  0.f) + 1e-8f;
            float d3 = fmaxf(fmaf(-2.f, sacc[nt][3], q2b + k2b2), 0.f) + 1e-8f;
            float p0 = __expf(-sqrtf(d0));
            float p1 = __expf(-sqrtf(d1));
            float p2 = __expf(-sqrtf(d2));
            float p3 = __expf(-sqrtf(d3));
            rs0 += p0 + p1;
            rs1 += p2 + p3;
            bf162 w01 = __floats2bfloat162_rn(p0, p1);
            bf162 w23 = __floats2bfloat162_rn(p2, p3);
            if ((nt & 1) == 0) { pa[nt >> 1][0] = *(u32*)&w01; pa[nt >> 1][1] = *(u32*)&w23; }
            else               { pa[nt >> 1][2] = *(u32*)&w01; pa[nt >> 1][3] = *(u32*)&w23; }
        }

        // O += P @ V : A from registers, B = V via ldmatrix.trans
        #pragma unroll
        for (int k4 = 0; k4 < 4; k4++) {
            int kk = k4 * 16;
            #pragma unroll
            for (int p = 0; p < 4; p++) {
                u32 bb[4];
                ldsm4t(bb, baddr_t(Vs, FAST, kk, 16 * p, lane));
                mma16(oacc[2*p],     pa[k4], &bb[0]);
                mma16(oacc[2*p + 1], pa[k4], &bb[2]);
            }
        }
    }

    // quad-reduce row sums (cols split across tig only)
    rs0 += __shfl_xor_sync(0xffffffffu, rs0, 1);
    rs0 += __shfl_xor_sync(0xffffffffu, rs0, 2);
    rs1 += __shfl_xor_sync(0xffffffffu, rs1, 1);
    rs1 += __shfl_xor_sync(0xffffffffu, rs1, 2);
    float li0 = 1.0f / rs0;
    float li1 = 1.0f / rs1;

    const int b = bh >> 3, h = bh & 7;
    const int i = i0 + wm + gid;
    #pragma unroll
    for (int nt = 0; nt < 8; nt++) {
        int dh = nt * 8 + 2 * tig;
        bf162 w0 = __floats2bfloat162_rn(oacc[nt][0] * li0, oacc[nt][1] * li0);
        bf162 w1 = __floats2bfloat162_rn(oacc[nt][2] * li1, oacc[nt][3] * li1);
        *(u32*)(g_attnout + ((size_t)(b * Nseq + i) * Ddim + h * DH + dh)) = *(u32*)&w0;
        *(u32*)(g_attnout + ((size_t)(b * Nseq + i + 8) * Ddim + h * DH + dh)) = *(u32*)&w1;
    }
}

// ---------------- launch ------------------------------------------------------
extern "C" void kernel_launch(void* const* d_in, const int* in_sizes, int n_in,
                              void* d_out, int out_size)
{
    const float* x = nullptr;
    const float* Wm[4] = {nullptr, nullptr, nullptr, nullptr};
    const float* vec[8] = {nullptr};
    int nm = 0, nv = 0;
    for (int i = 0; i < n_in; i++) {
        if (in_sizes[i] == BN_ROWS * Ddim)      x = (const float*)d_in[i];
        else if (in_sizes[i] == Ddim * Ddim)    { if (nm < 4) Wm[nm++] = (const float*)d_in[i]; }
        else if (in_sizes[i] == Ddim)           { if (nv < 8) vec[nv++] = (const float*)d_in[i]; }
    }
    const float *bq = vec[0], *bk = vec[1], *bv = vec[2], *bo = vec[3];
    const float *ln1g = vec[4], *ln1b = vec[5], *ln2g = vec[6], *ln2b = vec[7];

    void *p_h = nullptr, *p_y = nullptr;
    cudaGetSymbolAddress(&p_h, g_h);
    cudaGetSymbolAddress(&p_y, g_y);

    cudaFuncSetAttribute(fused_attn_kernel,
                         cudaFuncAttributeMaxDynamicSharedMemorySize, FA_SMEM);
    cudaFuncSetAttribute(qkv_mma_kernel,
                         cudaFuncAttributeMaxDynamicSharedMemorySize, GEMM_SMEM);
    cudaFuncSetAttribute(proj_mma_kernel,
                         cudaFuncAttributeMaxDynamicSharedMemorySize, GEMM_SMEM);

    wconv_kernel<<<dim3(256, 4), 256>>>(Wm[0], Wm[1], Wm[2], Wm[3]);
    ln_bf16_kernel<<<BN_ROWS, 128>>>(x, ln1g, ln1b, (bf16*)p_h);
    qkv_mma_kernel<<<dim3(Ddim / 128, BN_ROWS / 128, 3), 256, GEMM_SMEM>>>(bq, bk, bv);
    sq_kernel<<<HROWS / 256, 256>>>();   // FIXED: all 65536 head-rows
    fused_attn_kernel<<<dim3(Nseq / 128, NBH), 256, FA_SMEM>>>();
    proj_mma_kernel<<<dim3(Ddim / 128, BN_ROWS / 128), 256, GEMM_SMEM>>>(bo, x);
    ln_f32_kernel<<<BN_ROWS, 128>>>((const float*)p_y, ln2g, ln2b, (float*)d_out);
}

// round 12
// speedup vs baseline: 7.9262x; 1.1322x over previous
#include <cuda_runtime.h>
#include <cuda_bf16.h>
#include <stdint.h>
#include <cstdint>
#include <math.h>

#define Bdim 8
#define Nseq 1024
#define Ddim 512
#define Hn 8
#define DH 64
#define BN_ROWS (Bdim * Nseq)   // 8192
#define NBH (Bdim * Hn)         // 64
#define HROWS (NBH * Nseq)      // 65536 head-rows of DH

typedef unsigned int u32;
typedef __nv_bfloat16 bf16;
typedef __nv_bfloat162 bf162;

// ---------------- scratch (device globals; no allocation allowed) ------------
__device__ bf16  g_h[BN_ROWS * Ddim];        // LN1 output (bf16)
__device__ bf16  g_q[BN_ROWS * Ddim];        // [BH, N, DH] bf16
__device__ bf16  g_k[BN_ROWS * Ddim];
__device__ bf16  g_v[BN_ROWS * Ddim];
__device__ bf16  g_attnout[BN_ROWS * Ddim];  // [B, N, D] bf16
__device__ float g_y[BN_ROWS * Ddim];        // proj + residual, pre-LN2 (f32)
__device__ bf16  g_wb[4][Ddim * Ddim];       // bf16 copies of Wq,Wk,Wv,Wo
__device__ float g_q2[HROWS];                // ||q||^2 per head-row
__device__ float g_k2[HROWS];                // ||k||^2 per head-row

// ---------------- helpers -----------------------------------------------------
__device__ __forceinline__ u32 s2u(const void* p) {
    u32 a;
    asm("{ .reg .u64 t; cvta.to.shared.u64 t, %1; cvt.u32.u64 %0, t; }" : "=r"(a) : "l"(p));
    return a;
}
__device__ __forceinline__ void cpa16(u32 smem, const void* g) {
    asm volatile("cp.async.cg.shared.global [%0],[%1],16;" :: "r"(smem), "l"(g));
}
#define CP_COMMIT() asm volatile("cp.async.commit_group;")
#define CP_WAIT0()  asm volatile("cp.async.wait_group 0;")

__device__ __forceinline__ void ldsm4(u32* r, u32 addr) {
    asm volatile("ldmatrix.sync.aligned.m8n8.x4.shared.b16 {%0,%1,%2,%3},[%4];"
                 : "=r"(r[0]), "=r"(r[1]), "=r"(r[2]), "=r"(r[3]) : "r"(addr));
}
__device__ __forceinline__ void ldsm4t(u32* r, u32 addr) {
    asm volatile("ldmatrix.sync.aligned.m8n8.x4.trans.shared.b16 {%0,%1,%2,%3},[%4];"
                 : "=r"(r[0]), "=r"(r[1]), "=r"(r[2]), "=r"(r[3]) : "r"(addr));
}
__device__ __forceinline__ void mma16(float* c, const u32* a, const u32* b) {
    asm volatile(
        "mma.sync.aligned.m16n8k16.row.col.f32.bf16.bf16.f32 "
        "{%0,%1,%2,%3},{%4,%5,%6,%7},{%8,%9},{%0,%1,%2,%3};\n"
        : "+f"(c[0]), "+f"(c[1]), "+f"(c[2]), "+f"(c[3])
        : "r"(a[0]), "r"(a[1]), "r"(a[2]), "r"(a[3]), "r"(b[0]), "r"(b[1]));
}
__device__ __forceinline__ u32 aaddr(const bf16* base, int stride, int mm, int k, int lane) {
    int row = mm + (lane & 7) + (((lane >> 3) & 1) << 3);
    int col = k + ((lane >> 4) << 3);
    return s2u(base + row * stride + col);
}
__device__ __forceinline__ u32 baddr_k(const bf16* base, int stride, int n, int k, int lane) {
    int m = lane >> 3;
    int row = n + ((m >> 1) << 3) + (lane & 7);
    int col = k + ((m & 1) << 3);
    return s2u(base + row * stride + col);
}
__device__ __forceinline__ u32 baddr_t(const bf16* base, int stride, int k, int n, int lane) {
    int m = lane >> 3;
    int row = k + ((m & 1) << 3) + (lane & 7);
    int col = n + ((m >> 1) << 3);
    return s2u(base + row * stride + col);
}
__device__ __forceinline__ float2 b2f(u32 u) {
    bf162 h = *(bf162*)&u;
    return __bfloat1622float2(h);
}
// single-MUFU sqrt (avoids the IEEE Newton sequence without fast-math)
__device__ __forceinline__ float sqrt_ap(float x) {
    float y;
    asm("sqrt.approx.f32 %0, %1;" : "=f"(y) : "f"(x));
    return y;
}

// ---------------- weight f32->bf16 conversion ---------------------------------
__global__ void wconv_kernel(const float* __restrict__ w0, const float* __restrict__ w1,
                             const float* __restrict__ w2, const float* __restrict__ w3)
{
    const float* src = (blockIdx.y == 0) ? w0 : (blockIdx.y == 1) ? w1
                      : (blockIdx.y == 2) ? w2 : w3;
    bf16* dst = g_wb[blockIdx.y];
    int i = blockIdx.x * 256 + threadIdx.x;
    float4 v = ((const float4*)src)[i];
    bf162 lo = __floats2bfloat162_rn(v.x, v.y);
    bf162 hi = __floats2bfloat162_rn(v.z, v.w);
    uint2 pk = { *(u32*)&lo, *(u32*)&hi };
    ((uint2*)dst)[i] = pk;
}

// ---------------- q2/k2 precompute: one row per thread, q-half / k-half -------
__global__ void sq_kernel()
{
    int gtid = blockIdx.x * 256 + threadIdx.x;   // 0..2*HROWS-1
    int row = gtid & (HROWS - 1);
    const bf16* src = (gtid < HROWS) ? g_q : g_k;
    float* dst = (gtid < HROWS) ? g_q2 : g_k2;
    const uint4* p = (const uint4*)(src + (size_t)row * DH);
    float s = 0.f;
    #pragma unroll
    for (int i = 0; i < 8; i++) {
        uint4 u = p[i];
        float2 f0 = b2f(u.x), f1 = b2f(u.y), f2 = b2f(u.z), f3 = b2f(u.w);
        s += f0.x*f0.x + f0.y*f0.y + f1.x*f1.x + f1.y*f1.y
           + f2.x*f2.x + f2.y*f2.y + f3.x*f3.x + f3.y*f3.y;
    }
    dst[row] = s;
}

// ---------------- LayerNorm ---------------------------------------------------
__device__ __forceinline__ float4 ln_row_body(const float* __restrict__ in,
                                              const float* __restrict__ gamma,
                                              const float* __restrict__ beta,
                                              int row)
{
    const float4* r = (const float4*)(in + (size_t)row * Ddim);
    float4 a = r[threadIdx.x];
    float s  = a.x + a.y + a.z + a.w;
    float s2 = a.x*a.x + a.y*a.y + a.z*a.z + a.w*a.w;
    #pragma unroll
    for (int off = 16; off; off >>= 1) {
        s  += __shfl_xor_sync(0xffffffffu, s,  off);
        s2 += __shfl_xor_sync(0xffffffffu, s2, off);
    }
    __shared__ float sbA[4], sbB[4];
    int wid = threadIdx.x >> 5, lane = threadIdx.x & 31;
    if (lane == 0) { sbA[wid] = s; sbB[wid] = s2; }
    __syncthreads();
    s  = sbA[0] + sbA[1] + sbA[2] + sbA[3];
    s2 = sbB[0] + sbB[1] + sbB[2] + sbB[3];
    float mean = s * (1.0f / Ddim);
    float var  = s2 * (1.0f / Ddim) - mean * mean;
    float rstd = rsqrtf(var + 1e-5f);
    float4 g = ((const float4*)gamma)[threadIdx.x];
    float4 b = ((const float4*)beta)[threadIdx.x];
    float4 o;
    o.x = (a.x - mean) * rstd * g.x + b.x;
    o.y = (a.y - mean) * rstd * g.y + b.y;
    o.z = (a.z - mean) * rstd * g.z + b.z;
    o.w = (a.w - mean) * rstd * g.w + b.w;
    return o;
}

__global__ void ln_bf16_kernel(const float* __restrict__ in,
                               const float* __restrict__ gamma,
                               const float* __restrict__ beta,
                               bf16* __restrict__ out)
{
    int row = blockIdx.x;
    float4 o = ln_row_body(in, gamma, beta, row);
    bf162 lo = __floats2bfloat162_rn(o.x, o.y);
    bf162 hi = __floats2bfloat162_rn(o.z, o.w);
    uint2 pk = { *(u32*)&lo, *(u32*)&hi };
    *(uint2*)(out + (size_t)row * Ddim + 4 * threadIdx.x) = pk;
}

__global__ void ln_f32_kernel(const float* __restrict__ in,
                              const float* __restrict__ gamma,
                              const float* __restrict__ beta,
                              float* __restrict__ out)
{
    int row = blockIdx.x;
    float4 o = ln_row_body(in, gamma, beta, row);
    ((float4*)(out + (size_t)row * Ddim))[threadIdx.x] = o;
}

// ---------------- bf16 MMA GEMM core, cp.async double-buffered ----------------
#define AST 72
#define WST 136
#define GAS0 0
#define GAS1 18432
#define GWS0 36864
#define GWS1 54272
#define GBS  71680
#define GEMM_SMEM 72192

__device__ __forceinline__ void gemm_load_stage(const bf16* __restrict__ A,
                                                const bf16* __restrict__ W,
                                                bf16* As, bf16* Ws,
                                                int m0, int n0, int k0, int t)
{
    #pragma unroll
    for (int i = 0; i < 4; i++) {
        int f = t + 256 * i;
        int r = f >> 3, c = (f & 7) * 8;
        cpa16(s2u(As + r * AST + c), A + (size_t)(m0 + r) * Ddim + k0 + c);
    }
    #pragma unroll
    for (int i = 0; i < 4; i++) {
        int f = t + 256 * i;
        int r = f >> 4, c = (f & 15) * 8;
        cpa16(s2u(Ws + r * WST + c), W + (size_t)(k0 + r) * Ddim + n0 + c);
    }
    CP_COMMIT();
}

__device__ __forceinline__ void gemm_pipe_body(const bf16* __restrict__ A,
                                               const bf16* __restrict__ W,
                                               float acc[4][4][4],
                                               char* smraw)
{
    bf16* Asb[2] = { (bf16*)(smraw + GAS0), (bf16*)(smraw + GAS1) };
    bf16* Wsb[2] = { (bf16*)(smraw + GWS0), (bf16*)(smraw + GWS1) };
    const int t = threadIdx.x, lane = t & 31, wid = t >> 5;
    const int wm = (wid >> 2) * 64, wn = (wid & 3) * 32;
    const int m0 = blockIdx.y * 128, n0 = blockIdx.x * 128;

    #pragma unroll
    for (int i = 0; i < 4; i++)
        #pragma unroll
        for (int j = 0; j < 4; j++)
            #pragma unroll
            for (int c = 0; c < 4; c++) acc[i][j][c] = 0.f;

    gemm_load_stage(A, W, Asb[0], Wsb[0], m0, n0, 0, t);

    for (int kc = 0; kc < 8; kc++) {
        bf16* As = Asb[kc & 1];
        bf16* Ws = Wsb[kc & 1];
        CP_WAIT0();
        __syncthreads();
        if (kc < 7)
            gemm_load_stage(A, W, Asb[(kc + 1) & 1], Wsb[(kc + 1) & 1],
                            m0, n0, (kc + 1) * 64, t);
        #pragma unroll
        for (int ks = 0; ks < 4; ks++) {
            int kk = ks * 16;
            u32 a[4][4], b[4][2];
            #pragma unroll
            for (int mt = 0; mt < 4; mt++)
                ldsm4(a[mt], aaddr(As, AST, wm + mt * 16, kk, lane));
            #pragma unroll
            for (int p = 0; p < 2; p++) {
                u32 bb[4];
                ldsm4t(bb, baddr_t(Ws, WST, kk, wn + 16 * p, lane));
                b[2*p][0] = bb[0]; b[2*p][1] = bb[1];
                b[2*p+1][0] = bb[2]; b[2*p+1][1] = bb[3];
            }
            #pragma unroll
            for (int mt = 0; mt < 4; mt++)
                #pragma unroll
                for (int nt = 0; nt < 4; nt++) mma16(acc[mt][nt], a[mt], b[nt]);
        }
    }
}

// QKV: z picks {q,k,v}; bf16 output in [BH, N, DH] layout, bias fused.
__global__ void __launch_bounds__(256) qkv_mma_kernel(
    const float* __restrict__ bq, const float* __restrict__ bk,
    const float* __restrict__ bv)
{
    extern __shared__ char smraw[];
    float* bs = (float*)(smraw + GBS);
    const bf16* W = g_wb[blockIdx.z];
    const float* bias = (blockIdx.z == 0) ? bq : (blockIdx.z == 1) ? bk : bv;
    bf16* O = (blockIdx.z == 0) ? g_q : (blockIdx.z == 1) ? g_k : g_v;

    const int t = threadIdx.x, lane = t & 31, wid = t >> 5;
    const int gid = lane >> 2, tig = lane & 3;
    const int wm = (wid >> 2) * 64, wn = (wid & 3) * 32;
    const int m0 = blockIdx.y * 128, n0 = blockIdx.x * 128;
    if (t < 128) bs[t] = bias[n0 + t];

    float acc[4][4][4];
    gemm_pipe_body(g_h, W, acc, smraw);

    #pragma unroll
    for (int mt = 0; mt < 4; mt++)
        #pragma unroll
        for (int nt = 0; nt < 4; nt++) {
            int cl = wn + nt * 8 + 2 * tig;
            int n  = n0 + cl;
            int h  = n >> 6, dh = n & 63;
            int mr = m0 + wm + mt * 16 + gid;
            {
                int b0i = mr >> 10, ns = mr & 1023;
                bf162 v = __floats2bfloat162_rn(acc[mt][nt][0] + bs[cl],
                                                acc[mt][nt][1] + bs[cl + 1]);
                *(u32*)(O + (((size_t)(b0i * Hn + h) * Nseq + ns) * DH + dh)) = *(u32*)&v;
            }
            {
                int mr2 = mr + 8;
                int b0i = mr2 >> 10, ns = mr2 & 1023;
                bf162 v = __floats2bfloat162_rn(acc[mt][nt][2] + bs[cl],
                                                acc[mt][nt][3] + bs[cl + 1]);
                *(u32*)(O + (((size_t)(b0i * Hn + h) * Nseq + ns) * DH + dh)) = *(u32*)&v;
            }
        }
}

// Output projection: g_y = attnout @ Wo + bo + x   (bf16 A, f32 out)
__global__ void __launch_bounds__(256) proj_mma_kernel(
    const float* __restrict__ bo, const float* __restrict__ xres)
{
    extern __shared__ char smraw[];
    float* bs = (float*)(smraw + GBS);
    const int t = threadIdx.x, lane = t & 31, wid = t >> 5;
    const int gid = lane >> 2, tig = lane & 3;
    const int wm = (wid >> 2) * 64, wn = (wid & 3) * 32;
    const int m0 = blockIdx.y * 128, n0 = blockIdx.x * 128;
    if (t < 128) bs[t] = bo[n0 + t];

    float acc[4][4][4];
    gemm_pipe_body(g_attnout, g_wb[3], acc, smraw);

    #pragma unroll
    for (int mt = 0; mt < 4; mt++)
        #pragma unroll
        for (int nt = 0; nt < 4; nt++) {
            int cl = wn + nt * 8 + 2 * tig;
            int n  = n0 + cl;
            int mr = m0 + wm + mt * 16 + gid;
            {
                size_t idx = (size_t)mr * Ddim + n;
                float2 xr = *(const float2*)(xres + idx);
                float2 p = { acc[mt][nt][0] + bs[cl] + xr.x,
                             acc[mt][nt][1] + bs[cl + 1] + xr.y };
                *(float2*)(g_y + idx) = p;
            }
            {
                size_t idx = (size_t)(mr + 8) * Ddim + n;
                float2 xr = *(const float2*)(xres + idx);
                float2 p = { acc[mt][nt][2] + bs[cl] + xr.x,
                             acc[mt][nt][3] + bs[cl + 1] + xr.y };
                *(float2*)(g_y + idx) = p;
            }
        }
}

// ---------------- Fused attention: register-resident P ------------------------
#define FAST 72
#define QS_B   0
#define KS0_B  18432
#define KS1_B  27648
#define VS0_B  36864
#define VS1_B  46080
#define K20_B  55296
#define K21_B  55552
#define FA_SMEM 55808

__global__ void __launch_bounds__(256, 2) fused_attn_kernel()
{
    extern __shared__ char smraw[];
    bf16*  Qs     = (bf16*)(smraw + QS_B);
    bf16*  Ksb[2] = { (bf16*)(smraw + KS0_B), (bf16*)(smraw + KS1_B) };
    bf16*  Vsb[2] = { (bf16*)(smraw + VS0_B), (bf16*)(smraw + VS1_B) };
    float* k2b[2] = { (float*)(smraw + K20_B), (float*)(smraw + K21_B) };

    const int t = threadIdx.x, lane = t & 31, wid = t >> 5;
    const int gid = lane >> 2, tig = lane & 3;
    const int wm = wid * 16;
    const int i0 = blockIdx.x * 128;
    const int bh = blockIdx.y;
    const bf16* Qg = g_q + (size_t)bh * Nseq * DH;
    const bf16* Kg = g_k + (size_t)bh * Nseq * DH;
    const bf16* Vg = g_v + (size_t)bh * Nseq * DH;
    const float* k2g = g_k2 + (size_t)bh * Nseq;

    // prefetch chunk 0 (K, V, k2)
    #pragma unroll
    for (int i = 0; i < 2; i++) {
        int f = t + 256 * i;
        int r = f >> 3, c = (f & 7) * 8;
        cpa16(s2u(Ksb[0] + r * FAST + c), Kg + (size_t)r * DH + c);
        cpa16(s2u(Vsb[0] + r * FAST + c), Vg + (size_t)r * DH + c);
    }
    if (t < 16) cpa16(s2u(k2b[0] + t * 4), k2g + t * 4);
    CP_COMMIT();

    // load Q tile (plain stores; first chunk's sync orders them)
    #pragma unroll
    for (int i = 0; i < 4; i++) {
        int f = t + 256 * i;
        int r = f >> 3, c = (f & 7) * 8;
        *(uint4*)(Qs + r * FAST + c) = *(const uint4*)(Qg + (size_t)(i0 + r) * DH + c);
    }
    const float q2a = g_q2[(size_t)bh * Nseq + i0 + wm + gid];
    const float q2b = g_q2[(size_t)bh * Nseq + i0 + wm + gid + 8];

    float oacc[8][4];
    #pragma unroll
    for (int nt = 0; nt < 8; nt++)
        #pragma unroll
        for (int c = 0; c < 4; c++) oacc[nt][c] = 0.f;
    float rs0 = 0.f, rs1 = 0.f;

    for (int jc = 0; jc < 16; jc++) {
        bf16*  Ks  = Ksb[jc & 1];
        bf16*  Vs  = Vsb[jc & 1];
        float* k2c = k2b[jc & 1];
        CP_WAIT0();
        __syncthreads();   // chunk data visible; all warps done with other buffer
        if (jc < 15) {
            int j1 = (jc + 1) * 64;
            bf16*  Kn  = Ksb[(jc + 1) & 1];
            bf16*  Vn  = Vsb[(jc + 1) & 1];
            float* k2n = k2b[(jc + 1) & 1];
            #pragma unroll
            for (int i = 0; i < 2; i++) {
                int f = t + 256 * i;
                int r = f >> 3, c = (f & 7) * 8;
                cpa16(s2u(Kn + r * FAST + c), Kg + (size_t)(j1 + r) * DH + c);
                cpa16(s2u(Vn + r * FAST + c), Vg + (size_t)(j1 + r) * DH + c);
            }
            if (t < 16) cpa16(s2u(k2n + t * 4), k2g + j1 + t * 4);
            CP_COMMIT();
        }

        // S = Q @ K^T : warp tile 16 rows x 64 keys
        float sacc[8][4];
        #pragma unroll
        for (int nt = 0; nt < 8; nt++)
            #pragma unroll
            for (int c = 0; c < 4; c++) sacc[nt][c] = 0.f;
        #pragma unroll
        for (int ks = 0; ks < 4; ks++) {
            int kk = ks * 16;
            u32 a[4];
            ldsm4(a, aaddr(Qs, FAST, wm, kk, lane));
            #pragma unroll
            for (int p = 0; p < 4; p++) {
                u32 bb[4];
                ldsm4(bb, baddr_k(Ks, FAST, 16 * p, kk, lane));
                mma16(sacc[2*p],     a, &bb[0]);
                mma16(sacc[2*p + 1], a, &bb[2]);
            }
        }

        // epilogue: P = exp(-sqrt.approx(dist)) directly into PV A-fragments
        u32 pa[4][4];
        #pragma unroll
        for (int nt = 0; nt < 8; nt++) {
            int cl = nt * 8 + 2 * tig;
            float k2a = k2c[cl], k2b2 = k2c[cl + 1];
            float d0 = fmaxf(fmaf(-2.f, sacc[nt][0], q2a + k2a),  0.f) + 1e-8f;
            float d1 = fmaxf(fmaf(-2.f, sacc[nt][1], q2a + k2b2), 0.f) + 1e-8f;
            float d2 = fmaxf(fmaf(-2.f, sacc[nt][2], q2b + k2a),  0.f) + 1e-8f;
            float d3 = fmaxf(fmaf(-2.f, sacc[nt][3], q2b + k2b2), 0.f) + 1e-8f;
            float p0 = __expf(-sqrt_ap(d0));
            float p1 = __expf(-sqrt_ap(d1));
            float p2 = __expf(-sqrt_ap(d2));
            float p3 = __expf(-sqrt_ap(d3));
            rs0 += p0 + p1;
            rs1 += p2 + p3;
            bf162 w01 = __floats2bfloat162_rn(p0, p1);
            bf162 w23 = __floats2bfloat162_rn(p2, p3);
            if ((nt & 1) == 0) { pa[nt >> 1][0] = *(u32*)&w01; pa[nt >> 1][1] = *(u32*)&w23; }
            else               { pa[nt >> 1][2] = *(u32*)&w01; pa[nt >> 1][3] = *(u32*)&w23; }
        }

        // O += P @ V : A from registers, B = V via ldmatrix.trans
        #pragma unroll
        for (int k4 = 0; k4 < 4; k4++) {
            int kk = k4 * 16;
            #pragma unroll
            for (int p = 0; p < 4; p++) {
                u32 bb[4];
                ldsm4t(bb, baddr_t(Vs, FAST, kk, 16 * p, lane));
                mma16(oacc[2*p],     pa[k4], &bb[0]);
                mma16(oacc[2*p + 1], pa[k4], &bb[2]);
            }
        }
    }

    // quad-reduce row sums (cols split across tig only)
    rs0 += __shfl_xor_sync(0xffffffffu, rs0, 1);
    rs0 += __shfl_xor_sync(0xffffffffu, rs0, 2);
    rs1 += __shfl_xor_sync(0xffffffffu, rs1, 1);
    rs1 += __shfl_xor_sync(0xffffffffu, rs1, 2);
    float li0 = 1.0f / rs0;
    float li1 = 1.0f / rs1;

    const int b = bh >> 3, h = bh & 7;
    const int i = i0 + wm + gid;
    #pragma unroll
    for (int nt = 0; nt < 8; nt++) {
        int dh = nt * 8 + 2 * tig;
        bf162 w0 = __floats2bfloat162_rn(oacc[nt][0] * li0, oacc[nt][1] * li0);
        bf162 w1 = __floats2bfloat162_rn(oacc[nt][2] * li1, oacc[nt][3] * li1);
        *(u32*)(g_attnout + ((size_t)(b * Nseq + i) * Ddim + h * DH + dh)) = *(u32*)&w0;
        *(u32*)(g_attnout + ((size_t)(b * Nseq + i + 8) * Ddim + h * DH + dh)) = *(u32*)&w1;
    }
}

// ---------------- launch ------------------------------------------------------
extern "C" void kernel_launch(void* const* d_in, const int* in_sizes, int n_in,
                              void* d_out, int out_size)
{
    const float* x = nullptr;
    const float* Wm[4] = {nullptr, nullptr, nullptr, nullptr};
    const float* vec[8] = {nullptr};
    int nm = 0, nv = 0;
    for (int i = 0; i < n_in; i++) {
        if (in_sizes[i] == BN_ROWS * Ddim)      x = (const float*)d_in[i];
        else if (in_sizes[i] == Ddim * Ddim)    { if (nm < 4) Wm[nm++] = (const float*)d_in[i]; }
        else if (in_sizes[i] == Ddim)           { if (nv < 8) vec[nv++] = (const float*)d_in[i]; }
    }
    const float *bq = vec[0], *bk = vec[1], *bv = vec[2], *bo = vec[3];
    const float *ln1g = vec[4], *ln1b = vec[5], *ln2g = vec[6], *ln2b = vec[7];

    void *p_h = nullptr, *p_y = nullptr;
    cudaGetSymbolAddress(&p_h, g_h);
    cudaGetSymbolAddress(&p_y, g_y);

    cudaFuncSetAttribute(fused_attn_kernel,
                         cudaFuncAttributeMaxDynamicSharedMemorySize, FA_SMEM);
    cudaFuncSetAttribute(qkv_mma_kernel,
                         cudaFuncAttributeMaxDynamicSharedMemorySize, GEMM_SMEM);
    cudaFuncSetAttribute(proj_mma_kernel,
                         cudaFuncAttributeMaxDynamicSharedMemorySize, GEMM_SMEM);

    wconv_kernel<<<dim3(256, 4), 256>>>(Wm[0], Wm[1], Wm[2], Wm[3]);
    ln_bf16_kernel<<<BN_ROWS, 128>>>(x, ln1g, ln1b, (bf16*)p_h);
    qkv_mma_kernel<<<dim3(Ddim / 128, BN_ROWS / 128, 3), 256, GEMM_SMEM>>>(bq, bk, bv);
    sq_kernel<<<2 * HROWS / 256, 256>>>();
    fused_attn_kernel<<<dim3(Nseq / 128, NBH), 256, FA_SMEM>>>();
    proj_mma_kernel<<<dim3(Ddim / 128, BN_ROWS / 128), 256, GEMM_SMEM>>>(bo, x);
    ln_f32_kernel<<<BN_ROWS, 128>>>((const float*)p_y, ln2g, ln2b, (float*)d_out);
}

// round 13
// speedup vs baseline: 8.1905x; 1.0334x over previous
#include <cuda_runtime.h>
#include <cuda_bf16.h>
#include <stdint.h>
#include <cstdint>
#include <math.h>

#define Bdim 8
#define Nseq 1024
#define Ddim 512
#define Hn 8
#define DH 64
#define BN_ROWS (Bdim * Nseq)   // 8192
#define NBH (Bdim * Hn)         // 64
#define HROWS (NBH * Nseq)      // 65536 head-rows of DH

typedef unsigned int u32;
typedef __nv_bfloat16 bf16;
typedef __nv_bfloat162 bf162;

// ---------------- scratch (device globals; no allocation allowed) ------------
__device__ bf16  g_h[BN_ROWS * Ddim];        // LN1 output (bf16)
__device__ bf16  g_q[BN_ROWS * Ddim];        // [BH, N, DH] bf16
__device__ bf16  g_k[BN_ROWS * Ddim];
__device__ bf16  g_v[BN_ROWS * Ddim];
__device__ bf16  g_attnout[BN_ROWS * Ddim];  // [B, N, D] bf16
__device__ float g_y[BN_ROWS * Ddim];        // proj + residual, pre-LN2 (f32)
__device__ bf16  g_wb[4][Ddim * Ddim];       // bf16 copies of Wq,Wk,Wv,Wo
__device__ float g_q2[HROWS];                // ||q||^2 per head-row
__device__ float g_k2[HROWS];                // ||k||^2 per head-row

// ---------------- helpers -----------------------------------------------------
__device__ __forceinline__ u32 s2u(const void* p) {
    u32 a;
    asm("{ .reg .u64 t; cvta.to.shared.u64 t, %1; cvt.u32.u64 %0, t; }" : "=r"(a) : "l"(p));
    return a;
}
__device__ __forceinline__ void cpa16(u32 smem, const void* g) {
    asm volatile("cp.async.cg.shared.global [%0],[%1],16;" :: "r"(smem), "l"(g));
}
#define CP_COMMIT() asm volatile("cp.async.commit_group;")
#define CP_WAIT0()  asm volatile("cp.async.wait_group 0;")

__device__ __forceinline__ void ldsm4(u32* r, u32 addr) {
    asm volatile("ldmatrix.sync.aligned.m8n8.x4.shared.b16 {%0,%1,%2,%3},[%4];"
                 : "=r"(r[0]), "=r"(r[1]), "=r"(r[2]), "=r"(r[3]) : "r"(addr));
}
__device__ __forceinline__ void ldsm4t(u32* r, u32 addr) {
    asm volatile("ldmatrix.sync.aligned.m8n8.x4.trans.shared.b16 {%0,%1,%2,%3},[%4];"
                 : "=r"(r[0]), "=r"(r[1]), "=r"(r[2]), "=r"(r[3]) : "r"(addr));
}
__device__ __forceinline__ void mma16(float* c, const u32* a, const u32* b) {
    asm volatile(
        "mma.sync.aligned.m16n8k16.row.col.f32.bf16.bf16.f32 "
        "{%0,%1,%2,%3},{%4,%5,%6,%7},{%8,%9},{%0,%1,%2,%3};\n"
        : "+f"(c[0]), "+f"(c[1]), "+f"(c[2]), "+f"(c[3])
        : "r"(a[0]), "r"(a[1]), "r"(a[2]), "r"(a[3]), "r"(b[0]), "r"(b[1]));
}
__device__ __forceinline__ u32 aaddr(const bf16* base, int stride, int mm, int k, int lane) {
    int row = mm + (lane & 7) + (((lane >> 3) & 1) << 3);
    int col = k + ((lane >> 4) << 3);
    return s2u(base + row * stride + col);
}
__device__ __forceinline__ u32 baddr_k(const bf16* base, int stride, int n, int k, int lane) {
    int m = lane >> 3;
    int row = n + ((m >> 1) << 3) + (lane & 7);
    int col = k + ((m & 1) << 3);
    return s2u(base + row * stride + col);
}
__device__ __forceinline__ u32 baddr_t(const bf16* base, int stride, int k, int n, int lane) {
    int m = lane >> 3;
    int row = k + ((m & 1) << 3) + (lane & 7);
    int col = n + ((m >> 1) << 3);
    return s2u(base + row * stride + col);
}
__device__ __forceinline__ float2 b2f(u32 u) {
    bf162 h = *(bf162*)&u;
    return __bfloat1622float2(h);
}
__device__ __forceinline__ float sqrt_ap(float x) {
    float y;
    asm("sqrt.approx.f32 %0, %1;" : "=f"(y) : "f"(x));
    return y;
}

// ---------------- weight f32->bf16 conversion ---------------------------------
__global__ void wconv_kernel(const float* __restrict__ w0, const float* __restrict__ w1,
                             const float* __restrict__ w2, const float* __restrict__ w3)
{
    const float* src = (blockIdx.y == 0) ? w0 : (blockIdx.y == 1) ? w1
                      : (blockIdx.y == 2) ? w2 : w3;
    bf16* dst = g_wb[blockIdx.y];
    int i = blockIdx.x * 256 + threadIdx.x;
    float4 v = ((const float4*)src)[i];
    bf162 lo = __floats2bfloat162_rn(v.x, v.y);
    bf162 hi = __floats2bfloat162_rn(v.z, v.w);
    uint2 pk = { *(u32*)&lo, *(u32*)&hi };
    ((uint2*)dst)[i] = pk;
}

// ---------------- LayerNorm: one WARP per row, shuffle-only reduction ----------
__device__ __forceinline__ void ln_warp_body(const float* __restrict__ in,
                                             const float* __restrict__ gamma,
                                             const float* __restrict__ beta,
                                             int row, int lane, float4 o[4])
{
    const float4* r = (const float4*)(in + (size_t)row * Ddim);
    float4 a[4];
    float s = 0.f, s2 = 0.f;
    #pragma unroll
    for (int i = 0; i < 4; i++) {
        a[i] = r[i * 32 + lane];
        s  += a[i].x + a[i].y + a[i].z + a[i].w;
        s2 += a[i].x*a[i].x + a[i].y*a[i].y + a[i].z*a[i].z + a[i].w*a[i].w;
    }
    #pragma unroll
    for (int off = 16; off; off >>= 1) {
        s  += __shfl_xor_sync(0xffffffffu, s,  off);
        s2 += __shfl_xor_sync(0xffffffffu, s2, off);
    }
    float mean = s * (1.0f / Ddim);
    float var  = s2 * (1.0f / Ddim) - mean * mean;
    float rstd = rsqrtf(var + 1e-5f);
    #pragma unroll
    for (int i = 0; i < 4; i++) {
        float4 g = ((const float4*)gamma)[i * 32 + lane];
        float4 b = ((const float4*)beta)[i * 32 + lane];
        o[i].x = (a[i].x - mean) * rstd * g.x + b.x;
        o[i].y = (a[i].y - mean) * rstd * g.y + b.y;
        o[i].z = (a[i].z - mean) * rstd * g.z + b.z;
        o[i].w = (a[i].w - mean) * rstd * g.w + b.w;
    }
}

__global__ void __launch_bounds__(256) ln_bf16_kernel(
    const float* __restrict__ in, const float* __restrict__ gamma,
    const float* __restrict__ beta, bf16* __restrict__ out)
{
    int lane = threadIdx.x & 31;
    int row = blockIdx.x * 8 + (threadIdx.x >> 5);
    float4 o[4];
    ln_warp_body(in, gamma, beta, row, lane, o);
    #pragma unroll
    for (int i = 0; i < 4; i++) {
        bf162 lo = __floats2bfloat162_rn(o[i].x, o[i].y);
        bf162 hi = __floats2bfloat162_rn(o[i].z, o[i].w);
        uint2 pk = { *(u32*)&lo, *(u32*)&hi };
        *(uint2*)(out + (size_t)row * Ddim + (i * 32 + lane) * 4) = pk;
    }
}

__global__ void __launch_bounds__(256) ln_f32_kernel(
    const float* __restrict__ in, const float* __restrict__ gamma,
    const float* __restrict__ beta, float* __restrict__ out)
{
    int lane = threadIdx.x & 31;
    int row = blockIdx.x * 8 + (threadIdx.x >> 5);
    float4 o[4];
    ln_warp_body(in, gamma, beta, row, lane, o);
    #pragma unroll
    for (int i = 0; i < 4; i++)
        ((float4*)(out + (size_t)row * Ddim))[i * 32 + lane] = o[i];
}

// ---------------- bf16 MMA GEMM core, cp.async double-buffered ----------------
#define AST 72
#define WST 136
#define GAS0 0
#define GAS1 18432
#define GWS0 36864
#define GWS1 54272
#define GBS  71680
#define Q2P  72192     // [128 rows][2 heads][2 halves] f32 = 2048 B
#define GEMM_SMEM 74240

__device__ __forceinline__ void gemm_load_stage(const bf16* __restrict__ A,
                                                const bf16* __restrict__ W,
                                                bf16* As, bf16* Ws,
                                                int m0, int n0, int k0, int t)
{
    #pragma unroll
    for (int i = 0; i < 4; i++) {
        int f = t + 256 * i;
        int r = f >> 3, c = (f & 7) * 8;
        cpa16(s2u(As + r * AST + c), A + (size_t)(m0 + r) * Ddim + k0 + c);
    }
    #pragma unroll
    for (int i = 0; i < 4; i++) {
        int f = t + 256 * i;
        int r = f >> 4, c = (f & 15) * 8;
        cpa16(s2u(Ws + r * WST + c), W + (size_t)(k0 + r) * Ddim + n0 + c);
    }
    CP_COMMIT();
}

__device__ __forceinline__ void gemm_pipe_body(const bf16* __restrict__ A,
                                               const bf16* __restrict__ W,
                                               float acc[4][4][4],
                                               char* smraw)
{
    bf16* Asb[2] = { (bf16*)(smraw + GAS0), (bf16*)(smraw + GAS1) };
    bf16* Wsb[2] = { (bf16*)(smraw + GWS0), (bf16*)(smraw + GWS1) };
    const int t = threadIdx.x, lane = t & 31, wid = t >> 5;
    const int wm = (wid >> 2) * 64, wn = (wid & 3) * 32;
    const int m0 = blockIdx.y * 128, n0 = blockIdx.x * 128;

    #pragma unroll
    for (int i = 0; i < 4; i++)
        #pragma unroll
        for (int j = 0; j < 4; j++)
            #pragma unroll
            for (int c = 0; c < 4; c++) acc[i][j][c] = 0.f;

    gemm_load_stage(A, W, Asb[0], Wsb[0], m0, n0, 0, t);

    for (int kc = 0; kc < 8; kc++) {
        bf16* As = Asb[kc & 1];
        bf16* Ws = Wsb[kc & 1];
        CP_WAIT0();
        __syncthreads();
        if (kc < 7)
            gemm_load_stage(A, W, Asb[(kc + 1) & 1], Wsb[(kc + 1) & 1],
                            m0, n0, (kc + 1) * 64, t);
        #pragma unroll
        for (int ks = 0; ks < 4; ks++) {
            int kk = ks * 16;
            u32 a[4][4], b[4][2];
            #pragma unroll
            for (int mt = 0; mt < 4; mt++)
                ldsm4(a[mt], aaddr(As, AST, wm + mt * 16, kk, lane));
            #pragma unroll
            for (int p = 0; p < 2; p++) {
                u32 bb[4];
                ldsm4t(bb, baddr_t(Ws, WST, kk, wn + 16 * p, lane));
                b[2*p][0] = bb[0]; b[2*p][1] = bb[1];
                b[2*p+1][0] = bb[2]; b[2*p+1][1] = bb[3];
            }
            #pragma unroll
            for (int mt = 0; mt < 4; mt++)
                #pragma unroll
                for (int nt = 0; nt < 4; nt++) mma16(acc[mt][nt], a[mt], b[nt]);
        }
    }
}

// QKV: z picks {q,k,v}; bf16 output in [BH, N, DH] layout, bias fused.
// For z<2 the epilogue also computes exact per-head-row ||.||^2 (block owns
// 2 complete heads x 128 rows) -> g_q2 / g_k2. Deterministic, no atomics.
__global__ void __launch_bounds__(256) qkv_mma_kernel(
    const float* __restrict__ bq, const float* __restrict__ bk,
    const float* __restrict__ bv)
{
    extern __shared__ char smraw[];
    float* bs  = (float*)(smraw + GBS);
    float* q2p = (float*)(smraw + Q2P);   // [row][head_local][half]
    const bf16* W = g_wb[blockIdx.z];
    const float* bias = (blockIdx.z == 0) ? bq : (blockIdx.z == 1) ? bk : bv;
    bf16* O = (blockIdx.z == 0) ? g_q : (blockIdx.z == 1) ? g_k : g_v;

    const int t = threadIdx.x, lane = t & 31, wid = t >> 5;
    const int gid = lane >> 2, tig = lane & 3;
    const int wm = (wid >> 2) * 64, wn = (wid & 3) * 32;
    const int m0 = blockIdx.y * 128, n0 = blockIdx.x * 128;
    if (t < 128) bs[t] = bias[n0 + t];

    float acc[4][4][4];
    gemm_pipe_body(g_h, W, acc, smraw);

    float rp[4][2];
    #pragma unroll
    for (int mt = 0; mt < 4; mt++) { rp[mt][0] = 0.f; rp[mt][1] = 0.f; }

    #pragma unroll
    for (int mt = 0; mt < 4; mt++)
        #pragma unroll
        for (int nt = 0; nt < 4; nt++) {
            int cl = wn + nt * 8 + 2 * tig;
            int n  = n0 + cl;
            int h  = n >> 6, dh = n & 63;
            int mr = m0 + wm + mt * 16 + gid;
            {
                int b0i = mr >> 10, ns = mr & 1023;
                bf162 v = __floats2bfloat162_rn(acc[mt][nt][0] + bs[cl],
                                                acc[mt][nt][1] + bs[cl + 1]);
                *(u32*)(O + (((size_t)(b0i * Hn + h) * Nseq + ns) * DH + dh)) = *(u32*)&v;
                float2 f = b2f(*(u32*)&v);
                rp[mt][0] += f.x * f.x + f.y * f.y;
            }
            {
                int mr2 = mr + 8;
                int b0i = mr2 >> 10, ns = mr2 & 1023;
                bf162 v = __floats2bfloat162_rn(acc[mt][nt][2] + bs[cl],
                                                acc[mt][nt][3] + bs[cl + 1]);
                *(u32*)(O + (((size_t)(b0i * Hn + h) * Nseq + ns) * DH + dh)) = *(u32*)&v;
                float2 f = b2f(*(u32*)&v);
                rp[mt][1] += f.x * f.x + f.y * f.y;
            }
        }

    if (blockIdx.z < 2) {
        int hl = wn >> 6, half = (wn >> 5) & 1;
        #pragma unroll
        for (int mt = 0; mt < 4; mt++) {
            float v0 = rp[mt][0], v1 = rp[mt][1];
            v0 += __shfl_xor_sync(0xffffffffu, v0, 1);
            v0 += __shfl_xor_sync(0xffffffffu, v0, 2);
            v1 += __shfl_xor_sync(0xffffffffu, v1, 1);
            v1 += __shfl_xor_sync(0xffffffffu, v1, 2);
            if (tig == 0) {
                int rl = wm + mt * 16 + gid;
                q2p[(rl * 2 + hl) * 2 + half]       = v0;
                q2p[((rl + 8) * 2 + hl) * 2 + half] = v1;
            }
        }
        __syncthreads();
        float* dst = (blockIdx.z == 0) ? g_q2 : g_k2;
        if (t < 128) {
            int m = m0 + t;
            int b0i = m >> 10, ns = m & 1023;
            int h0 = n0 >> 6;
            #pragma unroll
            for (int hl2 = 0; hl2 < 2; hl2++) {
                float s = q2p[(t * 2 + hl2) * 2 + 0] + q2p[(t * 2 + hl2) * 2 + 1];
                dst[(size_t)(b0i * Hn + h0 + hl2) * Nseq + ns] = s;
            }
        }
    }
}

// Output projection: g_y = attnout @ Wo + bo + x   (bf16 A, f32 out)
__global__ void __launch_bounds__(256) proj_mma_kernel(
    const float* __restrict__ bo, const float* __restrict__ xres)
{
    extern __shared__ char smraw[];
    float* bs = (float*)(smraw + GBS);
    const int t = threadIdx.x, lane = t & 31, wid = t >> 5;
    const int gid = lane >> 2, tig = lane & 3;
    const int wm = (wid >> 2) * 64, wn = (wid & 3) * 32;
    const int m0 = blockIdx.y * 128, n0 = blockIdx.x * 128;
    if (t < 128) bs[t] = bo[n0 + t];

    float acc[4][4][4];
    gemm_pipe_body(g_attnout, g_wb[3], acc, smraw);

    #pragma unroll
    for (int mt = 0; mt < 4; mt++)
        #pragma unroll
        for (int nt = 0; nt < 4; nt++) {
            int cl = wn + nt * 8 + 2 * tig;
            int n  = n0 + cl;
            int mr = m0 + wm + mt * 16 + gid;
            {
                size_t idx = (size_t)mr * Ddim + n;
                float2 xr = *(const float2*)(xres + idx);
                float2 p = { acc[mt][nt][0] + bs[cl] + xr.x,
                             acc[mt][nt][1] + bs[cl + 1] + xr.y };
                *(float2*)(g_y + idx) = p;
            }
            {
                size_t idx = (size_t)(mr + 8) * Ddim + n;
                float2 xr = *(const float2*)(xres + idx);
                float2 p = { acc[mt][nt][2] + bs[cl] + xr.x,
                             acc[mt][nt][3] + bs[cl + 1] + xr.y };
                *(float2*)(g_y + idx) = p;
            }
        }
}

// ---------------- Fused attention: register-resident P ------------------------
#define FAST 72
#define QS_B   0
#define KS0_B  18432
#define KS1_B  27648
#define VS0_B  36864
#define VS1_B  46080
#define K20_B  55296
#define K21_B  55552
#define FA_SMEM 55808

__global__ void __launch_bounds__(256, 2) fused_attn_kernel()
{
    extern __shared__ char smraw[];
    bf16*  Qs     = (bf16*)(smraw + QS_B);
    bf16*  Ksb[2] = { (bf16*)(smraw + KS0_B), (bf16*)(smraw + KS1_B) };
    bf16*  Vsb[2] = { (bf16*)(smraw + VS0_B), (bf16*)(smraw + VS1_B) };
    float* k2b[2] = { (float*)(smraw + K20_B), (float*)(smraw + K21_B) };

    const int t = threadIdx.x, lane = t & 31, wid = t >> 5;
    const int gid = lane >> 2, tig = lane & 3;
    const int wm = wid * 16;
    const int i0 = blockIdx.x * 128;
    const int bh = blockIdx.y;
    const bf16* Qg = g_q + (size_t)bh * Nseq * DH;
    const bf16* Kg = g_k + (size_t)bh * Nseq * DH;
    const bf16* Vg = g_v + (size_t)bh * Nseq * DH;
    const float* k2g = g_k2 + (size_t)bh * Nseq;

    // prefetch chunk 0 (K, V, k2)
    #pragma unroll
    for (int i = 0; i < 2; i++) {
        int f = t + 256 * i;
        int r = f >> 3, c = (f & 7) * 8;
        cpa16(s2u(Ksb[0] + r * FAST + c), Kg + (size_t)r * DH + c);
        cpa16(s2u(Vsb[0] + r * FAST + c), Vg + (size_t)r * DH + c);
    }
    if (t < 16) cpa16(s2u(k2b[0] + t * 4), k2g + t * 4);
    CP_COMMIT();

    // load Q tile (plain stores; first chunk's sync orders them)
    #pragma unroll
    for (int i = 0; i < 4; i++) {
        int f = t + 256 * i;
        int r = f >> 3, c = (f & 7) * 8;
        *(uint4*)(Qs + r * FAST + c) = *(const uint4*)(Qg + (size_t)(i0 + r) * DH + c);
    }
    const float q2a = g_q2[(size_t)bh * Nseq + i0 + wm + gid];
    const float q2b = g_q2[(size_t)bh * Nseq + i0 + wm + gid + 8];

    float oacc[8][4];
    #pragma unroll
    for (int nt = 0; nt < 8; nt++)
        #pragma unroll
        for (int c = 0; c < 4; c++) oacc[nt][c] = 0.f;
    float rs0 = 0.f, rs1 = 0.f;

    for (int jc = 0; jc < 16; jc++) {
        bf16*  Ks  = Ksb[jc & 1];
        bf16*  Vs  = Vsb[jc & 1];
        float* k2c = k2b[jc & 1];
        CP_WAIT0();
        __syncthreads();   // chunk data visible; all warps done with other buffer
        if (jc < 15) {
            int j1 = (jc + 1) * 64;
            bf16*  Kn  = Ksb[(jc + 1) & 1];
            bf16*  Vn  = Vsb[(jc + 1) & 1];
            float* k2n = k2b[(jc + 1) & 1];
            #pragma unroll
            for (int i = 0; i < 2; i++) {
                int f = t + 256 * i;
                int r = f >> 3, c = (f & 7) * 8;
                cpa16(s2u(Kn + r * FAST + c), Kg + (size_t)(j1 + r) * DH + c);
                cpa16(s2u(Vn + r * FAST + c), Vg + (size_t)(j1 + r) * DH + c);
            }
            if (t < 16) cpa16(s2u(k2n + t * 4), k2g + j1 + t * 4);
            CP_COMMIT();
        }

        // S = Q @ K^T : warp tile 16 rows x 64 keys
        float sacc[8][4];
        #pragma unroll
        for (int nt = 0; nt < 8; nt++)
            #pragma unroll
            for (int c = 0; c < 4; c++) sacc[nt][c] = 0.f;
        #pragma unroll
        for (int ks = 0; ks < 4; ks++) {
            int kk = ks * 16;
            u32 a[4];
            ldsm4(a, aaddr(Qs, FAST, wm, kk, lane));
            #pragma unroll
            for (int p = 0; p < 4; p++) {
                u32 bb[4];
                ldsm4(bb, baddr_k(Ks, FAST, 16 * p, kk, lane));
                mma16(sacc[2*p],     a, &bb[0]);
                mma16(sacc[2*p + 1], a, &bb[2]);
            }
        }

        // epilogue: P = exp(-sqrt.approx(dist)) directly into PV A-fragments
        u32 pa[4][4];
        #pragma unroll
        for (int nt = 0; nt < 8; nt++) {
            int cl = nt * 8 + 2 * tig;
            float k2a = k2c[cl], k2b2 = k2c[cl + 1];
            float d0 = fmaxf(fmaf(-2.f, sacc[nt][0], q2a + k2a),  0.f) + 1e-8f;
            float d1 = fmaxf(fmaf(-2.f, sacc[nt][1], q2a + k2b2), 0.f) + 1e-8f;
            float d2 = fmaxf(fmaf(-2.f, sacc[nt][2], q2b + k2a),  0.f) + 1e-8f;
            float d3 = fmaxf(fmaf(-2.f, sacc[nt][3], q2b + k2b2), 0.f) + 1e-8f;
            float p0 = __expf(-sqrt_ap(d0));
            float p1 = __expf(-sqrt_ap(d1));
            float p2 = __expf(-sqrt_ap(d2));
            float p3 = __expf(-sqrt_ap(d3));
            rs0 += p0 + p1;
            rs1 += p2 + p3;
            bf162 w01 = __floats2bfloat162_rn(p0, p1);
            bf162 w23 = __floats2bfloat162_rn(p2, p3);
            if ((nt & 1) == 0) { pa[nt >> 1][0] = *(u32*)&w01; pa[nt >> 1][1] = *(u32*)&w23; }
            else               { pa[nt >> 1][2] = *(u32*)&w01; pa[nt >> 1][3] = *(u32*)&w23; }
        }

        // O += P @ V : A from registers, B = V via ldmatrix.trans
        #pragma unroll
        for (int k4 = 0; k4 < 4; k4++) {
            int kk = k4 * 16;
            #pragma unroll
            for (int p = 0; p < 4; p++) {
                u32 bb[4];
                ldsm4t(bb, baddr_t(Vs, FAST, kk, 16 * p, lane));
                mma16(oacc[2*p],     pa[k4], &bb[0]);
                mma16(oacc[2*p + 1], pa[k4], &bb[2]);
            }
        }
    }

    // quad-reduce row sums (cols split across tig only)
    rs0 += __shfl_xor_sync(0xffffffffu, rs0, 1);
    rs0 += __shfl_xor_sync(0xffffffffu, rs0, 2);
    rs1 += __shfl_xor_sync(0xffffffffu, rs1, 1);
    rs1 += __shfl_xor_sync(0xffffffffu, rs1, 2);
    float li0 = 1.0f / rs0;
    float li1 = 1.0f / rs1;

    const int b = bh >> 3, h = bh & 7;
    const int i = i0 + wm + gid;
    #pragma unroll
    for (int nt = 0; nt < 8; nt++) {
        int dh = nt * 8 + 2 * tig;
        bf162 w0 = __floats2bfloat162_rn(oacc[nt][0] * li0, oacc[nt][1] * li0);
        bf162 w1 = __floats2bfloat162_rn(oacc[nt][2] * li1, oacc[nt][3] * li1);
        *(u32*)(g_attnout + ((size_t)(b * Nseq + i) * Ddim + h * DH + dh)) = *(u32*)&w0;
        *(u32*)(g_attnout + ((size_t)(b * Nseq + i + 8) * Ddim + h * DH + dh)) = *(u32*)&w1;
    }
}

// ---------------- launch ------------------------------------------------------
extern "C" void kernel_launch(void* const* d_in, const int* in_sizes, int n_in,
                              void* d_out, int out_size)
{
    const float* x = nullptr;
    const float* Wm[4] = {nullptr, nullptr, nullptr, nullptr};
    const float* vec[8] = {nullptr};
    int nm = 0, nv = 0;
    for (int i = 0; i < n_in; i++) {
        if (in_sizes[i] == BN_ROWS * Ddim)      x = (const float*)d_in[i];
        else if (in_sizes[i] == Ddim * Ddim)    { if (nm < 4) Wm[nm++] = (const float*)d_in[i]; }
        else if (in_sizes[i] == Ddim)           { if (nv < 8) vec[nv++] = (const float*)d_in[i]; }
    }
    const float *bq = vec[0], *bk = vec[1], *bv = vec[2], *bo = vec[3];
    const float *ln1g = vec[4], *ln1b = vec[5], *ln2g = vec[6], *ln2b = vec[7];

    void *p_h = nullptr, *p_y = nullptr;
    cudaGetSymbolAddress(&p_h, g_h);
    cudaGetSymbolAddress(&p_y, g_y);

    cudaFuncSetAttribute(fused_attn_kernel,
                         cudaFuncAttributeMaxDynamicSharedMemorySize, FA_SMEM);
    cudaFuncSetAttribute(qkv_mma_kernel,
                         cudaFuncAttributeMaxDynamicSharedMemorySize, GEMM_SMEM);
    cudaFuncSetAttribute(proj_mma_kernel,
                         cudaFuncAttributeMaxDynamicSharedMemorySize, GEMM_SMEM);

    wconv_kernel<<<dim3(256, 4), 256>>>(Wm[0], Wm[1], Wm[2], Wm[3]);
    ln_bf16_kernel<<<BN_ROWS / 8, 256>>>(x, ln1g, ln1b, (bf16*)p_h);
    qkv_mma_kernel<<<dim3(Ddim / 128, BN_ROWS / 128, 3), 256, GEMM_SMEM>>>(bq, bk, bv);
    fused_attn_kernel<<<dim3(Nseq / 128, NBH), 256, FA_SMEM>>>();
    proj_mma_kernel<<<dim3(Ddim / 128, BN_ROWS / 128), 256, GEMM_SMEM>>>(bo, x);
    ln_f32_kernel<<<BN_ROWS / 8, 256>>>((const float*)p_y, ln2g, ln2b, (float*)d_out);
}

// round 14
// speedup vs baseline: 8.5643x; 1.0456x over previous
#include <cuda_runtime.h>
#include <cuda_bf16.h>
#include <stdint.h>
#include <cstdint>
#include <math.h>

#define Bdim 8
#define Nseq 1024
#define Ddim 512
#define Hn 8
#define DH 64
#define BN_ROWS (Bdim * Nseq)   // 8192
#define NBH (Bdim * Hn)         // 64
#define HROWS (NBH * Nseq)      // 65536 head-rows of DH

#define L2E2 2.0813689810056077f        // (log2 e)^2
#define NEG2L2 (-2.0f * L2E2)
#define EPS_SC (1e-8f * L2E2)

typedef unsigned int u32;
typedef __nv_bfloat16 bf16;
typedef __nv_bfloat162 bf162;

// ---------------- scratch (device globals; no allocation allowed) ------------
__device__ bf16  g_h[BN_ROWS * Ddim];        // LN1 output (bf16)
__device__ bf16  g_q[BN_ROWS * Ddim];        // [BH, N, DH] bf16
__device__ bf16  g_k[BN_ROWS * Ddim];
__device__ bf16  g_v[BN_ROWS * Ddim];
__device__ bf16  g_attnout[BN_ROWS * Ddim];  // [B, N, D] bf16
__device__ float g_y[BN_ROWS * Ddim];        // proj + residual, pre-LN2 (f32)
__device__ bf16  g_wb[4][Ddim * Ddim];       // bf16 copies of Wq,Wk,Wv,Wo
__device__ float g_q2[HROWS];                // ||q||^2 * L2E2 per head-row
__device__ float g_k2[HROWS];                // ||k||^2 * L2E2 per head-row

// ---------------- helpers -----------------------------------------------------
__device__ __forceinline__ u32 s2u(const void* p) {
    u32 a;
    asm("{ .reg .u64 t; cvta.to.shared.u64 t, %1; cvt.u32.u64 %0, t; }" : "=r"(a) : "l"(p));
    return a;
}
__device__ __forceinline__ void cpa16(u32 smem, const void* g) {
    asm volatile("cp.async.cg.shared.global [%0],[%1],16;" :: "r"(smem), "l"(g));
}
#define CP_COMMIT() asm volatile("cp.async.commit_group;")
#define CP_WAIT0()  asm volatile("cp.async.wait_group 0;")

__device__ __forceinline__ void ldsm4(u32* r, u32 addr) {
    asm volatile("ldmatrix.sync.aligned.m8n8.x4.shared.b16 {%0,%1,%2,%3},[%4];"
                 : "=r"(r[0]), "=r"(r[1]), "=r"(r[2]), "=r"(r[3]) : "r"(addr));
}
__device__ __forceinline__ void ldsm4t(u32* r, u32 addr) {
    asm volatile("ldmatrix.sync.aligned.m8n8.x4.trans.shared.b16 {%0,%1,%2,%3},[%4];"
                 : "=r"(r[0]), "=r"(r[1]), "=r"(r[2]), "=r"(r[3]) : "r"(addr));
}
__device__ __forceinline__ void mma16(float* c, const u32* a, const u32* b) {
    asm volatile(
        "mma.sync.aligned.m16n8k16.row.col.f32.bf16.bf16.f32 "
        "{%0,%1,%2,%3},{%4,%5,%6,%7},{%8,%9},{%0,%1,%2,%3};\n"
        : "+f"(c[0]), "+f"(c[1]), "+f"(c[2]), "+f"(c[3])
        : "r"(a[0]), "r"(a[1]), "r"(a[2]), "r"(a[3]), "r"(b[0]), "r"(b[1]));
}
__device__ __forceinline__ u32 aaddr(const bf16* base, int stride, int mm, int k, int lane) {
    int row = mm + (lane & 7) + (((lane >> 3) & 1) << 3);
    int col = k + ((lane >> 4) << 3);
    return s2u(base + row * stride + col);
}
__device__ __forceinline__ u32 baddr_k(const bf16* base, int stride, int n, int k, int lane) {
    int m = lane >> 3;
    int row = n + ((m >> 1) << 3) + (lane & 7);
    int col = k + ((m & 1) << 3);
    return s2u(base + row * stride + col);
}
__device__ __forceinline__ u32 baddr_t(const bf16* base, int stride, int k, int n, int lane) {
    int m = lane >> 3;
    int row = k + ((m & 1) << 3) + (lane & 7);
    int col = n + ((m >> 1) << 3);
    return s2u(base + row * stride + col);
}
__device__ __forceinline__ float2 b2f(u32 u) {
    bf162 h = *(bf162*)&u;
    return __bfloat1622float2(h);
}
__device__ __forceinline__ float sqrt_ap(float x) {
    float y;
    asm("sqrt.approx.f32 %0, %1;" : "=f"(y) : "f"(x));
    return y;
}
__device__ __forceinline__ float ex2_ap(float x) {
    float y;
    asm("ex2.approx.ftz.f32 %0, %1;" : "=f"(y) : "f"(x));
    return y;
}

// ---------------- weight f32->bf16 conversion ---------------------------------
__global__ void wconv_kernel(const float* __restrict__ w0, const float* __restrict__ w1,
                             const float* __restrict__ w2, const float* __restrict__ w3)
{
    const float* src = (blockIdx.y == 0) ? w0 : (blockIdx.y == 1) ? w1
                      : (blockIdx.y == 2) ? w2 : w3;
    bf16* dst = g_wb[blockIdx.y];
    int i = blockIdx.x * 256 + threadIdx.x;
    float4 v = ((const float4*)src)[i];
    bf162 lo = __floats2bfloat162_rn(v.x, v.y);
    bf162 hi = __floats2bfloat162_rn(v.z, v.w);
    uint2 pk = { *(u32*)&lo, *(u32*)&hi };
    ((uint2*)dst)[i] = pk;
}

// ---------------- LayerNorm: one WARP per row, shuffle-only reduction ----------
__device__ __forceinline__ void ln_warp_body(const float* __restrict__ in,
                                             const float* __restrict__ gamma,
                                             const float* __restrict__ beta,
                                             int row, int lane, float4 o[4])
{
    const float4* r = (const float4*)(in + (size_t)row * Ddim);
    float4 a[4];
    float s = 0.f, s2 = 0.f;
    #pragma unroll
    for (int i = 0; i < 4; i++) {
        a[i] = r[i * 32 + lane];
        s  += a[i].x + a[i].y + a[i].z + a[i].w;
        s2 += a[i].x*a[i].x + a[i].y*a[i].y + a[i].z*a[i].z + a[i].w*a[i].w;
    }
    #pragma unroll
    for (int off = 16; off; off >>= 1) {
        s  += __shfl_xor_sync(0xffffffffu, s,  off);
        s2 += __shfl_xor_sync(0xffffffffu, s2, off);
    }
    float mean = s * (1.0f / Ddim);
    float var  = s2 * (1.0f / Ddim) - mean * mean;
    float rstd = rsqrtf(var + 1e-5f);
    #pragma unroll
    for (int i = 0; i < 4; i++) {
        float4 g = ((const float4*)gamma)[i * 32 + lane];
        float4 b = ((const float4*)beta)[i * 32 + lane];
        o[i].x = (a[i].x - mean) * rstd * g.x + b.x;
        o[i].y = (a[i].y - mean) * rstd * g.y + b.y;
        o[i].z = (a[i].z - mean) * rstd * g.z + b.z;
        o[i].w = (a[i].w - mean) * rstd * g.w + b.w;
    }
}

__global__ void __launch_bounds__(256) ln_bf16_kernel(
    const float* __restrict__ in, const float* __restrict__ gamma,
    const float* __restrict__ beta, bf16* __restrict__ out)
{
    int lane = threadIdx.x & 31;
    int row = blockIdx.x * 8 + (threadIdx.x >> 5);
    float4 o[4];
    ln_warp_body(in, gamma, beta, row, lane, o);
    #pragma unroll
    for (int i = 0; i < 4; i++) {
        bf162 lo = __floats2bfloat162_rn(o[i].x, o[i].y);
        bf162 hi = __floats2bfloat162_rn(o[i].z, o[i].w);
        uint2 pk = { *(u32*)&lo, *(u32*)&hi };
        *(uint2*)(out + (size_t)row * Ddim + (i * 32 + lane) * 4) = pk;
    }
}

__global__ void __launch_bounds__(256) ln_f32_kernel(
    const float* __restrict__ in, const float* __restrict__ gamma,
    const float* __restrict__ beta, float* __restrict__ out)
{
    int lane = threadIdx.x & 31;
    int row = blockIdx.x * 8 + (threadIdx.x >> 5);
    float4 o[4];
    ln_warp_body(in, gamma, beta, row, lane, o);
    #pragma unroll
    for (int i = 0; i < 4; i++)
        ((float4*)(out + (size_t)row * Ddim))[i * 32 + lane] = o[i];
}

// ---------------- bf16 MMA GEMM core, cp.async double-buffered ----------------
#define AST 72
#define WST 136
#define GAS0 0
#define GAS1 18432
#define GWS0 36864
#define GWS1 54272
#define GBS  71680
#define Q2P  72192     // [128 rows][2 heads][2 halves] f32 = 2048 B
#define GEMM_SMEM 74240

__device__ __forceinline__ void gemm_load_stage(const bf16* __restrict__ A,
                                                const bf16* __restrict__ W,
                                                bf16* As, bf16* Ws,
                                                int m0, int n0, int k0, int t)
{
    #pragma unroll
    for (int i = 0; i < 4; i++) {
        int f = t + 256 * i;
        int r = f >> 3, c = (f & 7) * 8;
        cpa16(s2u(As + r * AST + c), A + (size_t)(m0 + r) * Ddim + k0 + c);
    }
    #pragma unroll
    for (int i = 0; i < 4; i++) {
        int f = t + 256 * i;
        int r = f >> 4, c = (f & 15) * 8;
        cpa16(s2u(Ws + r * WST + c), W + (size_t)(k0 + r) * Ddim + n0 + c);
    }
    CP_COMMIT();
}

__device__ __forceinline__ void gemm_pipe_body(const bf16* __restrict__ A,
                                               const bf16* __restrict__ W,
                                               float acc[4][4][4],
                                               char* smraw)
{
    bf16* Asb[2] = { (bf16*)(smraw + GAS0), (bf16*)(smraw + GAS1) };
    bf16* Wsb[2] = { (bf16*)(smraw + GWS0), (bf16*)(smraw + GWS1) };
    const int t = threadIdx.x, lane = t & 31, wid = t >> 5;
    const int wm = (wid >> 2) * 64, wn = (wid & 3) * 32;
    const int m0 = blockIdx.y * 128, n0 = blockIdx.x * 128;

    #pragma unroll
    for (int i = 0; i < 4; i++)
        #pragma unroll
        for (int j = 0; j < 4; j++)
            #pragma unroll
            for (int c = 0; c < 4; c++) acc[i][j][c] = 0.f;

    gemm_load_stage(A, W, Asb[0], Wsb[0], m0, n0, 0, t);

    for (int kc = 0; kc < 8; kc++) {
        bf16* As = Asb[kc & 1];
        bf16* Ws = Wsb[kc & 1];
        CP_WAIT0();
        __syncthreads();
        if (kc < 7)
            gemm_load_stage(A, W, Asb[(kc + 1) & 1], Wsb[(kc + 1) & 1],
                            m0, n0, (kc + 1) * 64, t);
        #pragma unroll
        for (int ks = 0; ks < 4; ks++) {
            int kk = ks * 16;
            u32 a[4][4], b[4][2];
            #pragma unroll
            for (int mt = 0; mt < 4; mt++)
                ldsm4(a[mt], aaddr(As, AST, wm + mt * 16, kk, lane));
            #pragma unroll
            for (int p = 0; p < 2; p++) {
                u32 bb[4];
                ldsm4t(bb, baddr_t(Ws, WST, kk, wn + 16 * p, lane));
                b[2*p][0] = bb[0]; b[2*p][1] = bb[1];
                b[2*p+1][0] = bb[2]; b[2*p+1][1] = bb[3];
            }
            #pragma unroll
            for (int mt = 0; mt < 4; mt++)
                #pragma unroll
                for (int nt = 0; nt < 4; nt++) mma16(acc[mt][nt], a[mt], b[nt]);
        }
    }
}

// QKV: z picks {q,k,v}; bf16 output in [BH, N, DH] layout, bias fused.
// For z<2 the epilogue also computes exact per-head-row ||.||^2 * L2E2.
__global__ void __launch_bounds__(256) qkv_mma_kernel(
    const float* __restrict__ bq, const float* __restrict__ bk,
    const float* __restrict__ bv)
{
    extern __shared__ char smraw[];
    float* bs  = (float*)(smraw + GBS);
    float* q2p = (float*)(smraw + Q2P);   // [row][head_local][half]
    const bf16* W = g_wb[blockIdx.z];
    const float* bias = (blockIdx.z == 0) ? bq : (blockIdx.z == 1) ? bk : bv;
    bf16* O = (blockIdx.z == 0) ? g_q : (blockIdx.z == 1) ? g_k : g_v;

    const int t = threadIdx.x, lane = t & 31, wid = t >> 5;
    const int gid = lane >> 2, tig = lane & 3;
    const int wm = (wid >> 2) * 64, wn = (wid & 3) * 32;
    const int m0 = blockIdx.y * 128, n0 = blockIdx.x * 128;
    if (t < 128) bs[t] = bias[n0 + t];

    float acc[4][4][4];
    gemm_pipe_body(g_h, W, acc, smraw);

    float rp[4][2];
    #pragma unroll
    for (int mt = 0; mt < 4; mt++) { rp[mt][0] = 0.f; rp[mt][1] = 0.f; }

    #pragma unroll
    for (int mt = 0; mt < 4; mt++)
        #pragma unroll
        for (int nt = 0; nt < 4; nt++) {
            int cl = wn + nt * 8 + 2 * tig;
            int n  = n0 + cl;
            int h  = n >> 6, dh = n & 63;
            int mr = m0 + wm + mt * 16 + gid;
            {
                int b0i = mr >> 10, ns = mr & 1023;
                bf162 v = __floats2bfloat162_rn(acc[mt][nt][0] + bs[cl],
                                                acc[mt][nt][1] + bs[cl + 1]);
                *(u32*)(O + (((size_t)(b0i * Hn + h) * Nseq + ns) * DH + dh)) = *(u32*)&v;
                float2 f = b2f(*(u32*)&v);
                rp[mt][0] += f.x * f.x + f.y * f.y;
            }
            {
                int mr2 = mr + 8;
                int b0i = mr2 >> 10, ns = mr2 & 1023;
                bf162 v = __floats2bfloat162_rn(acc[mt][nt][2] + bs[cl],
                                                acc[mt][nt][3] + bs[cl + 1]);
                *(u32*)(O + (((size_t)(b0i * Hn + h) * Nseq + ns) * DH + dh)) = *(u32*)&v;
                float2 f = b2f(*(u32*)&v);
                rp[mt][1] += f.x * f.x + f.y * f.y;
            }
        }

    if (blockIdx.z < 2) {
        int hl = wn >> 6, half = (wn >> 5) & 1;
        #pragma unroll
        for (int mt = 0; mt < 4; mt++) {
            float v0 = rp[mt][0], v1 = rp[mt][1];
            v0 += __shfl_xor_sync(0xffffffffu, v0, 1);
            v0 += __shfl_xor_sync(0xffffffffu, v0, 2);
            v1 += __shfl_xor_sync(0xffffffffu, v1, 1);
            v1 += __shfl_xor_sync(0xffffffffu, v1, 2);
            if (tig == 0) {
                int rl = wm + mt * 16 + gid;
                q2p[(rl * 2 + hl) * 2 + half]       = v0;
                q2p[((rl + 8) * 2 + hl) * 2 + half] = v1;
            }
        }
        __syncthreads();
        float* dst = (blockIdx.z == 0) ? g_q2 : g_k2;
        if (t < 128) {
            int m = m0 + t;
            int b0i = m >> 10, ns = m & 1023;
            int h0 = n0 >> 6;
            #pragma unroll
            for (int hl2 = 0; hl2 < 2; hl2++) {
                float s = (q2p[(t * 2 + hl2) * 2 + 0] + q2p[(t * 2 + hl2) * 2 + 1]) * L2E2;
                dst[(size_t)(b0i * Hn + h0 + hl2) * Nseq + ns] = s;
            }
        }
    }
}

// Output projection: g_y = attnout @ Wo + bo + x   (bf16 A, f32 out)
__global__ void __launch_bounds__(256) proj_mma_kernel(
    const float* __restrict__ bo, const float* __restrict__ xres)
{
    extern __shared__ char smraw[];
    float* bs = (float*)(smraw + GBS);
    const int t = threadIdx.x, lane = t & 31, wid = t >> 5;
    const int gid = lane >> 2, tig = lane & 3;
    const int wm = (wid >> 2) * 64, wn = (wid & 3) * 32;
    const int m0 = blockIdx.y * 128, n0 = blockIdx.x * 128;
    if (t < 128) bs[t] = bo[n0 + t];

    float acc[4][4][4];
    gemm_pipe_body(g_attnout, g_wb[3], acc, smraw);

    #pragma unroll
    for (int mt = 0; mt < 4; mt++)
        #pragma unroll
        for (int nt = 0; nt < 4; nt++) {
            int cl = wn + nt * 8 + 2 * tig;
            int n  = n0 + cl;
            int mr = m0 + wm + mt * 16 + gid;
            {
                size_t idx = (size_t)mr * Ddim + n;
                float2 xr = *(const float2*)(xres + idx);
                float2 p = { acc[mt][nt][0] + bs[cl] + xr.x,
                             acc[mt][nt][1] + bs[cl + 1] + xr.y };
                *(float2*)(g_y + idx) = p;
            }
            {
                size_t idx = (size_t)(mr + 8) * Ddim + n;
                float2 xr = *(const float2*)(xres + idx);
                float2 p = { acc[mt][nt][2] + bs[cl] + xr.x,
                             acc[mt][nt][3] + bs[cl + 1] + xr.y };
                *(float2*)(g_y + idx) = p;
            }
        }
}

// ---------------- Fused attention: register-resident P ------------------------
// p = exp(-sqrt(d)) = 2^(-sqrt(d * L2E2)); q2/k2 pre-scaled by L2E2, so
// d' = fma(-2*L2E2, s, q2'+k2'), clamp to EPS_SC, p = ex2(-sqrt_ap(d')).
#define FAST 72
#define QS_B   0
#define KS0_B  18432
#define KS1_B  27648
#define VS0_B  36864
#define VS1_B  46080
#define K20_B  55296
#define K21_B  55552
#define FA_SMEM 55808

__global__ void __launch_bounds__(256, 2) fused_attn_kernel()
{
    extern __shared__ char smraw[];
    bf16*  Qs     = (bf16*)(smraw + QS_B);
    bf16*  Ksb[2] = { (bf16*)(smraw + KS0_B), (bf16*)(smraw + KS1_B) };
    bf16*  Vsb[2] = { (bf16*)(smraw + VS0_B), (bf16*)(smraw + VS1_B) };
    float* k2b[2] = { (float*)(smraw + K20_B), (float*)(smraw + K21_B) };

    const int t = threadIdx.x, lane = t & 31, wid = t >> 5;
    const int gid = lane >> 2, tig = lane & 3;
    const int wm = wid * 16;
    const int i0 = blockIdx.x * 128;
    const int bh = blockIdx.y;
    const bf16* Qg = g_q + (size_t)bh * Nseq * DH;
    const bf16* Kg = g_k + (size_t)bh * Nseq * DH;
    const bf16* Vg = g_v + (size_t)bh * Nseq * DH;
    const float* k2g = g_k2 + (size_t)bh * Nseq;

    // prefetch chunk 0 (K, V, k2)
    #pragma unroll
    for (int i = 0; i < 2; i++) {
        int f = t + 256 * i;
        int r = f >> 3, c = (f & 7) * 8;
        cpa16(s2u(Ksb[0] + r * FAST + c), Kg + (size_t)r * DH + c);
        cpa16(s2u(Vsb[0] + r * FAST + c), Vg + (size_t)r * DH + c);
    }
    if (t < 16) cpa16(s2u(k2b[0] + t * 4), k2g + t * 4);
    CP_COMMIT();

    // load Q tile (plain stores; first chunk's sync orders them)
    #pragma unroll
    for (int i = 0; i < 4; i++) {
        int f = t + 256 * i;
        int r = f >> 3, c = (f & 7) * 8;
        *(uint4*)(Qs + r * FAST + c) = *(const uint4*)(Qg + (size_t)(i0 + r) * DH + c);
    }
    const float q2a = g_q2[(size_t)bh * Nseq + i0 + wm + gid];
    const float q2b = g_q2[(size_t)bh * Nseq + i0 + wm + gid + 8];

    float oacc[8][4];
    #pragma unroll
    for (int nt = 0; nt < 8; nt++)
        #pragma unroll
        for (int c = 0; c < 4; c++) oacc[nt][c] = 0.f;
    float rs0 = 0.f, rs1 = 0.f;

    for (int jc = 0; jc < 16; jc++) {
        bf16*  Ks  = Ksb[jc & 1];
        bf16*  Vs  = Vsb[jc & 1];
        float* k2c = k2b[jc & 1];
        CP_WAIT0();
        __syncthreads();   // chunk data visible; all warps done with other buffer
        if (jc < 15) {
            int j1 = (jc + 1) * 64;
            bf16*  Kn  = Ksb[(jc + 1) & 1];
            bf16*  Vn  = Vsb[(jc + 1) & 1];
            float* k2n = k2b[(jc + 1) & 1];
            #pragma unroll
            for (int i = 0; i < 2; i++) {
                int f = t + 256 * i;
                int r = f >> 3, c = (f & 7) * 8;
                cpa16(s2u(Kn + r * FAST + c), Kg + (size_t)(j1 + r) * DH + c);
                cpa16(s2u(Vn + r * FAST + c), Vg + (size_t)(j1 + r) * DH + c);
            }
            if (t < 16) cpa16(s2u(k2n + t * 4), k2g + j1 + t * 4);
            CP_COMMIT();
        }

        // S = Q @ K^T : warp tile 16 rows x 64 keys
        float sacc[8][4];
        #pragma unroll
        for (int nt = 0; nt < 8; nt++)
            #pragma unroll
            for (int c = 0; c < 4; c++) sacc[nt][c] = 0.f;
        #pragma unroll
        for (int ks = 0; ks < 4; ks++) {
            int kk = ks * 16;
            u32 a[4];
            ldsm4(a, aaddr(Qs, FAST, wm, kk, lane));
            #pragma unroll
            for (int p = 0; p < 4; p++) {
                u32 bb[4];
                ldsm4(bb, baddr_k(Ks, FAST, 16 * p, kk, lane));
                mma16(sacc[2*p],     a, &bb[0]);
                mma16(sacc[2*p + 1], a, &bb[2]);
            }
        }

        // epilogue: P = ex2(-sqrt(d')) directly into PV A-fragments
        u32 pa[4][4];
        #pragma unroll
        for (int nt = 0; nt < 8; nt++) {
            int cl = nt * 8 + 2 * tig;
            float k2a = k2c[cl], k2b2 = k2c[cl + 1];
            float d0 = fmaxf(fmaf(NEG2L2, sacc[nt][0], q2a + k2a),  EPS_SC);
            float d1 = fmaxf(fmaf(NEG2L2, sacc[nt][1], q2a + k2b2), EPS_SC);
            float d2 = fmaxf(fmaf(NEG2L2, sacc[nt][2], q2b + k2a),  EPS_SC);
            float d3 = fmaxf(fmaf(NEG2L2, sacc[nt][3], q2b + k2b2), EPS_SC);
            float p0 = ex2_ap(-sqrt_ap(d0));
            float p1 = ex2_ap(-sqrt_ap(d1));
            float p2 = ex2_ap(-sqrt_ap(d2));
            float p3 = ex2_ap(-sqrt_ap(d3));
            rs0 += p0 + p1;
            rs1 += p2 + p3;
            bf162 w01 = __floats2bfloat162_rn(p0, p1);
            bf162 w23 = __floats2bfloat162_rn(p2, p3);
            if ((nt & 1) == 0) { pa[nt >> 1][0] = *(u32*)&w01; pa[nt >> 1][1] = *(u32*)&w23; }
            else               { pa[nt >> 1][2] = *(u32*)&w01; pa[nt >> 1][3] = *(u32*)&w23; }
        }

        // O += P @ V : A from registers, B = V via ldmatrix.trans
        #pragma unroll
        for (int k4 = 0; k4 < 4; k4++) {
            int kk = k4 * 16;
            #pragma unroll
            for (int p = 0; p < 4; p++) {
                u32 bb[4];
                ldsm4t(bb, baddr_t(Vs, FAST, kk, 16 * p, lane));
                mma16(oacc[2*p],     pa[k4], &bb[0]);
                mma16(oacc[2*p + 1], pa[k4], &bb[2]);
            }
        }
    }

    // quad-reduce row sums (cols split across tig only)
    rs0 += __shfl_xor_sync(0xffffffffu, rs0, 1);
    rs0 += __shfl_xor_sync(0xffffffffu, rs0, 2);
    rs1 += __shfl_xor_sync(0xffffffffu, rs1, 1);
    rs1 += __shfl_xor_sync(0xffffffffu, rs1, 2);
    float li0 = 1.0f / rs0;
    float li1 = 1.0f / rs1;

    const int b = bh >> 3, h = bh & 7;
    const int i = i0 + wm + gid;
    #pragma unroll
    for (int nt = 0; nt < 8; nt++) {
        int dh = nt * 8 + 2 * tig;
        bf162 w0 = __floats2bfloat162_rn(oacc[nt][0] * li0, oacc[nt][1] * li0);
        bf162 w1 = __floats2bfloat162_rn(oacc[nt][2] * li1, oacc[nt][3] * li1);
        *(u32*)(g_attnout + ((size_t)(b * Nseq + i) * Ddim + h * DH + dh)) = *(u32*)&w0;
        *(u32*)(g_attnout + ((size_t)(b * Nseq + i + 8) * Ddim + h * DH + dh)) = *(u32*)&w1;
    }
}

// ---------------- launch ------------------------------------------------------
extern "C" void kernel_launch(void* const* d_in, const int* in_sizes, int n_in,
                              void* d_out, int out_size)
{
    const float* x = nullptr;
    const float* Wm[4] = {nullptr, nullptr, nullptr, nullptr};
    const float* vec[8] = {nullptr};
    int nm = 0, nv = 0;
    for (int i = 0; i < n_in; i++) {
        if (in_sizes[i] == BN_ROWS * Ddim)      x = (const float*)d_in[i];
        else if (in_sizes[i] == Ddim * Ddim)    { if (nm < 4) Wm[nm++] = (const float*)d_in[i]; }
        else if (in_sizes[i] == Ddim)           { if (nv < 8) vec[nv++] = (const float*)d_in[i]; }
    }
    const float *bq = vec[0], *bk = vec[1], *bv = vec[2], *bo = vec[3];
    const float *ln1g = vec[4], *ln1b = vec[5], *ln2g = vec[6], *ln2b = vec[7];

    void *p_h = nullptr, *p_y = nullptr;
    cudaGetSymbolAddress(&p_h, g_h);
    cudaGetSymbolAddress(&p_y, g_y);

    cudaFuncSetAttribute(fused_attn_kernel,
                         cudaFuncAttributeMaxDynamicSharedMemorySize, FA_SMEM);
    cudaFuncSetAttribute(qkv_mma_kernel,
                         cudaFuncAttributeMaxDynamicSharedMemorySize, GEMM_SMEM);
    cudaFuncSetAttribute(proj_mma_kernel,
                         cudaFuncAttributeMaxDynamicSharedMemorySize, GEMM_SMEM);

    wconv_kernel<<<dim3(256, 4), 256>>>(Wm[0], Wm[1], Wm[2], Wm[3]);
    ln_bf16_kernel<<<BN_ROWS / 8, 256>>>(x, ln1g, ln1b, (bf16*)p_h);
    qkv_mma_kernel<<<dim3(Ddim / 128, BN_ROWS / 128, 3), 256, GEMM_SMEM>>>(bq, bk, bv);
    fused_attn_kernel<<<dim3(Nseq / 128, NBH), 256, FA_SMEM>>>();
    proj_mma_kernel<<<dim3(Ddim / 128, BN_ROWS / 128), 256, GEMM_SMEM>>>(bo, x);
    ln_f32_kernel<<<BN_ROWS / 8, 256>>>((const float*)p_y, ln2g, ln2b, (float*)d_out);
}

// round 15
// speedup vs baseline: 8.7726x; 1.0243x over previous
#include <cuda_runtime.h>
#include <cuda_bf16.h>
#include <stdint.h>
#include <cstdint>
#include <math.h>

#define Bdim 8
#define Nseq 1024
#define Ddim 512
#define Hn 8
#define DH 64
#define BN_ROWS (Bdim * Nseq)   // 8192
#define NBH (Bdim * Hn)         // 64
#define HROWS (NBH * Nseq)      // 65536 head-rows of DH

#define L2E2 2.0813689810056077f        // (log2 e)^2
#define NEG2L2 (-2.0f * L2E2)
#define EPS_SC (1e-8f * L2E2)

typedef unsigned int u32;
typedef __nv_bfloat16 bf16;
typedef __nv_bfloat162 bf162;

// ---------------- scratch (device globals; no allocation allowed) ------------
__device__ bf16  g_h[BN_ROWS * Ddim];        // LN1 output (bf16)
__device__ bf16  g_q[BN_ROWS * Ddim];        // [BH, N, DH] bf16
__device__ bf16  g_k[BN_ROWS * Ddim];
__device__ bf16  g_v[BN_ROWS * Ddim];
__device__ bf16  g_attnout[BN_ROWS * Ddim];  // [B, N, D] bf16
__device__ float g_y[BN_ROWS * Ddim];        // proj + residual, pre-LN2 (f32)
__device__ bf16  g_wb[4][Ddim * Ddim];       // bf16 copies of Wq,Wk,Wv,Wo
__device__ float g_q2[HROWS];                // ||q||^2 * L2E2 per head-row
__device__ float g_k2[HROWS];                // ||k||^2 * L2E2 per head-row

// ---------------- helpers -----------------------------------------------------
__device__ __forceinline__ u32 s2u(const void* p) {
    u32 a;
    asm("{ .reg .u64 t; cvta.to.shared.u64 t, %1; cvt.u32.u64 %0, t; }" : "=r"(a) : "l"(p));
    return a;
}
__device__ __forceinline__ void cpa16(u32 smem, const void* g) {
    asm volatile("cp.async.cg.shared.global [%0],[%1],16;" :: "r"(smem), "l"(g));
}
#define CP_COMMIT() asm volatile("cp.async.commit_group;")
#define CP_WAIT0()  asm volatile("cp.async.wait_group 0;")

__device__ __forceinline__ void ldsm4(u32* r, u32 addr) {
    asm volatile("ldmatrix.sync.aligned.m8n8.x4.shared.b16 {%0,%1,%2,%3},[%4];"
                 : "=r"(r[0]), "=r"(r[1]), "=r"(r[2]), "=r"(r[3]) : "r"(addr));
}
__device__ __forceinline__ void ldsm4t(u32* r, u32 addr) {
    asm volatile("ldmatrix.sync.aligned.m8n8.x4.trans.shared.b16 {%0,%1,%2,%3},[%4];"
                 : "=r"(r[0]), "=r"(r[1]), "=r"(r[2]), "=r"(r[3]) : "r"(addr));
}
__device__ __forceinline__ void mma16(float* c, const u32* a, const u32* b) {
    asm volatile(
        "mma.sync.aligned.m16n8k16.row.col.f32.bf16.bf16.f32 "
        "{%0,%1,%2,%3},{%4,%5,%6,%7},{%8,%9},{%0,%1,%2,%3};\n"
        : "+f"(c[0]), "+f"(c[1]), "+f"(c[2]), "+f"(c[3])
        : "r"(a[0]), "r"(a[1]), "r"(a[2]), "r"(a[3]), "r"(b[0]), "r"(b[1]));
}
__device__ __forceinline__ u32 aaddr(const bf16* base, int stride, int mm, int k, int lane) {
    int row = mm + (lane & 7) + (((lane >> 3) & 1) << 3);
    int col = k + ((lane >> 4) << 3);
    return s2u(base + row * stride + col);
}
__device__ __forceinline__ u32 baddr_k(const bf16* base, int stride, int n, int k, int lane) {
    int m = lane >> 3;
    int row = n + ((m >> 1) << 3) + (lane & 7);
    int col = k + ((m & 1) << 3);
    return s2u(base + row * stride + col);
}
__device__ __forceinline__ u32 baddr_t(const bf16* base, int stride, int k, int n, int lane) {
    int m = lane >> 3;
    int row = k + ((m & 1) << 3) + (lane & 7);
    int col = n + ((m >> 1) << 3);
    return s2u(base + row * stride + col);
}
__device__ __forceinline__ float2 b2f(u32 u) {
    bf162 h = *(bf162*)&u;
    return __bfloat1622float2(h);
}
__device__ __forceinline__ float sqrt_ap(float x) {
    float y;
    asm("sqrt.approx.f32 %0, %1;" : "=f"(y) : "f"(x));
    return y;
}
__device__ __forceinline__ float ex2_ap(float x) {
    float y;
    asm("ex2.approx.ftz.f32 %0, %1;" : "=f"(y) : "f"(x));
    return y;
}

// ---------------- weight f32->bf16 conversion ---------------------------------
__global__ void wconv_kernel(const float* __restrict__ w0, const float* __restrict__ w1,
                             const float* __restrict__ w2, const float* __restrict__ w3)
{
    const float* src = (blockIdx.y == 0) ? w0 : (blockIdx.y == 1) ? w1
                      : (blockIdx.y == 2) ? w2 : w3;
    bf16* dst = g_wb[blockIdx.y];
    int i = blockIdx.x * 256 + threadIdx.x;
    float4 v = ((const float4*)src)[i];
    bf162 lo = __floats2bfloat162_rn(v.x, v.y);
    bf162 hi = __floats2bfloat162_rn(v.z, v.w);
    uint2 pk = { *(u32*)&lo, *(u32*)&hi };
    ((uint2*)dst)[i] = pk;
}

// ---------------- LayerNorm: one WARP per row, shuffle-only reduction ----------
__device__ __forceinline__ void ln_warp_body(const float* __restrict__ in,
                                             const float* __restrict__ gamma,
                                             const float* __restrict__ beta,
                                             int row, int lane, float4 o[4])
{
    const float4* r = (const float4*)(in + (size_t)row * Ddim);
    float4 a[4];
    float s = 0.f, s2 = 0.f;
    #pragma unroll
    for (int i = 0; i < 4; i++) {
        a[i] = r[i * 32 + lane];
        s  += a[i].x + a[i].y + a[i].z + a[i].w;
        s2 += a[i].x*a[i].x + a[i].y*a[i].y + a[i].z*a[i].z + a[i].w*a[i].w;
    }
    #pragma unroll
    for (int off = 16; off; off >>= 1) {
        s  += __shfl_xor_sync(0xffffffffu, s,  off);
        s2 += __shfl_xor_sync(0xffffffffu, s2, off);
    }
    float mean = s * (1.0f / Ddim);
    float var  = s2 * (1.0f / Ddim) - mean * mean;
    float rstd = rsqrtf(var + 1e-5f);
    #pragma unroll
    for (int i = 0; i < 4; i++) {
        float4 g = ((const float4*)gamma)[i * 32 + lane];
        float4 b = ((const float4*)beta)[i * 32 + lane];
        o[i].x = (a[i].x - mean) * rstd * g.x + b.x;
        o[i].y = (a[i].y - mean) * rstd * g.y + b.y;
        o[i].z = (a[i].z - mean) * rstd * g.z + b.z;
        o[i].w = (a[i].w - mean) * rstd * g.w + b.w;
    }
}

__global__ void __launch_bounds__(256) ln_bf16_kernel(
    const float* __restrict__ in, const float* __restrict__ gamma,
    const float* __restrict__ beta, bf16* __restrict__ out)
{
    int lane = threadIdx.x & 31;
    int row = blockIdx.x * 8 + (threadIdx.x >> 5);
    float4 o[4];
    ln_warp_body(in, gamma, beta, row, lane, o);
    #pragma unroll
    for (int i = 0; i < 4; i++) {
        bf162 lo = __floats2bfloat162_rn(o[i].x, o[i].y);
        bf162 hi = __floats2bfloat162_rn(o[i].z, o[i].w);
        uint2 pk = { *(u32*)&lo, *(u32*)&hi };
        *(uint2*)(out + (size_t)row * Ddim + (i * 32 + lane) * 4) = pk;
    }
}

__global__ void __launch_bounds__(256) ln_f32_kernel(
    const float* __restrict__ in, const float* __restrict__ gamma,
    const float* __restrict__ beta, float* __restrict__ out)
{
    int lane = threadIdx.x & 31;
    int row = blockIdx.x * 8 + (threadIdx.x >> 5);
    float4 o[4];
    ln_warp_body(in, gamma, beta, row, lane, o);
    #pragma unroll
    for (int i = 0; i < 4; i++)
        ((float4*)(out + (size_t)row * Ddim))[i * 32 + lane] = o[i];
}

// ---------------- bf16 MMA GEMM core, cp.async double-buffered ----------------
#define AST 72
#define WST 136
#define GAS0 0
#define GAS1 18432
#define GWS0 36864
#define GWS1 54272
#define GBS  71680
#define Q2P  72192     // [128 rows][2 heads][2 halves] f32 = 2048 B
#define GEMM_SMEM 74240

__device__ __forceinline__ void gemm_load_stage(const bf16* __restrict__ A,
                                                const bf16* __restrict__ W,
                                                bf16* As, bf16* Ws,
                                                int m0, int n0, int k0, int t)
{
    #pragma unroll
    for (int i = 0; i < 4; i++) {
        int f = t + 256 * i;
        int r = f >> 3, c = (f & 7) * 8;
        cpa16(s2u(As + r * AST + c), A + (size_t)(m0 + r) * Ddim + k0 + c);
    }
    #pragma unroll
    for (int i = 0; i < 4; i++) {
        int f = t + 256 * i;
        int r = f >> 4, c = (f & 15) * 8;
        cpa16(s2u(Ws + r * WST + c), W + (size_t)(k0 + r) * Ddim + n0 + c);
    }
    CP_COMMIT();
}

__device__ __forceinline__ void gemm_pipe_body(const bf16* __restrict__ A,
                                               const bf16* __restrict__ W,
                                               float acc[4][4][4],
                                               char* smraw)
{
    bf16* Asb[2] = { (bf16*)(smraw + GAS0), (bf16*)(smraw + GAS1) };
    bf16* Wsb[2] = { (bf16*)(smraw + GWS0), (bf16*)(smraw + GWS1) };
    const int t = threadIdx.x, lane = t & 31, wid = t >> 5;
    const int wm = (wid >> 2) * 64, wn = (wid & 3) * 32;
    const int m0 = blockIdx.y * 128, n0 = blockIdx.x * 128;

    #pragma unroll
    for (int i = 0; i < 4; i++)
        #pragma unroll
        for (int j = 0; j < 4; j++)
            #pragma unroll
            for (int c = 0; c < 4; c++) acc[i][j][c] = 0.f;

    gemm_load_stage(A, W, Asb[0], Wsb[0], m0, n0, 0, t);

    for (int kc = 0; kc < 8; kc++) {
        bf16* As = Asb[kc & 1];
        bf16* Ws = Wsb[kc & 1];
        CP_WAIT0();
        __syncthreads();
        if (kc < 7)
            gemm_load_stage(A, W, Asb[(kc + 1) & 1], Wsb[(kc + 1) & 1],
                            m0, n0, (kc + 1) * 64, t);
        #pragma unroll
        for (int ks = 0; ks < 4; ks++) {
            int kk = ks * 16;
            u32 a[4][4], b[4][2];
            #pragma unroll
            for (int mt = 0; mt < 4; mt++)
                ldsm4(a[mt], aaddr(As, AST, wm + mt * 16, kk, lane));
            #pragma unroll
            for (int p = 0; p < 2; p++) {
                u32 bb[4];
                ldsm4t(bb, baddr_t(Ws, WST, kk, wn + 16 * p, lane));
                b[2*p][0] = bb[0]; b[2*p][1] = bb[1];
                b[2*p+1][0] = bb[2]; b[2*p+1][1] = bb[3];
            }
            #pragma unroll
            for (int mt = 0; mt < 4; mt++)
                #pragma unroll
                for (int nt = 0; nt < 4; nt++) mma16(acc[mt][nt], a[mt], b[nt]);
        }
    }
}

// QKV: z picks {q,k,v}; bf16 output in [BH, N, DH] layout, bias fused.
// For z<2 the epilogue also computes exact per-head-row ||.||^2 * L2E2.
__global__ void __launch_bounds__(256) qkv_mma_kernel(
    const float* __restrict__ bq, const float* __restrict__ bk,
    const float* __restrict__ bv)
{
    extern __shared__ char smraw[];
    float* bs  = (float*)(smraw + GBS);
    float* q2p = (float*)(smraw + Q2P);   // [row][head_local][half]
    const bf16* W = g_wb[blockIdx.z];
    const float* bias = (blockIdx.z == 0) ? bq : (blockIdx.z == 1) ? bk : bv;
    bf16* O = (blockIdx.z == 0) ? g_q : (blockIdx.z == 1) ? g_k : g_v;

    const int t = threadIdx.x, lane = t & 31, wid = t >> 5;
    const int gid = lane >> 2, tig = lane & 3;
    const int wm = (wid >> 2) * 64, wn = (wid & 3) * 32;
    const int m0 = blockIdx.y * 128, n0 = blockIdx.x * 128;
    if (t < 128) bs[t] = bias[n0 + t];

    float acc[4][4][4];
    gemm_pipe_body(g_h, W, acc, smraw);

    float rp[4][2];
    #pragma unroll
    for (int mt = 0; mt < 4; mt++) { rp[mt][0] = 0.f; rp[mt][1] = 0.f; }

    #pragma unroll
    for (int mt = 0; mt < 4; mt++)
        #pragma unroll
        for (int nt = 0; nt < 4; nt++) {
            int cl = wn + nt * 8 + 2 * tig;
            int n  = n0 + cl;
            int h  = n >> 6, dh = n & 63;
            int mr = m0 + wm + mt * 16 + gid;
            {
                int b0i = mr >> 10, ns = mr & 1023;
                bf162 v = __floats2bfloat162_rn(acc[mt][nt][0] + bs[cl],
                                                acc[mt][nt][1] + bs[cl + 1]);
                *(u32*)(O + (((size_t)(b0i * Hn + h) * Nseq + ns) * DH + dh)) = *(u32*)&v;
                float2 f = b2f(*(u32*)&v);
                rp[mt][0] += f.x * f.x + f.y * f.y;
            }
            {
                int mr2 = mr + 8;
                int b0i = mr2 >> 10, ns = mr2 & 1023;
                bf162 v = __floats2bfloat162_rn(acc[mt][nt][2] + bs[cl],
                                                acc[mt][nt][3] + bs[cl + 1]);
                *(u32*)(O + (((size_t)(b0i * Hn + h) * Nseq + ns) * DH + dh)) = *(u32*)&v;
                float2 f = b2f(*(u32*)&v);
                rp[mt][1] += f.x * f.x + f.y * f.y;
            }
        }

    if (blockIdx.z < 2) {
        int hl = wn >> 6, half = (wn >> 5) & 1;
        #pragma unroll
        for (int mt = 0; mt < 4; mt++) {
            float v0 = rp[mt][0], v1 = rp[mt][1];
            v0 += __shfl_xor_sync(0xffffffffu, v0, 1);
            v0 += __shfl_xor_sync(0xffffffffu, v0, 2);
            v1 += __shfl_xor_sync(0xffffffffu, v1, 1);
            v1 += __shfl_xor_sync(0xffffffffu, v1, 2);
            if (tig == 0) {
                int rl = wm + mt * 16 + gid;
                q2p[(rl * 2 + hl) * 2 + half]       = v0;
                q2p[((rl + 8) * 2 + hl) * 2 + half] = v1;
            }
        }
        __syncthreads();
        float* dst = (blockIdx.z == 0) ? g_q2 : g_k2;
        if (t < 128) {
            int m = m0 + t;
            int b0i = m >> 10, ns = m & 1023;
            int h0 = n0 >> 6;
            #pragma unroll
            for (int hl2 = 0; hl2 < 2; hl2++) {
                float s = (q2p[(t * 2 + hl2) * 2 + 0] + q2p[(t * 2 + hl2) * 2 + 1]) * L2E2;
                dst[(size_t)(b0i * Hn + h0 + hl2) * Nseq + ns] = s;
            }
        }
    }
}

// Output projection: g_y = attnout @ Wo + bo + x   (bf16 A, f32 out)
__global__ void __launch_bounds__(256) proj_mma_kernel(
    const float* __restrict__ bo, const float* __restrict__ xres)
{
    extern __shared__ char smraw[];
    float* bs = (float*)(smraw + GBS);
    const int t = threadIdx.x, lane = t & 31, wid = t >> 5;
    const int gid = lane >> 2, tig = lane & 3;
    const int wm = (wid >> 2) * 64, wn = (wid & 3) * 32;
    const int m0 = blockIdx.y * 128, n0 = blockIdx.x * 128;
    if (t < 128) bs[t] = bo[n0 + t];

    float acc[4][4][4];
    gemm_pipe_body(g_attnout, g_wb[3], acc, smraw);

    #pragma unroll
    for (int mt = 0; mt < 4; mt++)
        #pragma unroll
        for (int nt = 0; nt < 4; nt++) {
            int cl = wn + nt * 8 + 2 * tig;
            int n  = n0 + cl;
            int mr = m0 + wm + mt * 16 + gid;
            {
                size_t idx = (size_t)mr * Ddim + n;
                float2 xr = *(const float2*)(xres + idx);
                float2 p = { acc[mt][nt][0] + bs[cl] + xr.x,
                             acc[mt][nt][1] + bs[cl + 1] + xr.y };
                *(float2*)(g_y + idx) = p;
            }
            {
                size_t idx = (size_t)(mr + 8) * Ddim + n;
                float2 xr = *(const float2*)(xres + idx);
                float2 p = { acc[mt][nt][2] + bs[cl] + xr.x,
                             acc[mt][nt][3] + bs[cl + 1] + xr.y };
                *(float2*)(g_y + idx) = p;
            }
        }
}

// ---------------- Fused attention: register-resident P ------------------------
// Q A-fragments hoisted out of the chunk loop; k2 loads vectorized (LDS.64).
#define FAST 72
#define QS_B   0
#define KS0_B  18432
#define KS1_B  27648
#define VS0_B  36864
#define VS1_B  46080
#define K20_B  55296
#define K21_B  55552
#define FA_SMEM 55808

__global__ void __launch_bounds__(256, 2) fused_attn_kernel()
{
    extern __shared__ char smraw[];
    bf16*  Qs     = (bf16*)(smraw + QS_B);
    bf16*  Ksb[2] = { (bf16*)(smraw + KS0_B), (bf16*)(smraw + KS1_B) };
    bf16*  Vsb[2] = { (bf16*)(smraw + VS0_B), (bf16*)(smraw + VS1_B) };
    float* k2b[2] = { (float*)(smraw + K20_B), (float*)(smraw + K21_B) };

    const int t = threadIdx.x, lane = t & 31, wid = t >> 5;
    const int gid = lane >> 2, tig = lane & 3;
    const int wm = wid * 16;
    const int i0 = blockIdx.x * 128;
    const int bh = blockIdx.y;
    const bf16* Qg = g_q + (size_t)bh * Nseq * DH;
    const bf16* Kg = g_k + (size_t)bh * Nseq * DH;
    const bf16* Vg = g_v + (size_t)bh * Nseq * DH;
    const float* k2g = g_k2 + (size_t)bh * Nseq;

    // prefetch chunk 0 (K, V, k2)
    #pragma unroll
    for (int i = 0; i < 2; i++) {
        int f = t + 256 * i;
        int r = f >> 3, c = (f & 7) * 8;
        cpa16(s2u(Ksb[0] + r * FAST + c), Kg + (size_t)r * DH + c);
        cpa16(s2u(Vsb[0] + r * FAST + c), Vg + (size_t)r * DH + c);
    }
    if (t < 16) cpa16(s2u(k2b[0] + t * 4), k2g + t * 4);
    CP_COMMIT();

    // load Q tile, then hoist this warp's Q A-fragments into registers
    #pragma unroll
    for (int i = 0; i < 4; i++) {
        int f = t + 256 * i;
        int r = f >> 3, c = (f & 7) * 8;
        *(uint4*)(Qs + r * FAST + c) = *(const uint4*)(Qg + (size_t)(i0 + r) * DH + c);
    }
    const float q2a = g_q2[(size_t)bh * Nseq + i0 + wm + gid];
    const float q2b = g_q2[(size_t)bh * Nseq + i0 + wm + gid + 8];
    __syncthreads();                 // Qs visible to all warps
    u32 qa[4][4];
    #pragma unroll
    for (int ks = 0; ks < 4; ks++)
        ldsm4(qa[ks], aaddr(Qs, FAST, wm, ks * 16, lane));

    float oacc[8][4];
    #pragma unroll
    for (int nt = 0; nt < 8; nt++)
        #pragma unroll
        for (int c = 0; c < 4; c++) oacc[nt][c] = 0.f;
    float rs0 = 0.f, rs1 = 0.f;

    #pragma unroll 2
    for (int jc = 0; jc < 16; jc++) {
        bf16*  Ks  = Ksb[jc & 1];
        bf16*  Vs  = Vsb[jc & 1];
        float* k2c = k2b[jc & 1];
        CP_WAIT0();
        __syncthreads();   // chunk data visible; all warps done with other buffer
        if (jc < 15) {
            int j1 = (jc + 1) * 64;
            bf16*  Kn  = Ksb[(jc + 1) & 1];
            bf16*  Vn  = Vsb[(jc + 1) & 1];
            float* k2n = k2b[(jc + 1) & 1];
            #pragma unroll
            for (int i = 0; i < 2; i++) {
                int f = t + 256 * i;
                int r = f >> 3, c = (f & 7) * 8;
                cpa16(s2u(Kn + r * FAST + c), Kg + (size_t)(j1 + r) * DH + c);
                cpa16(s2u(Vn + r * FAST + c), Vg + (size_t)(j1 + r) * DH + c);
            }
            if (t < 16) cpa16(s2u(k2n + t * 4), k2g + j1 + t * 4);
            CP_COMMIT();
        }

        // S = Q @ K^T : warp tile 16 rows x 64 keys (Q frags from registers)
        float sacc[8][4];
        #pragma unroll
        for (int nt = 0; nt < 8; nt++)
            #pragma unroll
            for (int c = 0; c < 4; c++) sacc[nt][c] = 0.f;
        #pragma unroll
        for (int ks = 0; ks < 4; ks++) {
            int kk = ks * 16;
            #pragma unroll
            for (int p = 0; p < 4; p++) {
                u32 bb[4];
                ldsm4(bb, baddr_k(Ks, FAST, 16 * p, kk, lane));
                mma16(sacc[2*p],     qa[ks], &bb[0]);
                mma16(sacc[2*p + 1], qa[ks], &bb[2]);
            }
        }

        // epilogue: P = ex2(-sqrt(d')) directly into PV A-fragments
        u32 pa[4][4];
        #pragma unroll
        for (int nt = 0; nt < 8; nt++) {
            int cl = nt * 8 + 2 * tig;
            float2 kk2 = *(const float2*)(k2c + cl);   // LDS.64
            float d0 = fmaxf(fmaf(NEG2L2, sacc[nt][0], q2a + kk2.x), EPS_SC);
            float d1 = fmaxf(fmaf(NEG2L2, sacc[nt][1], q2a + kk2.y), EPS_SC);
            float d2 = fmaxf(fmaf(NEG2L2, sacc[nt][2], q2b + kk2.x), EPS_SC);
            float d3 = fmaxf(fmaf(NEG2L2, sacc[nt][3], q2b + kk2.y), EPS_SC);
            float p0 = ex2_ap(-sqrt_ap(d0));
            float p1 = ex2_ap(-sqrt_ap(d1));
            float p2 = ex2_ap(-sqrt_ap(d2));
            float p3 = ex2_ap(-sqrt_ap(d3));
            rs0 += p0 + p1;
            rs1 += p2 + p3;
            bf162 w01 = __floats2bfloat162_rn(p0, p1);
            bf162 w23 = __floats2bfloat162_rn(p2, p3);
            if ((nt & 1) == 0) { pa[nt >> 1][0] = *(u32*)&w01; pa[nt >> 1][1] = *(u32*)&w23; }
            else               { pa[nt >> 1][2] = *(u32*)&w01; pa[nt >> 1][3] = *(u32*)&w23; }
        }

        // O += P @ V : A from registers, B = V via ldmatrix.trans
        #pragma unroll
        for (int k4 = 0; k4 < 4; k4++) {
            int kk = k4 * 16;
            #pragma unroll
            for (int p = 0; p < 4; p++) {
                u32 bb[4];
                ldsm4t(bb, baddr_t(Vs, FAST, kk, 16 * p, lane));
                mma16(oacc[2*p],     pa[k4], &bb[0]);
                mma16(oacc[2*p + 1], pa[k4], &bb[2]);
            }
        }
    }

    // quad-reduce row sums (cols split across tig only)
    rs0 += __shfl_xor_sync(0xffffffffu, rs0, 1);
    rs0 += __shfl_xor_sync(0xffffffffu, rs0, 2);
    rs1 += __shfl_xor_sync(0xffffffffu, rs1, 1);
    rs1 += __shfl_xor_sync(0xffffffffu, rs1, 2);
    float li0 = 1.0f / rs0;
    float li1 = 1.0f / rs1;

    const int b = bh >> 3, h = bh & 7;
    const int i = i0 + wm + gid;
    #pragma unroll
    for (int nt = 0; nt < 8; nt++) {
        int dh = nt * 8 + 2 * tig;
        bf162 w0 = __floats2bfloat162_rn(oacc[nt][0] * li0, oacc[nt][1] * li0);
        bf162 w1 = __floats2bfloat162_rn(oacc[nt][2] * li1, oacc[nt][3] * li1);
        *(u32*)(g_attnout + ((size_t)(b * Nseq + i) * Ddim + h * DH + dh)) = *(u32*)&w0;
        *(u32*)(g_attnout + ((size_t)(b * Nseq + i + 8) * Ddim + h * DH + dh)) = *(u32*)&w1;
    }
}

// ---------------- launch ------------------------------------------------------
extern "C" void kernel_launch(void* const* d_in, const int* in_sizes, int n_in,
                              void* d_out, int out_size)
{
    const float* x = nullptr;
    const float* Wm[4] = {nullptr, nullptr, nullptr, nullptr};
    const float* vec[8] = {nullptr};
    int nm = 0, nv = 0;
    for (int i = 0; i < n_in; i++) {
        if (in_sizes[i] == BN_ROWS * Ddim)      x = (const float*)d_in[i];
        else if (in_sizes[i] == Ddim * Ddim)    { if (nm < 4) Wm[nm++] = (const float*)d_in[i]; }
        else if (in_sizes[i] == Ddim)           { if (nv < 8) vec[nv++] = (const float*)d_in[i]; }
    }
    const float *bq = vec[0], *bk = vec[1], *bv = vec[2], *bo = vec[3];
    const float *ln1g = vec[4], *ln1b = vec[5], *ln2g = vec[6], *ln2b = vec[7];

    void *p_h = nullptr, *p_y = nullptr;
    cudaGetSymbolAddress(&p_h, g_h);
    cudaGetSymbolAddress(&p_y, g_y);

    cudaFuncSetAttribute(fused_attn_kernel,
                         cudaFuncAttributeMaxDynamicSharedMemorySize, FA_SMEM);
    cudaFuncSetAttribute(qkv_mma_kernel,
                         cudaFuncAttributeMaxDynamicSharedMemorySize, GEMM_SMEM);
    cudaFuncSetAttribute(proj_mma_kernel,
                         cudaFuncAttributeMaxDynamicSharedMemorySize, GEMM_SMEM);

    wconv_kernel<<<dim3(256, 4), 256>>>(Wm[0], Wm[1], Wm[2], Wm[3]);
    ln_bf16_kernel<<<BN_ROWS / 8, 256>>>(x, ln1g, ln1b, (bf16*)p_h);
    qkv_mma_kernel<<<dim3(Ddim / 128, BN_ROWS / 128, 3), 256, GEMM_SMEM>>>(bq, bk, bv);
    fused_attn_kernel<<<dim3(Nseq / 128, NBH), 256, FA_SMEM>>>();
    proj_mma_kernel<<<dim3(Ddim / 128, BN_ROWS / 128), 256, GEMM_SMEM>>>(bo, x);
    ln_f32_kernel<<<BN_ROWS / 8, 256>>>((const float*)p_y, ln2g, ln2b, (float*)d_out);
}